// round 8
// baseline (speedup 1.0000x reference)
#include <cuda_runtime.h>
#include <cuda_bf16.h>
#include <math.h>
#include <stdint.h>

// ---------------- problem constants ----------------
#define BATCH 4
#define TSEQ  1024
#define CDIM  768
#define NHEAD 12
#define HD    64
#define VOCAB 50304
#define NLAYER 12
#define NTOK  (BATCH*TSEQ)     // 4096
#define C3    (3*CDIM)         // 2304
#define C4    (4*CDIM)         // 3072

// ---------------- scratch (static device globals; no allocation allowed) ----
__device__ float g_h   [NTOK * CDIM];
__device__ float g_hn  [NTOK * CDIM];
__device__ float g_qkv [NTOK * C3];
__device__ float g_att [NTOK * CDIM];
__device__ float g_fc  [NTOK * C4];
__device__ float g_rowloss[NTOK];

// ---------------- embedding: h = wte[x] + wpe[t] ----------------
__global__ __launch_bounds__(256) void embed_kernel(const int* __restrict__ x,
                                                    const float* __restrict__ wte,
                                                    const float* __restrict__ wpe) {
    int m = blockIdx.x;
    int t = m % TSEQ;
    int idx = x[m];
    const float* we = wte + (size_t)idx * CDIM;
    const float* wp = wpe + (size_t)t * CDIM;
    float* o = g_h + (size_t)m * CDIM;
    for (int c = threadIdx.x; c < CDIM; c += 256)
        o[c] = we[c] + wp[c];
}

// ---------------- layernorm (block per row) ----------------
__global__ __launch_bounds__(256) void ln_kernel(const float* __restrict__ in,
                                                 const float* __restrict__ w,
                                                 const float* __restrict__ bb,
                                                 float* __restrict__ out) {
    int row = blockIdx.x;
    const float* x = in + (size_t)row * CDIM;
    float s = 0.f, s2 = 0.f;
    for (int c = threadIdx.x; c < CDIM; c += 256) {
        float v = x[c]; s += v; s2 += v * v;
    }
    __shared__ float ss[8], ss2[8];
    #pragma unroll
    for (int o = 16; o; o >>= 1) {
        s  += __shfl_down_sync(0xffffffffu, s,  o);
        s2 += __shfl_down_sync(0xffffffffu, s2, o);
    }
    if ((threadIdx.x & 31) == 0) { ss[threadIdx.x >> 5] = s; ss2[threadIdx.x >> 5] = s2; }
    __syncthreads();
    if (threadIdx.x == 0) {
        float a = 0.f, a2 = 0.f;
        #pragma unroll
        for (int i = 0; i < 8; i++) { a += ss[i]; a2 += ss2[i]; }
        ss[0] = a; ss2[0] = a2;
    }
    __syncthreads();
    float mean = ss[0] * (1.f / CDIM);
    float var  = ss2[0] * (1.f / CDIM) - mean * mean;
    float rstd = rsqrtf(var + 1e-5f);
    float* o = out + (size_t)row * CDIM;
    for (int c = threadIdx.x; c < CDIM; c += 256)
        o[c] = (x[c] - mean) * rstd * w[c] + bb[c];
}

// ---------------- epilogue helper ----------------
template<int EPI>
__device__ __forceinline__ void epi_store(float* __restrict__ C,
                                          const float* __restrict__ bias,
                                          const float* __restrict__ add,
                                          int r, int cc, int N, float v0, float v1) {
    if (bias) { v0 += bias[cc]; v1 += bias[cc + 1]; }
    if (EPI == 1) {
        float t0 = 0.7978845608028654f * (v0 + 0.044715f * v0 * v0 * v0);
        v0 = 0.5f * v0 * (1.0f + tanhf(t0));
        float t1 = 0.7978845608028654f * (v1 + 0.044715f * v1 * v1 * v1);
        v1 = 0.5f * v1 * (1.0f + tanhf(t1));
    } else if (EPI == 2) {
        const float2 a2 = *(const float2*)(add + (size_t)r * N + cc);
        v0 += a2.x; v1 += a2.y;
    }
    float2 o2; o2.x = v0; o2.y = v1;
    *(float2*)(C + (size_t)r * N + cc) = o2;
}

// ---------------- bf16 split helpers ----------------
__device__ __forceinline__ void bsplit(float x, uint16_t& h, uint16_t& l) {
    __nv_bfloat16 bh = __float2bfloat16_rn(x);
    h = __bfloat16_as_ushort(bh);
    float r = x - __bfloat162float(bh);
    l = __bfloat16_as_ushort(__float2bfloat16_rn(r));
}
__device__ __forceinline__ void pack_hl(float vx, float vy, uint32_t& h, uint32_t& l) {
    uint16_t hx, lx, hy, ly;
    bsplit(vx, hx, lx); bsplit(vy, hy, ly);
    h = (uint32_t)hx | ((uint32_t)hy << 16);
    l = (uint32_t)lx | ((uint32_t)ly << 16);
}
__device__ __forceinline__ void mma_bf16(float* c, const uint32_t* a, const uint32_t* b) {
    asm volatile(
        "mma.sync.aligned.m16n8k16.row.col.f32.bf16.bf16.f32 "
        "{%0,%1,%2,%3},{%4,%5,%6,%7},{%8,%9},{%0,%1,%2,%3};"
        : "+f"(c[0]), "+f"(c[1]), "+f"(c[2]), "+f"(c[3])
        : "r"(a[0]), "r"(a[1]), "r"(a[2]), "r"(a[3]), "r"(b[0]), "r"(b[1]));
}

// ---------------- 3xBF16 GEMM (fp32-class accuracy, reg-prefetch pipelined) --
// C = epi(A[M,K] @ op(B) + bias). Per product: hi*hi + hi*lo + lo*hi.
// TRANSB=false: B is [K,N]. TRANSB=true: B is [N,K] (tied LM head).
// Block tile 128x128x32, 8 warps each 64x32 via m16n8k16.
// Mainloop: STS(tile k) -> sync -> LDG(tile k+1 into regs) -> MMA(tile k) -> sync.
template<int EPI, bool TRANSB>
__global__ __launch_bounds__(256) void bf16_gemm(const float* __restrict__ A,
                                                 const float* __restrict__ B,
                                                 const float* __restrict__ bias,
                                                 const float* __restrict__ add,
                                                 float* __restrict__ C,
                                                 int M, int N, int K) {
    constexpr int BM = 128, BN = 128, BK = 32;
    constexpr int ST = 40;   // padded row stride (bf16 elems) -> conflict-free frags
    __shared__ __nv_bfloat16 Ah[BM * ST], Al[BM * ST];
    __shared__ __nv_bfloat16 Bh[BN * ST], Bl[BN * ST];   // stored [n][k]

    int tid  = threadIdx.x;
    int wid  = tid >> 5, lane = tid & 31;
    int wr   = wid >> 2, wc = wid & 3;            // warp grid 2 x 4
    int g    = lane >> 2, tg = lane & 3;          // groupID, thread-in-group
    int row0 = blockIdx.y * BM, col0 = blockIdx.x * BN;

    // per-thread staging coordinates
    const int am = tid >> 3, ak = (tid & 7) * 4;          // A: 4 rows x float4
    const int bn = tid >> 3, bk = (tid & 7) * 4;          // B TRANSB
    const int nn = tid & 127, kb = (tid >> 7) * 16;       // B !TRANSB

    float4 aReg[4];
    float4 bRegT[4];
    float  bRegN[16];

    auto ldA = [&](int k0) {
        #pragma unroll
        for (int i = 0; i < 4; i++)
            aReg[i] = *(const float4*)(A + (size_t)(row0 + am + i * 32) * K + k0 + ak);
    };
    auto ldB = [&](int k0) {
        if (TRANSB) {
            #pragma unroll
            for (int i = 0; i < 4; i++)
                bRegT[i] = *(const float4*)(B + (size_t)(col0 + bn + i * 32) * K + k0 + bk);
        } else {
            #pragma unroll
            for (int j = 0; j < 16; j++)
                bRegN[j] = B[(size_t)(k0 + kb + j) * N + col0 + nn];
        }
    };

    float c[4][4][4];
    #pragma unroll
    for (int mi = 0; mi < 4; mi++)
        #pragma unroll
        for (int ni = 0; ni < 4; ni++)
            #pragma unroll
            for (int r = 0; r < 4; r++) c[mi][ni][r] = 0.f;

    ldA(0); ldB(0);

    for (int k0 = 0; k0 < K; k0 += BK) {
        // ---- split current regs into smem ----
        #pragma unroll
        for (int i = 0; i < 4; i++) {
            int idx = (am + i * 32) * ST + ak;
            pack_hl(aReg[i].x, aReg[i].y, *(uint32_t*)&Ah[idx],     *(uint32_t*)&Al[idx]);
            pack_hl(aReg[i].z, aReg[i].w, *(uint32_t*)&Ah[idx + 2], *(uint32_t*)&Al[idx + 2]);
        }
        if (TRANSB) {
            #pragma unroll
            for (int i = 0; i < 4; i++) {
                int idx = (bn + i * 32) * ST + bk;
                pack_hl(bRegT[i].x, bRegT[i].y, *(uint32_t*)&Bh[idx],     *(uint32_t*)&Bl[idx]);
                pack_hl(bRegT[i].z, bRegT[i].w, *(uint32_t*)&Bh[idx + 2], *(uint32_t*)&Bl[idx + 2]);
            }
        } else {
            #pragma unroll
            for (int j = 0; j < 8; j++) {
                int idx = nn * ST + kb + 2 * j;
                pack_hl(bRegN[2*j], bRegN[2*j+1], *(uint32_t*)&Bh[idx], *(uint32_t*)&Bl[idx]);
            }
        }
        __syncthreads();

        // ---- prefetch next tile into registers (overlaps with MMAs below) ----
        if (k0 + BK < K) { ldA(k0 + BK); ldB(k0 + BK); }

        // ---- compute ----
        #pragma unroll
        for (int ks = 0; ks < 2; ks++) {
            int kk = ks * 16;
            uint32_t ah[4][4], al[4][4], bh[4][2], bl[4][2];
            #pragma unroll
            for (int mi = 0; mi < 4; mi++) {
                int r1 = (wr * 64 + mi * 16 + g) * ST + kk + 2 * tg;
                int r2 = r1 + 8 * ST;
                ah[mi][0] = *(const uint32_t*)&Ah[r1];
                ah[mi][1] = *(const uint32_t*)&Ah[r2];
                ah[mi][2] = *(const uint32_t*)&Ah[r1 + 8];
                ah[mi][3] = *(const uint32_t*)&Ah[r2 + 8];
                al[mi][0] = *(const uint32_t*)&Al[r1];
                al[mi][1] = *(const uint32_t*)&Al[r2];
                al[mi][2] = *(const uint32_t*)&Al[r1 + 8];
                al[mi][3] = *(const uint32_t*)&Al[r2 + 8];
            }
            #pragma unroll
            for (int ni = 0; ni < 4; ni++) {
                int n1 = (wc * 32 + ni * 8 + g) * ST + kk + 2 * tg;
                bh[ni][0] = *(const uint32_t*)&Bh[n1];
                bh[ni][1] = *(const uint32_t*)&Bh[n1 + 8];
                bl[ni][0] = *(const uint32_t*)&Bl[n1];
                bl[ni][1] = *(const uint32_t*)&Bl[n1 + 8];
            }
            #pragma unroll
            for (int mi = 0; mi < 4; mi++)
                #pragma unroll
                for (int ni = 0; ni < 4; ni++) {
                    mma_bf16(c[mi][ni], ah[mi], bh[ni]);
                    mma_bf16(c[mi][ni], ah[mi], bl[ni]);
                    mma_bf16(c[mi][ni], al[mi], bh[ni]);
                }
        }
        __syncthreads();
    }

    #pragma unroll
    for (int mi = 0; mi < 4; mi++)
        #pragma unroll
        for (int ni = 0; ni < 4; ni++) {
            int r0 = row0 + wr * 64 + mi * 16 + g;
            int cc = col0 + wc * 32 + ni * 8 + tg * 2;
            epi_store<EPI>(C, bias, add, r0,     cc, N, c[mi][ni][0], c[mi][ni][1]);
            epi_store<EPI>(C, bias, add, r0 + 8, cc, N, c[mi][ni][2], c[mi][ni][3]);
        }
}

// ---------------- MMA flash attention (3xBF16, causal, NO score scaling) ----
// grid: (T/128, H, B); block 256 = 8 warps; warp owns 16 q-rows.
// Subtile = 64 keys. K staged [key][d]; V staged transposed [d][key] in the
// SAME smem buffer (K phase then V phase). Softmax fp32 in registers.
__global__ __launch_bounds__(256) void attn_mma(const float* __restrict__ qkv,
                                                float* __restrict__ att) {
    constexpr int ST = 72;   // padded stride (bf16) -> conflict-free frag reads
    int b = blockIdx.z, h = blockIdx.y;
    int q0 = blockIdx.x * 128;
    int tid = threadIdx.x, wid = tid >> 5, lane = tid & 31;
    int g = lane >> 2, tg = lane & 3;
    int qw0 = q0 + wid * 16;
    const size_t base = (size_t)b * TSEQ * C3;

    __shared__ __nv_bfloat16 sH[64 * ST], sL[64 * ST];

    // ---- Q fragments (rows qw0+g, qw0+g+8), hi/lo ----
    uint32_t qh[4][4], ql[4][4];
    {
        const float* q_r0 = qkv + base + (size_t)(qw0 + g) * C3 + h * HD;
        const float* q_r1 = q_r0 + 8 * C3;
        #pragma unroll
        for (int s = 0; s < 4; s++) {
            float2 v0 = *(const float2*)(q_r0 + 16 * s + 2 * tg);
            float2 v1 = *(const float2*)(q_r1 + 16 * s + 2 * tg);
            float2 v2 = *(const float2*)(q_r0 + 16 * s + 2 * tg + 8);
            float2 v3 = *(const float2*)(q_r1 + 16 * s + 2 * tg + 8);
            pack_hl(v0.x, v0.y, qh[s][0], ql[s][0]);
            pack_hl(v1.x, v1.y, qh[s][1], ql[s][1]);
            pack_hl(v2.x, v2.y, qh[s][2], ql[s][2]);
            pack_hl(v3.x, v3.y, qh[s][3], ql[s][3]);
        }
    }

    float o[8][4];
    #pragma unroll
    for (int ni = 0; ni < 8; ni++)
        #pragma unroll
        for (int r = 0; r < 4; r++) o[ni][r] = 0.f;
    float m0 = -1e30f, m1 = -1e30f, l0 = 0.f, l1 = 0.f;

    int kend = q0 + 128;
    for (int j0 = 0; j0 < kend; j0 += 64) {
        bool act = (j0 <= qw0 + 15);
        __syncthreads();   // prior PV reads done before overwrite
        {   // ---- stage K [key][d] hi/lo ----
            int kk = tid >> 2, d0 = (tid & 3) * 16;
            const float* kp = qkv + base + (size_t)(j0 + kk) * C3 + CDIM + h * HD + d0;
            #pragma unroll
            for (int i = 0; i < 4; i++) {
                float4 v = ((const float4*)kp)[i];
                int idx = kk * ST + d0 + i * 4;
                pack_hl(v.x, v.y, *(uint32_t*)&sH[idx],     *(uint32_t*)&sL[idx]);
                pack_hl(v.z, v.w, *(uint32_t*)&sH[idx + 2], *(uint32_t*)&sL[idx + 2]);
            }
        }
        __syncthreads();

        uint32_t ph[4][4], pl[4][4];
        if (act) {
            // ---- S = Q @ K^T over 8 n-tiles x 4 k-steps ----
            float s[8][4];
            #pragma unroll
            for (int ni = 0; ni < 8; ni++) {
                s[ni][0] = s[ni][1] = s[ni][2] = s[ni][3] = 0.f;
                #pragma unroll
                for (int ss = 0; ss < 4; ss++) {
                    int ib = (8 * ni + g) * ST + 16 * ss + 2 * tg;
                    uint32_t bh[2] = { *(const uint32_t*)&sH[ib], *(const uint32_t*)&sH[ib + 8] };
                    uint32_t bl[2] = { *(const uint32_t*)&sL[ib], *(const uint32_t*)&sL[ib + 8] };
                    mma_bf16(s[ni], qh[ss], bh);
                    mma_bf16(s[ni], qh[ss], bl);
                    mma_bf16(s[ni], ql[ss], bh);
                }
            }
            // ---- causal mask + online softmax ----
            int r0 = qw0 + g, r1 = r0 + 8;
            float mx0 = -1e30f, mx1 = -1e30f;
            #pragma unroll
            for (int ni = 0; ni < 8; ni++) {
                int kc = j0 + 8 * ni + 2 * tg;
                if (kc     > r0) s[ni][0] = -1e30f;
                if (kc + 1 > r0) s[ni][1] = -1e30f;
                if (kc     > r1) s[ni][2] = -1e30f;
                if (kc + 1 > r1) s[ni][3] = -1e30f;
                mx0 = fmaxf(mx0, fmaxf(s[ni][0], s[ni][1]));
                mx1 = fmaxf(mx1, fmaxf(s[ni][2], s[ni][3]));
            }
            mx0 = fmaxf(mx0, __shfl_xor_sync(0xffffffffu, mx0, 1));
            mx0 = fmaxf(mx0, __shfl_xor_sync(0xffffffffu, mx0, 2));
            mx1 = fmaxf(mx1, __shfl_xor_sync(0xffffffffu, mx1, 1));
            mx1 = fmaxf(mx1, __shfl_xor_sync(0xffffffffu, mx1, 2));
            float nm0 = fmaxf(m0, mx0), nm1 = fmaxf(m1, mx1);
            float c0 = __expf(m0 - nm0), c1 = __expf(m1 - nm1);
            m0 = nm0; m1 = nm1;
            float p[8][4];
            float ls0 = 0.f, ls1 = 0.f;
            #pragma unroll
            for (int ni = 0; ni < 8; ni++) {
                p[ni][0] = __expf(s[ni][0] - nm0);
                p[ni][1] = __expf(s[ni][1] - nm0);
                p[ni][2] = __expf(s[ni][2] - nm1);
                p[ni][3] = __expf(s[ni][3] - nm1);
                ls0 += p[ni][0] + p[ni][1];
                ls1 += p[ni][2] + p[ni][3];
            }
            l0 = l0 * c0 + ls0;
            l1 = l1 * c1 + ls1;
            #pragma unroll
            for (int ni = 0; ni < 8; ni++) {
                o[ni][0] *= c0; o[ni][1] *= c0; o[ni][2] *= c1; o[ni][3] *= c1;
            }
            // ---- pack P as A-fragments (hi/lo) ----
            #pragma unroll
            for (int ss = 0; ss < 4; ss++) {
                pack_hl(p[2*ss][0],   p[2*ss][1],   ph[ss][0], pl[ss][0]);
                pack_hl(p[2*ss][2],   p[2*ss][3],   ph[ss][1], pl[ss][1]);
                pack_hl(p[2*ss+1][0], p[2*ss+1][1], ph[ss][2], pl[ss][2]);
                pack_hl(p[2*ss+1][2], p[2*ss+1][3], ph[ss][3], pl[ss][3]);
            }
        }
        __syncthreads();   // S-phase reads done
        {   // ---- stage V transposed [d][key] hi/lo ----
            int kk = tid >> 2, d0 = (tid & 3) * 16;
            const float* vp = qkv + base + (size_t)(j0 + kk) * C3 + 2 * CDIM + h * HD + d0;
            #pragma unroll
            for (int i = 0; i < 4; i++) {
                float4 v = ((const float4*)vp)[i];
                int d = d0 + i * 4;
                uint16_t hh, ll;
                bsplit(v.x, hh, ll);
                sH[(d + 0) * ST + kk] = __ushort_as_bfloat16(hh);
                sL[(d + 0) * ST + kk] = __ushort_as_bfloat16(ll);
                bsplit(v.y, hh, ll);
                sH[(d + 1) * ST + kk] = __ushort_as_bfloat16(hh);
                sL[(d + 1) * ST + kk] = __ushort_as_bfloat16(ll);
                bsplit(v.z, hh, ll);
                sH[(d + 2) * ST + kk] = __ushort_as_bfloat16(hh);
                sL[(d + 2) * ST + kk] = __ushort_as_bfloat16(ll);
                bsplit(v.w, hh, ll);
                sH[(d + 3) * ST + kk] = __ushort_as_bfloat16(hh);
                sL[(d + 3) * ST + kk] = __ushort_as_bfloat16(ll);
            }
        }
        __syncthreads();
        if (act) {
            // ---- O += P @ V : n-tiles are dim groups, k-steps over keys ----
            #pragma unroll
            for (int ni = 0; ni < 8; ni++)
                #pragma unroll
                for (int ss = 0; ss < 4; ss++) {
                    int ib = (8 * ni + g) * ST + 16 * ss + 2 * tg;
                    uint32_t bh[2] = { *(const uint32_t*)&sH[ib], *(const uint32_t*)&sH[ib + 8] };
                    uint32_t bl[2] = { *(const uint32_t*)&sL[ib], *(const uint32_t*)&sL[ib + 8] };
                    mma_bf16(o[ni], ph[ss], bh);
                    mma_bf16(o[ni], ph[ss], bl);
                    mma_bf16(o[ni], pl[ss], bh);
                }
        }
    }

    // ---- epilogue ----
    l0 += __shfl_xor_sync(0xffffffffu, l0, 1);
    l0 += __shfl_xor_sync(0xffffffffu, l0, 2);
    l1 += __shfl_xor_sync(0xffffffffu, l1, 1);
    l1 += __shfl_xor_sync(0xffffffffu, l1, 2);
    float i0 = 1.f / l0, i1 = 1.f / l1;
    float* o0 = att + (size_t)(b * TSEQ + qw0 + g) * CDIM + h * HD;
    float* o1 = o0 + 8 * CDIM;
    #pragma unroll
    for (int ni = 0; ni < 8; ni++) {
        float2 a; a.x = o[ni][0] * i0; a.y = o[ni][1] * i0;
        float2 c; c.x = o[ni][2] * i1; c.y = o[ni][3] * i1;
        *(float2*)(o0 + 8 * ni + 2 * tg) = a;
        *(float2*)(o1 + 8 * ni + 2 * tg) = c;
    }
}

// ---------------- per-row cross-entropy ----------------
__global__ __launch_bounds__(256) void loss_row_kernel(const float* __restrict__ logits,
                                                       const int* __restrict__ targets) {
    int row = blockIdx.x;
    const float* x = logits + (size_t)row * VOCAB;
    __shared__ float sh[8];
    float mx = -1e30f;
    for (int c = threadIdx.x; c < VOCAB; c += 256) mx = fmaxf(mx, x[c]);
    #pragma unroll
    for (int o = 16; o; o >>= 1) mx = fmaxf(mx, __shfl_down_sync(0xffffffffu, mx, o));
    if ((threadIdx.x & 31) == 0) sh[threadIdx.x >> 5] = mx;
    __syncthreads();
    if (threadIdx.x == 0) {
        float a = sh[0];
        #pragma unroll
        for (int i = 1; i < 8; i++) a = fmaxf(a, sh[i]);
        sh[0] = a;
    }
    __syncthreads();
    mx = sh[0];
    __syncthreads();
    float s = 0.f;
    for (int c = threadIdx.x; c < VOCAB; c += 256) s += expf(x[c] - mx);
    #pragma unroll
    for (int o = 16; o; o >>= 1) s += __shfl_down_sync(0xffffffffu, s, o);
    if ((threadIdx.x & 31) == 0) sh[threadIdx.x >> 5] = s;
    __syncthreads();
    if (threadIdx.x == 0) {
        float a = 0.f;
        #pragma unroll
        for (int i = 0; i < 8; i++) a += sh[i];
        g_rowloss[row] = (mx + logf(a)) - x[targets[row]];
    }
}

__global__ __launch_bounds__(1024) void loss_reduce_kernel(float* __restrict__ out) {
    __shared__ float sh[1024];
    int t = threadIdx.x;
    float s = 0.f;
    for (int i = t; i < NTOK; i += 1024) s += g_rowloss[i];
    sh[t] = s;
    __syncthreads();
    for (int o = 512; o; o >>= 1) {
        if (t < o) sh[t] += sh[t + o];
        __syncthreads();
    }
    if (t == 0) out[0] = sh[0] * (1.f / NTOK);
}

// ---------------- launch ----------------
extern "C" void kernel_launch(void* const* d_in, const int* in_sizes, int n_in,
                              void* d_out, int out_size) {
    const int*   x       = (const int*)  d_in[0];
    const int*   targets = (const int*)  d_in[1];
    const float* wte     = (const float*)d_in[2];
    const float* wpe     = (const float*)d_in[3];
    const float* ln1_w   = (const float*)d_in[4];
    const float* ln1_b   = (const float*)d_in[5];
    const float* attn_w  = (const float*)d_in[6];
    const float* attn_b  = (const float*)d_in[7];
    const float* proj_w  = (const float*)d_in[8];
    const float* proj_b  = (const float*)d_in[9];
    const float* ln2_w   = (const float*)d_in[10];
    const float* ln2_b   = (const float*)d_in[11];
    const float* fc_w    = (const float*)d_in[12];
    const float* fc_b    = (const float*)d_in[13];
    const float* fc2_w   = (const float*)d_in[14];
    const float* fc2_b   = (const float*)d_in[15];
    const float* lnf_w   = (const float*)d_in[16];
    const float* lnf_b   = (const float*)d_in[17];

    float* logits = (float*)d_out;
    float* lossp  = (float*)d_out + (out_size - 1);

    float *p_h, *p_hn, *p_qkv, *p_att, *p_fc;
    cudaGetSymbolAddress((void**)&p_h,   g_h);
    cudaGetSymbolAddress((void**)&p_hn,  g_hn);
    cudaGetSymbolAddress((void**)&p_qkv, g_qkv);
    cudaGetSymbolAddress((void**)&p_att, g_att);
    cudaGetSymbolAddress((void**)&p_fc,  g_fc);

    embed_kernel<<<NTOK, 256>>>(x, wte, wpe);

    for (int l = 0; l < NLAYER; l++) {
        ln_kernel<<<NTOK, 256>>>(p_h, ln1_w + (size_t)l * CDIM, ln1_b + (size_t)l * CDIM, p_hn);
        bf16_gemm<0, false><<<dim3(C3 / 128, NTOK / 128), 256>>>(
            p_hn, attn_w + (size_t)l * CDIM * C3, attn_b + (size_t)l * C3,
            nullptr, p_qkv, NTOK, C3, CDIM);
        attn_mma<<<dim3(TSEQ / 128, NHEAD, BATCH), 256>>>(p_qkv, p_att);
        bf16_gemm<2, false><<<dim3(CDIM / 128, NTOK / 128), 256>>>(
            p_att, proj_w + (size_t)l * CDIM * CDIM, proj_b + (size_t)l * CDIM,
            p_h, p_h, NTOK, CDIM, CDIM);
        ln_kernel<<<NTOK, 256>>>(p_h, ln2_w + (size_t)l * CDIM, ln2_b + (size_t)l * CDIM, p_hn);
        bf16_gemm<1, false><<<dim3(C4 / 128, NTOK / 128), 256>>>(
            p_hn, fc_w + (size_t)l * CDIM * C4, fc_b + (size_t)l * C4,
            nullptr, p_fc, NTOK, C4, CDIM);
        bf16_gemm<2, false><<<dim3(CDIM / 128, NTOK / 128), 256>>>(
            p_fc, fc2_w + (size_t)l * C4 * CDIM, fc2_b + (size_t)l * CDIM,
            p_h, p_h, NTOK, CDIM, C4);
    }

    ln_kernel<<<NTOK, 256>>>(p_h, lnf_w, lnf_b, p_hn);
    bf16_gemm<0, true><<<dim3(VOCAB / 128, NTOK / 128), 256>>>(
        p_hn, wte, nullptr, nullptr, logits, NTOK, VOCAB, CDIM);

    loss_row_kernel<<<NTOK, 256>>>(logits, targets);
    loss_reduce_kernel<<<1, 1024>>>(lossp);
}

// round 10
// speedup vs baseline: 1.1252x; 1.1252x over previous
#include <cuda_runtime.h>
#include <cuda_bf16.h>
#include <math.h>
#include <stdint.h>

// ---------------- problem constants ----------------
#define BATCH 4
#define TSEQ  1024
#define CDIM  768
#define NHEAD 12
#define HD    64
#define VOCAB 50304
#define NLAYER 12
#define NTOK  (BATCH*TSEQ)     // 4096
#define C3    (3*CDIM)         // 2304
#define C4    (4*CDIM)         // 3072

#define WATTN (NLAYER*C3*CDIM)
#define WPROJ (NLAYER*CDIM*CDIM)
#define WFC   (NLAYER*C4*CDIM)
#define WFC2  (NLAYER*CDIM*C4)
#define WTEN  (VOCAB*CDIM)

// ---------------- scratch (static device globals; no allocation allowed) ----
__device__ float g_h   [NTOK * CDIM];
__device__ float g_qkv [NTOK * C3];
__device__ float g_rowloss[NTOK];
__device__ __nv_bfloat16 g_hnH[NTOK * CDIM], g_hnL[NTOK * CDIM];
__device__ __nv_bfloat16 g_attH[NTOK * CDIM], g_attL[NTOK * CDIM];
__device__ __nv_bfloat16 g_fcH[NTOK * C4],   g_fcL[NTOK * C4];
__device__ __nv_bfloat16 g_waH[WATTN],  g_waL[WATTN];    // [L][3C][C]
__device__ __nv_bfloat16 g_wpH[WPROJ],  g_wpL[WPROJ];    // [L][C][C]  (transposed)
__device__ __nv_bfloat16 g_wfH[WFC],    g_wfL[WFC];      // [L][4C][C]
__device__ __nv_bfloat16 g_wf2H[WFC2],  g_wf2L[WFC2];    // [L][C][4C]
__device__ __nv_bfloat16 g_wteH[WTEN],  g_wteL[WTEN];    // [V][C]

// ---------------- bf16 split helpers ----------------
__device__ __forceinline__ void bsplit(float x, uint16_t& h, uint16_t& l) {
    __nv_bfloat16 bh = __float2bfloat16_rn(x);
    h = __bfloat16_as_ushort(bh);
    float r = x - __bfloat162float(bh);
    l = __bfloat16_as_ushort(__float2bfloat16_rn(r));
}
__device__ __forceinline__ void pack_hl(float vx, float vy, uint32_t& h, uint32_t& l) {
    uint16_t hx, lx, hy, ly;
    bsplit(vx, hx, lx); bsplit(vy, hy, ly);
    h = (uint32_t)hx | ((uint32_t)hy << 16);
    l = (uint32_t)lx | ((uint32_t)ly << 16);
}
__device__ __forceinline__ void mma_bf16(float* c, const uint32_t* a, const uint32_t* b) {
    asm volatile(
        "mma.sync.aligned.m16n8k16.row.col.f32.bf16.bf16.f32 "
        "{%0,%1,%2,%3},{%4,%5,%6,%7},{%8,%9},{%0,%1,%2,%3};"
        : "+f"(c[0]), "+f"(c[1]), "+f"(c[2]), "+f"(c[3])
        : "r"(a[0]), "r"(a[1]), "r"(a[2]), "r"(a[3]), "r"(b[0]), "r"(b[1]));
}
__device__ __forceinline__ uint32_t smem_u32(const void* p) {
    uint32_t a;
    asm("{ .reg .u64 t; cvta.to.shared.u64 t, %1; cvt.u32.u64 %0, t; }" : "=r"(a) : "l"(p));
    return a;
}

// ---------------- weight conversion kernels (once per launch) ----------------
// Transpose-split: in [K,N] fp32 (per layer z) -> out [N,K] bf16 hi/lo.
__global__ __launch_bounds__(256) void wsplit_t(const float* __restrict__ in,
                                                __nv_bfloat16* __restrict__ oh,
                                                __nv_bfloat16* __restrict__ ol,
                                                int K, int N) {
    __shared__ float t[32][33];
    size_t loff = (size_t)blockIdx.z * K * N;
    const float* src = in + loff;
    int nb = blockIdx.x * 32, kb = blockIdx.y * 32;
    int tx = threadIdx.x & 31, ty = threadIdx.x >> 5;   // 32 x 8
    #pragma unroll
    for (int i = 0; i < 32; i += 8)
        t[ty + i][tx] = src[(size_t)(kb + ty + i) * N + nb + tx];
    __syncthreads();
    #pragma unroll
    for (int i = 0; i < 32; i += 8) {
        float v = t[tx][ty + i];
        uint16_t h, l; bsplit(v, h, l);
        size_t o = loff + (size_t)(nb + ty + i) * K + kb + tx;
        oh[o] = __ushort_as_bfloat16(h);
        ol[o] = __ushort_as_bfloat16(l);
    }
}
// Plain split (already [N][K]): wte.
__global__ __launch_bounds__(256) void wsplit(const float* __restrict__ in,
                                              __nv_bfloat16* __restrict__ oh,
                                              __nv_bfloat16* __restrict__ ol, int n) {
    int i = (blockIdx.x * 256 + threadIdx.x) * 2;
    if (i < n) {
        uint32_t h, l;
        pack_hl(in[i], in[i + 1], h, l);
        *(uint32_t*)&oh[i] = h;
        *(uint32_t*)&ol[i] = l;
    }
}

// ---------------- embedding ----------------
__global__ __launch_bounds__(256) void embed_kernel(const int* __restrict__ x,
                                                    const float* __restrict__ wte,
                                                    const float* __restrict__ wpe) {
    int m = blockIdx.x;
    int t = m % TSEQ;
    int idx = x[m];
    const float* we = wte + (size_t)idx * CDIM;
    const float* wp = wpe + (size_t)t * CDIM;
    float* o = g_h + (size_t)m * CDIM;
    for (int c = threadIdx.x; c < CDIM; c += 256)
        o[c] = we[c] + wp[c];
}

// ---------------- layernorm: fp32 in -> bf16 hi/lo pair out ----------------
__global__ __launch_bounds__(256) void ln_kernel(const float* __restrict__ in,
                                                 const float* __restrict__ w,
                                                 const float* __restrict__ bb,
                                                 __nv_bfloat16* __restrict__ oh,
                                                 __nv_bfloat16* __restrict__ ol) {
    int row = blockIdx.x;
    const float* x = in + (size_t)row * CDIM;
    float s = 0.f, s2 = 0.f;
    for (int c = threadIdx.x; c < CDIM; c += 256) {
        float v = x[c]; s += v; s2 += v * v;
    }
    __shared__ float ss[8], ss2[8];
    #pragma unroll
    for (int o = 16; o; o >>= 1) {
        s  += __shfl_down_sync(0xffffffffu, s,  o);
        s2 += __shfl_down_sync(0xffffffffu, s2, o);
    }
    if ((threadIdx.x & 31) == 0) { ss[threadIdx.x >> 5] = s; ss2[threadIdx.x >> 5] = s2; }
    __syncthreads();
    if (threadIdx.x == 0) {
        float a = 0.f, a2 = 0.f;
        #pragma unroll
        for (int i = 0; i < 8; i++) { a += ss[i]; a2 += ss2[i]; }
        ss[0] = a; ss2[0] = a2;
    }
    __syncthreads();
    float mean = ss[0] * (1.f / CDIM);
    float var  = ss2[0] * (1.f / CDIM) - mean * mean;
    float rstd = rsqrtf(var + 1e-5f);
    __nv_bfloat16* oH = oh + (size_t)row * CDIM;
    __nv_bfloat16* oL = ol + (size_t)row * CDIM;
    for (int c = threadIdx.x * 2; c < CDIM; c += 512) {
        float v0 = (x[c]     - mean) * rstd * w[c]     + bb[c];
        float v1 = (x[c + 1] - mean) * rstd * w[c + 1] + bb[c + 1];
        uint32_t hh, ll;
        pack_hl(v0, v1, hh, ll);
        *(uint32_t*)&oH[c] = hh;
        *(uint32_t*)&oL[c] = ll;
    }
}

// ---------------- pipelined 3xBF16 GEMM (pre-split inputs, cp.async) --------
// C = epi(A @ B^T): A pair [M][K], B pair [N][K] (k-contiguous rows).
// EPI: 0 = +bias -> fp32; 1 = +bias,gelu -> bf16 pair; 2 = +bias+residual -> fp32;
//      3 = plain -> fp32.
// Tile 128x128x32, 8 warps (2x4), m16n8k16, 2-stage cp.async double buffer.
#define PG_STG   40960                       // bytes per stage
#define PG_ARR   10240                       // bytes per array (128 rows x 80B)
#define PG_SMEM  (2 * PG_STG)

template<int EPI>
__global__ __launch_bounds__(256) void pgemm(const __nv_bfloat16* __restrict__ AH,
                                             const __nv_bfloat16* __restrict__ AL,
                                             const __nv_bfloat16* __restrict__ BH,
                                             const __nv_bfloat16* __restrict__ BL,
                                             const float* __restrict__ bias,
                                             const float* __restrict__ add,
                                             float* __restrict__ Cf,
                                             __nv_bfloat16* __restrict__ CH,
                                             __nv_bfloat16* __restrict__ CL,
                                             int M, int N, int K) {
    constexpr int ST = 40;   // row stride in bf16 elems (80B)
    extern __shared__ char smem[];
    uint32_t sb = smem_u32(smem);

    int tid  = threadIdx.x;
    int wid  = tid >> 5, lane = tid & 31;
    int wr   = wid >> 2, wc = wid & 3;
    int g    = lane >> 2, tg = lane & 3;
    int row0 = blockIdx.y * 128, col0 = blockIdx.x * 128;

    const __nv_bfloat16* srcs[4] = { AH, AL, BH, BL };

    auto issue = [&](int k0, int s) {
        uint32_t sbase = sb + s * PG_STG;
        #pragma unroll
        for (int arr = 0; arr < 4; arr++) {
            const __nv_bfloat16* gs = srcs[arr];
            int rbase = (arr < 2) ? row0 : col0;
            #pragma unroll
            for (int i = 0; i < 2; i++) {
                int ch = tid + i * 256;
                int r = ch >> 2, cb = (ch & 3) * 16;
                const char* src = (const char*)(gs + (size_t)(rbase + r) * K + k0) + cb;
                uint32_t dst = sbase + arr * PG_ARR + r * 80 + cb;
                asm volatile("cp.async.cg.shared.global [%0], [%1], 16;"
                             :: "r"(dst), "l"(src) : "memory");
            }
        }
        asm volatile("cp.async.commit_group;" ::: "memory");
    };

    float c[4][4][4];
    #pragma unroll
    for (int mi = 0; mi < 4; mi++)
        #pragma unroll
        for (int ni = 0; ni < 4; ni++)
            #pragma unroll
            for (int r = 0; r < 4; r++) c[mi][ni][r] = 0.f;

    int nk = K / 32;
    issue(0, 0);

    for (int ki = 0; ki < nk; ki++) {
        if (ki + 1 < nk) {
            issue((ki + 1) * 32, (ki + 1) & 1);
            asm volatile("cp.async.wait_group 1;" ::: "memory");
        } else {
            asm volatile("cp.async.wait_group 0;" ::: "memory");
        }
        __syncthreads();

        const char* stg = smem + (ki & 1) * PG_STG;
        const __nv_bfloat16* Ah = (const __nv_bfloat16*)(stg);
        const __nv_bfloat16* Al = (const __nv_bfloat16*)(stg + PG_ARR);
        const __nv_bfloat16* Bh = (const __nv_bfloat16*)(stg + 2 * PG_ARR);
        const __nv_bfloat16* Bl = (const __nv_bfloat16*)(stg + 3 * PG_ARR);

        #pragma unroll
        for (int ks = 0; ks < 2; ks++) {
            int kk = ks * 16;
            uint32_t ah[4][4], al[4][4], bh[4][2], bl[4][2];
            #pragma unroll
            for (int mi = 0; mi < 4; mi++) {
                int r1 = (wr * 64 + mi * 16 + g) * ST + kk + 2 * tg;
                int r2 = r1 + 8 * ST;
                ah[mi][0] = *(const uint32_t*)&Ah[r1];
                ah[mi][1] = *(const uint32_t*)&Ah[r2];
                ah[mi][2] = *(const uint32_t*)&Ah[r1 + 8];
                ah[mi][3] = *(const uint32_t*)&Ah[r2 + 8];
                al[mi][0] = *(const uint32_t*)&Al[r1];
                al[mi][1] = *(const uint32_t*)&Al[r2];
                al[mi][2] = *(const uint32_t*)&Al[r1 + 8];
                al[mi][3] = *(const uint32_t*)&Al[r2 + 8];
            }
            #pragma unroll
            for (int ni = 0; ni < 4; ni++) {
                int n1 = (wc * 32 + ni * 8 + g) * ST + kk + 2 * tg;
                bh[ni][0] = *(const uint32_t*)&Bh[n1];
                bh[ni][1] = *(const uint32_t*)&Bh[n1 + 8];
                bl[ni][0] = *(const uint32_t*)&Bl[n1];
                bl[ni][1] = *(const uint32_t*)&Bl[n1 + 8];
            }
            #pragma unroll
            for (int mi = 0; mi < 4; mi++)
                #pragma unroll
                for (int ni = 0; ni < 4; ni++) {
                    mma_bf16(c[mi][ni], ah[mi], bh[ni]);
                    mma_bf16(c[mi][ni], ah[mi], bl[ni]);
                    mma_bf16(c[mi][ni], al[mi], bh[ni]);
                }
        }
        __syncthreads();
    }

    // ---- epilogue ----
    #pragma unroll
    for (int mi = 0; mi < 4; mi++)
        #pragma unroll
        for (int ni = 0; ni < 4; ni++) {
            int cc = col0 + wc * 32 + ni * 8 + tg * 2;
            #pragma unroll
            for (int hh = 0; hh < 2; hh++) {
                int r = row0 + wr * 64 + mi * 16 + g + hh * 8;
                float v0 = c[mi][ni][hh * 2 + 0];
                float v1 = c[mi][ni][hh * 2 + 1];
                if (EPI != 3) { v0 += bias[cc]; v1 += bias[cc + 1]; }
                if (EPI == 2) {
                    const float2 a2 = *(const float2*)(add + (size_t)r * N + cc);
                    v0 += a2.x; v1 += a2.y;
                }
                if (EPI == 1) {
                    float t0 = 0.7978845608028654f * (v0 + 0.044715f * v0 * v0 * v0);
                    v0 = 0.5f * v0 * (1.0f + tanhf(t0));
                    float t1 = 0.7978845608028654f * (v1 + 0.044715f * v1 * v1 * v1);
                    v1 = 0.5f * v1 * (1.0f + tanhf(t1));
                    uint32_t ph_, pl_;
                    pack_hl(v0, v1, ph_, pl_);
                    *(uint32_t*)&CH[(size_t)r * N + cc] = ph_;
                    *(uint32_t*)&CL[(size_t)r * N + cc] = pl_;
                } else {
                    float2 o2; o2.x = v0; o2.y = v1;
                    *(float2*)(Cf + (size_t)r * N + cc) = o2;
                }
            }
        }
}

// ---------------- MMA flash attention (3xBF16, causal, NO score scaling) ----
// Output written as bf16 hi/lo pair (feeds proj GEMM A).
__global__ __launch_bounds__(256) void attn_mma(const float* __restrict__ qkv,
                                                __nv_bfloat16* __restrict__ attH,
                                                __nv_bfloat16* __restrict__ attL) {
    constexpr int ST = 72;
    int b = blockIdx.z, h = blockIdx.y;
    int q0 = blockIdx.x * 128;
    int tid = threadIdx.x, wid = tid >> 5, lane = tid & 31;
    int g = lane >> 2, tg = lane & 3;
    int qw0 = q0 + wid * 16;
    const size_t base = (size_t)b * TSEQ * C3;

    __shared__ __nv_bfloat16 sH[64 * ST], sL[64 * ST];

    uint32_t qh[4][4], ql[4][4];
    {
        const float* q_r0 = qkv + base + (size_t)(qw0 + g) * C3 + h * HD;
        const float* q_r1 = q_r0 + 8 * C3;
        #pragma unroll
        for (int s = 0; s < 4; s++) {
            float2 v0 = *(const float2*)(q_r0 + 16 * s + 2 * tg);
            float2 v1 = *(const float2*)(q_r1 + 16 * s + 2 * tg);
            float2 v2 = *(const float2*)(q_r0 + 16 * s + 2 * tg + 8);
            float2 v3 = *(const float2*)(q_r1 + 16 * s + 2 * tg + 8);
            pack_hl(v0.x, v0.y, qh[s][0], ql[s][0]);
            pack_hl(v1.x, v1.y, qh[s][1], ql[s][1]);
            pack_hl(v2.x, v2.y, qh[s][2], ql[s][2]);
            pack_hl(v3.x, v3.y, qh[s][3], ql[s][3]);
        }
    }

    float o[8][4];
    #pragma unroll
    for (int ni = 0; ni < 8; ni++)
        #pragma unroll
        for (int r = 0; r < 4; r++) o[ni][r] = 0.f;
    float m0 = -1e30f, m1 = -1e30f, l0 = 0.f, l1 = 0.f;

    int kend = q0 + 128;
    for (int j0 = 0; j0 < kend; j0 += 64) {
        bool act = (j0 <= qw0 + 15);
        __syncthreads();
        {
            int kk = tid >> 2, d0 = (tid & 3) * 16;
            const float* kp = qkv + base + (size_t)(j0 + kk) * C3 + CDIM + h * HD + d0;
            #pragma unroll
            for (int i = 0; i < 4; i++) {
                float4 v = ((const float4*)kp)[i];
                int idx = kk * ST + d0 + i * 4;
                pack_hl(v.x, v.y, *(uint32_t*)&sH[idx],     *(uint32_t*)&sL[idx]);
                pack_hl(v.z, v.w, *(uint32_t*)&sH[idx + 2], *(uint32_t*)&sL[idx + 2]);
            }
        }
        __syncthreads();

        uint32_t ph[4][4], pl[4][4];
        if (act) {
            float s[8][4];
            #pragma unroll
            for (int ni = 0; ni < 8; ni++) {
                s[ni][0] = s[ni][1] = s[ni][2] = s[ni][3] = 0.f;
                #pragma unroll
                for (int ss = 0; ss < 4; ss++) {
                    int ib = (8 * ni + g) * ST + 16 * ss + 2 * tg;
                    uint32_t bh[2] = { *(const uint32_t*)&sH[ib], *(const uint32_t*)&sH[ib + 8] };
                    uint32_t bl[2] = { *(const uint32_t*)&sL[ib], *(const uint32_t*)&sL[ib + 8] };
                    mma_bf16(s[ni], qh[ss], bh);
                    mma_bf16(s[ni], qh[ss], bl);
                    mma_bf16(s[ni], ql[ss], bh);
                }
            }
            int r0 = qw0 + g, r1 = r0 + 8;
            float mx0 = -1e30f, mx1 = -1e30f;
            #pragma unroll
            for (int ni = 0; ni < 8; ni++) {
                int kc = j0 + 8 * ni + 2 * tg;
                if (kc     > r0) s[ni][0] = -1e30f;
                if (kc + 1 > r0) s[ni][1] = -1e30f;
                if (kc     > r1) s[ni][2] = -1e30f;
                if (kc + 1 > r1) s[ni][3] = -1e30f;
                mx0 = fmaxf(mx0, fmaxf(s[ni][0], s[ni][1]));
                mx1 = fmaxf(mx1, fmaxf(s[ni][2], s[ni][3]));
            }
            mx0 = fmaxf(mx0, __shfl_xor_sync(0xffffffffu, mx0, 1));
            mx0 = fmaxf(mx0, __shfl_xor_sync(0xffffffffu, mx0, 2));
            mx1 = fmaxf(mx1, __shfl_xor_sync(0xffffffffu, mx1, 1));
            mx1 = fmaxf(mx1, __shfl_xor_sync(0xffffffffu, mx1, 2));
            float nm0 = fmaxf(m0, mx0), nm1 = fmaxf(m1, mx1);
            float c0 = __expf(m0 - nm0), c1 = __expf(m1 - nm1);
            m0 = nm0; m1 = nm1;
            float p[8][4];
            float ls0 = 0.f, ls1 = 0.f;
            #pragma unroll
            for (int ni = 0; ni < 8; ni++) {
                p[ni][0] = __expf(s[ni][0] - nm0);
                p[ni][1] = __expf(s[ni][1] - nm0);
                p[ni][2] = __expf(s[ni][2] - nm1);
                p[ni][3] = __expf(s[ni][3] - nm1);
                ls0 += p[ni][0] + p[ni][1];
                ls1 += p[ni][2] + p[ni][3];
            }
            l0 = l0 * c0 + ls0;
            l1 = l1 * c1 + ls1;
            #pragma unroll
            for (int ni = 0; ni < 8; ni++) {
                o[ni][0] *= c0; o[ni][1] *= c0; o[ni][2] *= c1; o[ni][3] *= c1;
            }
            #pragma unroll
            for (int ss = 0; ss < 4; ss++) {
                pack_hl(p[2*ss][0],   p[2*ss][1],   ph[ss][0], pl[ss][0]);
                pack_hl(p[2*ss][2],   p[2*ss][3],   ph[ss][1], pl[ss][1]);
                pack_hl(p[2*ss+1][0], p[2*ss+1][1], ph[ss][2], pl[ss][2]);
                pack_hl(p[2*ss+1][2], p[2*ss+1][3], ph[ss][3], pl[ss][3]);
            }
        }
        __syncthreads();
        {
            int kk = tid >> 2, d0 = (tid & 3) * 16;
            const float* vp = qkv + base + (size_t)(j0 + kk) * C3 + 2 * CDIM + h * HD + d0;
            #pragma unroll
            for (int i = 0; i < 4; i++) {
                float4 v = ((const float4*)vp)[i];
                int d = d0 + i * 4;
                uint16_t hh, ll;
                bsplit(v.x, hh, ll);
                sH[(d + 0) * ST + kk] = __ushort_as_bfloat16(hh);
                sL[(d + 0) * ST + kk] = __ushort_as_bfloat16(ll);
                bsplit(v.y, hh, ll);
                sH[(d + 1) * ST + kk] = __ushort_as_bfloat16(hh);
                sL[(d + 1) * ST + kk] = __ushort_as_bfloat16(ll);
                bsplit(v.z, hh, ll);
                sH[(d + 2) * ST + kk] = __ushort_as_bfloat16(hh);
                sL[(d + 2) * ST + kk] = __ushort_as_bfloat16(ll);
                bsplit(v.w, hh, ll);
                sH[(d + 3) * ST + kk] = __ushort_as_bfloat16(hh);
                sL[(d + 3) * ST + kk] = __ushort_as_bfloat16(ll);
            }
        }
        __syncthreads();
        if (act) {
            #pragma unroll
            for (int ni = 0; ni < 8; ni++)
                #pragma unroll
                for (int ss = 0; ss < 4; ss++) {
                    int ib = (8 * ni + g) * ST + 16 * ss + 2 * tg;
                    uint32_t bh[2] = { *(const uint32_t*)&sH[ib], *(const uint32_t*)&sH[ib + 8] };
                    uint32_t bl[2] = { *(const uint32_t*)&sL[ib], *(const uint32_t*)&sL[ib + 8] };
                    mma_bf16(o[ni], ph[ss], bh);
                    mma_bf16(o[ni], ph[ss], bl);
                    mma_bf16(o[ni], pl[ss], bh);
                }
        }
    }

    l0 += __shfl_xor_sync(0xffffffffu, l0, 1);
    l0 += __shfl_xor_sync(0xffffffffu, l0, 2);
    l1 += __shfl_xor_sync(0xffffffffu, l1, 1);
    l1 += __shfl_xor_sync(0xffffffffu, l1, 2);
    float i0 = 1.f / l0, i1 = 1.f / l1;
    size_t ro0 = (size_t)(b * TSEQ + qw0 + g) * CDIM + h * HD;
    size_t ro1 = ro0 + 8 * CDIM;
    #pragma unroll
    for (int ni = 0; ni < 8; ni++) {
        uint32_t hA, lA;
        pack_hl(o[ni][0] * i0, o[ni][1] * i0, hA, lA);
        *(uint32_t*)&attH[ro0 + 8 * ni + 2 * tg] = hA;
        *(uint32_t*)&attL[ro0 + 8 * ni + 2 * tg] = lA;
        pack_hl(o[ni][2] * i1, o[ni][3] * i1, hA, lA);
        *(uint32_t*)&attH[ro1 + 8 * ni + 2 * tg] = hA;
        *(uint32_t*)&attL[ro1 + 8 * ni + 2 * tg] = lA;
    }
}

// ---------------- per-row cross-entropy ----------------
__global__ __launch_bounds__(256) void loss_row_kernel(const float* __restrict__ logits,
                                                       const int* __restrict__ targets) {
    int row = blockIdx.x;
    const float* x = logits + (size_t)row * VOCAB;
    __shared__ float sh[8];
    float mx = -1e30f;
    for (int c = threadIdx.x; c < VOCAB; c += 256) mx = fmaxf(mx, x[c]);
    #pragma unroll
    for (int o = 16; o; o >>= 1) mx = fmaxf(mx, __shfl_down_sync(0xffffffffu, mx, o));
    if ((threadIdx.x & 31) == 0) sh[threadIdx.x >> 5] = mx;
    __syncthreads();
    if (threadIdx.x == 0) {
        float a = sh[0];
        #pragma unroll
        for (int i = 1; i < 8; i++) a = fmaxf(a, sh[i]);
        sh[0] = a;
    }
    __syncthreads();
    mx = sh[0];
    __syncthreads();
    float s = 0.f;
    for (int c = threadIdx.x; c < VOCAB; c += 256) s += expf(x[c] - mx);
    #pragma unroll
    for (int o = 16; o; o >>= 1) s += __shfl_down_sync(0xffffffffu, s, o);
    if ((threadIdx.x & 31) == 0) sh[threadIdx.x >> 5] = s;
    __syncthreads();
    if (threadIdx.x == 0) {
        float a = 0.f;
        #pragma unroll
        for (int i = 0; i < 8; i++) a += sh[i];
        g_rowloss[row] = (mx + logf(a)) - x[targets[row]];
    }
}

__global__ __launch_bounds__(1024) void loss_reduce_kernel(float* __restrict__ out) {
    __shared__ float sh[1024];
    int t = threadIdx.x;
    float s = 0.f;
    for (int i = t; i < NTOK; i += 1024) s += g_rowloss[i];
    sh[t] = s;
    __syncthreads();
    for (int o = 512; o; o >>= 1) {
        if (t < o) sh[t] += sh[t + o];
        __syncthreads();
    }
    if (t == 0) out[0] = sh[0] * (1.f / NTOK);
}

// ---------------- launch ----------------
extern "C" void kernel_launch(void* const* d_in, const int* in_sizes, int n_in,
                              void* d_out, int out_size) {
    const int*   x       = (const int*)  d_in[0];
    const int*   targets = (const int*)  d_in[1];
    const float* wte     = (const float*)d_in[2];
    const float* wpe     = (const float*)d_in[3];
    const float* ln1_w   = (const float*)d_in[4];
    const float* ln1_b   = (const float*)d_in[5];
    const float* attn_w  = (const float*)d_in[6];
    const float* attn_b  = (const float*)d_in[7];
    const float* proj_w  = (const float*)d_in[8];
    const float* proj_b  = (const float*)d_in[9];
    const float* ln2_w   = (const float*)d_in[10];
    const float* ln2_b   = (const float*)d_in[11];
    const float* fc_w    = (const float*)d_in[12];
    const float* fc_b    = (const float*)d_in[13];
    const float* fc2_w   = (const float*)d_in[14];
    const float* fc2_b   = (const float*)d_in[15];
    const float* lnf_w   = (const float*)d_in[16];
    const float* lnf_b   = (const float*)d_in[17];

    float* logits = (float*)d_out;
    float* lossp  = (float*)d_out + (out_size - 1);

    float *p_h, *p_qkv;
    __nv_bfloat16 *p_hnH, *p_hnL, *p_attH, *p_attL, *p_fcH, *p_fcL;
    __nv_bfloat16 *p_waH, *p_waL, *p_wpH, *p_wpL, *p_wfH, *p_wfL, *p_wf2H, *p_wf2L, *p_wteH, *p_wteL;
    cudaGetSymbolAddress((void**)&p_h,    g_h);
    cudaGetSymbolAddress((void**)&p_qkv,  g_qkv);
    cudaGetSymbolAddress((void**)&p_hnH,  g_hnH);
    cudaGetSymbolAddress((void**)&p_hnL,  g_hnL);
    cudaGetSymbolAddress((void**)&p_attH, g_attH);
    cudaGetSymbolAddress((void**)&p_attL, g_attL);
    cudaGetSymbolAddress((void**)&p_fcH,  g_fcH);
    cudaGetSymbolAddress((void**)&p_fcL,  g_fcL);
    cudaGetSymbolAddress((void**)&p_waH,  g_waH);
    cudaGetSymbolAddress((void**)&p_waL,  g_waL);
    cudaGetSymbolAddress((void**)&p_wpH,  g_wpH);
    cudaGetSymbolAddress((void**)&p_wpL,  g_wpL);
    cudaGetSymbolAddress((void**)&p_wfH,  g_wfH);
    cudaGetSymbolAddress((void**)&p_wfL,  g_wfL);
    cudaGetSymbolAddress((void**)&p_wf2H, g_wf2H);
    cudaGetSymbolAddress((void**)&p_wf2L, g_wf2L);
    cudaGetSymbolAddress((void**)&p_wteH, g_wteH);
    cudaGetSymbolAddress((void**)&p_wteL, g_wteL);

    cudaFuncSetAttribute(pgemm<0>, cudaFuncAttributeMaxDynamicSharedMemorySize, PG_SMEM);
    cudaFuncSetAttribute(pgemm<1>, cudaFuncAttributeMaxDynamicSharedMemorySize, PG_SMEM);
    cudaFuncSetAttribute(pgemm<2>, cudaFuncAttributeMaxDynamicSharedMemorySize, PG_SMEM);
    cudaFuncSetAttribute(pgemm<3>, cudaFuncAttributeMaxDynamicSharedMemorySize, PG_SMEM);

    // ---- weight pre-split (once per launch) ----
    wsplit_t<<<dim3(C3 / 32, CDIM / 32, NLAYER), 256>>>(attn_w, p_waH, p_waL, CDIM, C3);
    wsplit_t<<<dim3(CDIM / 32, CDIM / 32, NLAYER), 256>>>(proj_w, p_wpH, p_wpL, CDIM, CDIM);
    wsplit_t<<<dim3(C4 / 32, CDIM / 32, NLAYER), 256>>>(fc_w, p_wfH, p_wfL, CDIM, C4);
    wsplit_t<<<dim3(CDIM / 32, C4 / 32, NLAYER), 256>>>(fc2_w, p_wf2H, p_wf2L, C4, CDIM);
    wsplit<<<(WTEN / 2 + 255) / 256, 256>>>(wte, p_wteH, p_wteL, WTEN);

    embed_kernel<<<NTOK, 256>>>(x, wte, wpe);

    for (int l = 0; l < NLAYER; l++) {
        ln_kernel<<<NTOK, 256>>>(p_h, ln1_w + (size_t)l * CDIM, ln1_b + (size_t)l * CDIM, p_hnH, p_hnL);
        pgemm<0><<<dim3(C3 / 128, NTOK / 128), 256, PG_SMEM>>>(
            p_hnH, p_hnL, p_waH + (size_t)l * C3 * CDIM, p_waL + (size_t)l * C3 * CDIM,
            attn_b + (size_t)l * C3, nullptr, p_qkv, nullptr, nullptr, NTOK, C3, CDIM);
        attn_mma<<<dim3(TSEQ / 128, NHEAD, BATCH), 256>>>(p_qkv, p_attH, p_attL);
        pgemm<2><<<dim3(CDIM / 128, NTOK / 128), 256, PG_SMEM>>>(
            p_attH, p_attL, p_wpH + (size_t)l * CDIM * CDIM, p_wpL + (size_t)l * CDIM * CDIM,
            proj_b + (size_t)l * CDIM, p_h, p_h, nullptr, nullptr, NTOK, CDIM, CDIM);
        ln_kernel<<<NTOK, 256>>>(p_h, ln2_w + (size_t)l * CDIM, ln2_b + (size_t)l * CDIM, p_hnH, p_hnL);
        pgemm<1><<<dim3(C4 / 128, NTOK / 128), 256, PG_SMEM>>>(
            p_hnH, p_hnL, p_wfH + (size_t)l * C4 * CDIM, p_wfL + (size_t)l * C4 * CDIM,
            fc_b + (size_t)l * C4, nullptr, nullptr, p_fcH, p_fcL, NTOK, C4, CDIM);
        pgemm<2><<<dim3(CDIM / 128, NTOK / 128), 256, PG_SMEM>>>(
            p_fcH, p_fcL, p_wf2H + (size_t)l * CDIM * C4, p_wf2L + (size_t)l * CDIM * C4,
            fc2_b + (size_t)l * CDIM, p_h, p_h, nullptr, nullptr, NTOK, CDIM, C4);
    }

    ln_kernel<<<NTOK, 256>>>(p_h, lnf_w, lnf_b, p_hnH, p_hnL);
    pgemm<3><<<dim3(VOCAB / 128, NTOK / 128), 256, PG_SMEM>>>(
        p_hnH, p_hnL, p_wteH, p_wteL, nullptr, nullptr, logits, nullptr, nullptr,
        NTOK, VOCAB, CDIM);

    loss_row_kernel<<<NTOK, 256>>>(logits, targets);
    loss_reduce_kernel<<<1, 1024>>>(lossp);
}

// round 13
// speedup vs baseline: 1.1373x; 1.0107x over previous
#include <cuda_runtime.h>
#include <cuda_bf16.h>
#include <math.h>
#include <stdint.h>

// ---------------- problem constants ----------------
#define BATCH 4
#define TSEQ  1024
#define CDIM  768
#define NHEAD 12
#define HD    64
#define VOCAB 50304
#define NLAYER 12
#define NTOK  (BATCH*TSEQ)     // 4096
#define C3    (3*CDIM)         // 2304
#define C4    (4*CDIM)         // 3072

#define WATTN (NLAYER*C3*CDIM)
#define WPROJ (NLAYER*CDIM*CDIM)
#define WFC   (NLAYER*C4*CDIM)
#define WFC2  (NLAYER*CDIM*C4)
#define WTEN  (VOCAB*CDIM)

// ---------------- scratch (static device globals; no allocation allowed) ----
__device__ float g_h   [NTOK * CDIM];
__device__ float g_qkv [NTOK * C3];
__device__ float g_rowloss[NTOK];
__device__ __nv_bfloat16 g_hnH[NTOK * CDIM], g_hnL[NTOK * CDIM];
__device__ __nv_bfloat16 g_attH[NTOK * CDIM], g_attL[NTOK * CDIM];
__device__ __nv_bfloat16 g_fcH[NTOK * C4],   g_fcL[NTOK * C4];
__device__ __nv_bfloat16 g_waH[WATTN],  g_waL[WATTN];    // [L][3C][C]
__device__ __nv_bfloat16 g_wpH[WPROJ],  g_wpL[WPROJ];    // [L][C][C]  (transposed)
__device__ __nv_bfloat16 g_wfH[WFC],    g_wfL[WFC];      // [L][4C][C]
__device__ __nv_bfloat16 g_wf2H[WFC2],  g_wf2L[WFC2];    // [L][C][4C]
__device__ __nv_bfloat16 g_wteH[WTEN],  g_wteL[WTEN];    // [V][C]

// ---------------- bf16 split helpers ----------------
__device__ __forceinline__ void bsplit(float x, uint16_t& h, uint16_t& l) {
    __nv_bfloat16 bh = __float2bfloat16_rn(x);
    h = __bfloat16_as_ushort(bh);
    float r = x - __bfloat162float(bh);
    l = __bfloat16_as_ushort(__float2bfloat16_rn(r));
}
__device__ __forceinline__ void pack_hl(float vx, float vy, uint32_t& h, uint32_t& l) {
    uint16_t hx, lx, hy, ly;
    bsplit(vx, hx, lx); bsplit(vy, hy, ly);
    h = (uint32_t)hx | ((uint32_t)hy << 16);
    l = (uint32_t)lx | ((uint32_t)ly << 16);
}
__device__ __forceinline__ void mma_bf16(float* c, const uint32_t* a, const uint32_t* b) {
    asm volatile(
        "mma.sync.aligned.m16n8k16.row.col.f32.bf16.bf16.f32 "
        "{%0,%1,%2,%3},{%4,%5,%6,%7},{%8,%9},{%0,%1,%2,%3};"
        : "+f"(c[0]), "+f"(c[1]), "+f"(c[2]), "+f"(c[3])
        : "r"(a[0]), "r"(a[1]), "r"(a[2]), "r"(a[3]), "r"(b[0]), "r"(b[1]));
}
__device__ __forceinline__ uint32_t smem_u32(const void* p) {
    uint32_t a;
    asm("{ .reg .u64 t; cvta.to.shared.u64 t, %1; cvt.u32.u64 %0, t; }" : "=r"(a) : "l"(p));
    return a;
}
__device__ __forceinline__ void ldsm4(uint32_t& r0, uint32_t& r1, uint32_t& r2, uint32_t& r3,
                                      uint32_t addr) {
    asm volatile("ldmatrix.sync.aligned.m8n8.x4.shared.b16 {%0,%1,%2,%3}, [%4];"
                 : "=r"(r0), "=r"(r1), "=r"(r2), "=r"(r3) : "r"(addr));
}

// ---------------- weight conversion kernels (once per launch) ----------------
__global__ __launch_bounds__(256) void wsplit_t(const float* __restrict__ in,
                                                __nv_bfloat16* __restrict__ oh,
                                                __nv_bfloat16* __restrict__ ol,
                                                int K, int N) {
    __shared__ float t[32][33];
    size_t loff = (size_t)blockIdx.z * K * N;
    const float* src = in + loff;
    int nb = blockIdx.x * 32, kb = blockIdx.y * 32;
    int tx = threadIdx.x & 31, ty = threadIdx.x >> 5;   // 32 x 8
    #pragma unroll
    for (int i = 0; i < 32; i += 8)
        t[ty + i][tx] = src[(size_t)(kb + ty + i) * N + nb + tx];
    __syncthreads();
    #pragma unroll
    for (int i = 0; i < 32; i += 8) {
        float v = t[tx][ty + i];
        uint16_t h, l; bsplit(v, h, l);
        size_t o = loff + (size_t)(nb + ty + i) * K + kb + tx;
        oh[o] = __ushort_as_bfloat16(h);
        ol[o] = __ushort_as_bfloat16(l);
    }
}
__global__ __launch_bounds__(256) void wsplit(const float* __restrict__ in,
                                              __nv_bfloat16* __restrict__ oh,
                                              __nv_bfloat16* __restrict__ ol, int n) {
    int i = (blockIdx.x * 256 + threadIdx.x) * 2;
    if (i < n) {
        uint32_t h, l;
        pack_hl(in[i], in[i + 1], h, l);
        *(uint32_t*)&oh[i] = h;
        *(uint32_t*)&ol[i] = l;
    }
}

// ---------------- embedding ----------------
__global__ __launch_bounds__(256) void embed_kernel(const int* __restrict__ x,
                                                    const float* __restrict__ wte,
                                                    const float* __restrict__ wpe) {
    int m = blockIdx.x;
    int t = m % TSEQ;
    int idx = x[m];
    const float* we = wte + (size_t)idx * CDIM;
    const float* wp = wpe + (size_t)t * CDIM;
    float* o = g_h + (size_t)m * CDIM;
    for (int c = threadIdx.x; c < CDIM; c += 256)
        o[c] = we[c] + wp[c];
}

// ---------------- layernorm: fp32 in -> bf16 hi/lo pair out ----------------
__global__ __launch_bounds__(256) void ln_kernel(const float* __restrict__ in,
                                                 const float* __restrict__ w,
                                                 const float* __restrict__ bb,
                                                 __nv_bfloat16* __restrict__ oh,
                                                 __nv_bfloat16* __restrict__ ol) {
    int row = blockIdx.x;
    const float* x = in + (size_t)row * CDIM;
    float s = 0.f, s2 = 0.f;
    for (int c = threadIdx.x; c < CDIM; c += 256) {
        float v = x[c]; s += v; s2 += v * v;
    }
    __shared__ float ss[8], ss2[8];
    #pragma unroll
    for (int o = 16; o; o >>= 1) {
        s  += __shfl_down_sync(0xffffffffu, s,  o);
        s2 += __shfl_down_sync(0xffffffffu, s2, o);
    }
    if ((threadIdx.x & 31) == 0) { ss[threadIdx.x >> 5] = s; ss2[threadIdx.x >> 5] = s2; }
    __syncthreads();
    if (threadIdx.x == 0) {
        float a = 0.f, a2 = 0.f;
        #pragma unroll
        for (int i = 0; i < 8; i++) { a += ss[i]; a2 += ss2[i]; }
        ss[0] = a; ss2[0] = a2;
    }
    __syncthreads();
    float mean = ss[0] * (1.f / CDIM);
    float var  = ss2[0] * (1.f / CDIM) - mean * mean;
    float rstd = rsqrtf(var + 1e-5f);
    __nv_bfloat16* oH = oh + (size_t)row * CDIM;
    __nv_bfloat16* oL = ol + (size_t)row * CDIM;
    for (int c = threadIdx.x * 2; c < CDIM; c += 512) {
        float v0 = (x[c]     - mean) * rstd * w[c]     + bb[c];
        float v1 = (x[c + 1] - mean) * rstd * w[c + 1] + bb[c + 1];
        uint32_t hh, ll;
        pack_hl(v0, v1, hh, ll);
        *(uint32_t*)&oH[c] = hh;
        *(uint32_t*)&oL[c] = ll;
    }
}

// ---------------- pipelined 3xBF16 GEMM (pre-split inputs, cp.async, ldmatrix)
// C = epi(A @ B^T): A pair [M][K], B pair [N][K] (k-contiguous rows).
// EPI: 0 = +bias -> fp32; 1 = +bias,gelu -> bf16 pair; 2 = +bias+residual -> fp32;
//      3 = plain -> fp32.
#define PG_STG   40960
#define PG_ARR   10240
#define PG_SMEM  (2 * PG_STG)

template<int EPI>
__global__ __launch_bounds__(256) void pgemm(const __nv_bfloat16* __restrict__ AH,
                                             const __nv_bfloat16* __restrict__ AL,
                                             const __nv_bfloat16* __restrict__ BH,
                                             const __nv_bfloat16* __restrict__ BL,
                                             const float* __restrict__ bias,
                                             const float* __restrict__ add,
                                             float* __restrict__ Cf,
                                             __nv_bfloat16* __restrict__ CH,
                                             __nv_bfloat16* __restrict__ CL,
                                             int M, int N, int K) {
    constexpr int ST = 40;   // row stride in bf16 elems (80B)
    extern __shared__ char smem[];
    uint32_t sb = smem_u32(smem);

    int tid  = threadIdx.x;
    int wid  = tid >> 5, lane = tid & 31;
    int wr   = wid >> 2, wc = wid & 3;
    int g    = lane >> 2, tg = lane & 3;
    int row0 = blockIdx.y * 128, col0 = blockIdx.x * 128;

    // ldmatrix lane coords: 16-row group, 8-col half
    const uint32_t lrow = lane & 15;
    const uint32_t lcol = (lane >> 4) << 3;

    const __nv_bfloat16* srcs[4] = { AH, AL, BH, BL };

    auto issue = [&](int k0, int s) {
        uint32_t sbase = sb + s * PG_STG;
        #pragma unroll
        for (int arr = 0; arr < 4; arr++) {
            const __nv_bfloat16* gs = srcs[arr];
            int rbase = (arr < 2) ? row0 : col0;
            #pragma unroll
            for (int i = 0; i < 2; i++) {
                int ch = tid + i * 256;
                int r = ch >> 2, cb = (ch & 3) * 16;
                const char* src = (const char*)(gs + (size_t)(rbase + r) * K + k0) + cb;
                uint32_t dst = sbase + arr * PG_ARR + r * 80 + cb;
                asm volatile("cp.async.cg.shared.global [%0], [%1], 16;"
                             :: "r"(dst), "l"(src) : "memory");
            }
        }
        asm volatile("cp.async.commit_group;" ::: "memory");
    };

    float c[4][4][4];
    #pragma unroll
    for (int mi = 0; mi < 4; mi++)
        #pragma unroll
        for (int ni = 0; ni < 4; ni++)
            #pragma unroll
            for (int r = 0; r < 4; r++) c[mi][ni][r] = 0.f;

    int nk = K / 32;
    issue(0, 0);

    for (int ki = 0; ki < nk; ki++) {
        if (ki + 1 < nk) {
            issue((ki + 1) * 32, (ki + 1) & 1);
            asm volatile("cp.async.wait_group 1;" ::: "memory");
        } else {
            asm volatile("cp.async.wait_group 0;" ::: "memory");
        }
        __syncthreads();

        uint32_t sAh = sb + (ki & 1) * PG_STG;
        uint32_t sAl = sAh + PG_ARR;
        uint32_t sBh = sAh + 2 * PG_ARR;
        uint32_t sBl = sAh + 3 * PG_ARR;

        #pragma unroll
        for (int ks = 0; ks < 2; ks++) {
            int kk = ks * 16;
            uint32_t ah[4][4], al[4][4], bh[4][2], bl[4][2];
            #pragma unroll
            for (int mi = 0; mi < 4; mi++) {
                uint32_t off = ((wr * 64 + mi * 16 + lrow) * ST + kk + lcol) * 2;
                ldsm4(ah[mi][0], ah[mi][1], ah[mi][2], ah[mi][3], sAh + off);
                ldsm4(al[mi][0], al[mi][1], al[mi][2], al[mi][3], sAl + off);
            }
            #pragma unroll
            for (int q = 0; q < 2; q++) {
                uint32_t off = ((wc * 32 + q * 16 + lrow) * ST + kk + lcol) * 2;
                uint32_t r0, r1, r2, r3;
                ldsm4(r0, r1, r2, r3, sBh + off);
                bh[2*q][0] = r0; bh[2*q+1][0] = r1; bh[2*q][1] = r2; bh[2*q+1][1] = r3;
                ldsm4(r0, r1, r2, r3, sBl + off);
                bl[2*q][0] = r0; bl[2*q+1][0] = r1; bl[2*q][1] = r2; bl[2*q+1][1] = r3;
            }
            #pragma unroll
            for (int mi = 0; mi < 4; mi++)
                #pragma unroll
                for (int ni = 0; ni < 4; ni++) {
                    mma_bf16(c[mi][ni], ah[mi], bh[ni]);
                    mma_bf16(c[mi][ni], ah[mi], bl[ni]);
                    mma_bf16(c[mi][ni], al[mi], bh[ni]);
                }
        }
        __syncthreads();
    }

    // ---- epilogue ----
    #pragma unroll
    for (int mi = 0; mi < 4; mi++)
        #pragma unroll
        for (int ni = 0; ni < 4; ni++) {
            int cc = col0 + wc * 32 + ni * 8 + tg * 2;
            #pragma unroll
            for (int hh = 0; hh < 2; hh++) {
                int r = row0 + wr * 64 + mi * 16 + g + hh * 8;
                float v0 = c[mi][ni][hh * 2 + 0];
                float v1 = c[mi][ni][hh * 2 + 1];
                if (EPI != 3) { v0 += bias[cc]; v1 += bias[cc + 1]; }
                if (EPI == 2) {
                    const float2 a2 = *(const float2*)(add + (size_t)r * N + cc);
                    v0 += a2.x; v1 += a2.y;
                }
                if (EPI == 1) {
                    float t0 = 0.7978845608028654f * (v0 + 0.044715f * v0 * v0 * v0);
                    v0 = 0.5f * v0 * (1.0f + tanhf(t0));
                    float t1 = 0.7978845608028654f * (v1 + 0.044715f * v1 * v1 * v1);
                    v1 = 0.5f * v1 * (1.0f + tanhf(t1));
                    uint32_t ph_, pl_;
                    pack_hl(v0, v1, ph_, pl_);
                    *(uint32_t*)&CH[(size_t)r * N + cc] = ph_;
                    *(uint32_t*)&CL[(size_t)r * N + cc] = pl_;
                } else {
                    float2 o2; o2.x = v0; o2.y = v1;
                    *(float2*)(Cf + (size_t)r * N + cc) = o2;
                }
            }
        }
}

// ---------------- MMA flash attention (3xBF16, causal, NO score scaling) ----
__global__ __launch_bounds__(256) void attn_mma(const float* __restrict__ qkv,
                                                __nv_bfloat16* __restrict__ attH,
                                                __nv_bfloat16* __restrict__ attL) {
    constexpr int ST = 72;
    int b = blockIdx.z, h = blockIdx.y;
    int q0 = blockIdx.x * 128;
    int tid = threadIdx.x, wid = tid >> 5, lane = tid & 31;
    int g = lane >> 2, tg = lane & 3;
    int qw0 = q0 + wid * 16;
    const size_t base = (size_t)b * TSEQ * C3;

    __shared__ __nv_bfloat16 sH[64 * ST], sL[64 * ST];

    uint32_t qh[4][4], ql[4][4];
    {
        const float* q_r0 = qkv + base + (size_t)(qw0 + g) * C3 + h * HD;
        const float* q_r1 = q_r0 + 8 * C3;
        #pragma unroll
        for (int s = 0; s < 4; s++) {
            float2 v0 = *(const float2*)(q_r0 + 16 * s + 2 * tg);
            float2 v1 = *(const float2*)(q_r1 + 16 * s + 2 * tg);
            float2 v2 = *(const float2*)(q_r0 + 16 * s + 2 * tg + 8);
            float2 v3 = *(const float2*)(q_r1 + 16 * s + 2 * tg + 8);
            pack_hl(v0.x, v0.y, qh[s][0], ql[s][0]);
            pack_hl(v1.x, v1.y, qh[s][1], ql[s][1]);
            pack_hl(v2.x, v2.y, qh[s][2], ql[s][2]);
            pack_hl(v3.x, v3.y, qh[s][3], ql[s][3]);
        }
    }

    float o[8][4];
    #pragma unroll
    for (int ni = 0; ni < 8; ni++)
        #pragma unroll
        for (int r = 0; r < 4; r++) o[ni][r] = 0.f;
    float m0 = -1e30f, m1 = -1e30f, l0 = 0.f, l1 = 0.f;

    int kend = q0 + 128;
    for (int j0 = 0; j0 < kend; j0 += 64) {
        bool act = (j0 <= qw0 + 15);
        __syncthreads();
        {
            int kk = tid >> 2, d0 = (tid & 3) * 16;
            const float* kp = qkv + base + (size_t)(j0 + kk) * C3 + CDIM + h * HD + d0;
            #pragma unroll
            for (int i = 0; i < 4; i++) {
                float4 v = ((const float4*)kp)[i];
                int idx = kk * ST + d0 + i * 4;
                pack_hl(v.x, v.y, *(uint32_t*)&sH[idx],     *(uint32_t*)&sL[idx]);
                pack_hl(v.z, v.w, *(uint32_t*)&sH[idx + 2], *(uint32_t*)&sL[idx + 2]);
            }
        }
        __syncthreads();

        uint32_t ph[4][4], pl[4][4];
        if (act) {
            float s[8][4];
            #pragma unroll
            for (int ni = 0; ni < 8; ni++) {
                s[ni][0] = s[ni][1] = s[ni][2] = s[ni][3] = 0.f;
                #pragma unroll
                for (int ss = 0; ss < 4; ss++) {
                    int ib = (8 * ni + g) * ST + 16 * ss + 2 * tg;
                    uint32_t bh[2] = { *(const uint32_t*)&sH[ib], *(const uint32_t*)&sH[ib + 8] };
                    uint32_t bl[2] = { *(const uint32_t*)&sL[ib], *(const uint32_t*)&sL[ib + 8] };
                    mma_bf16(s[ni], qh[ss], bh);
                    mma_bf16(s[ni], qh[ss], bl);
                    mma_bf16(s[ni], ql[ss], bh);
                }
            }
            int r0 = qw0 + g, r1 = r0 + 8;
            float mx0 = -1e30f, mx1 = -1e30f;
            #pragma unroll
            for (int ni = 0; ni < 8; ni++) {
                int kc = j0 + 8 * ni + 2 * tg;
                if (kc     > r0) s[ni][0] = -1e30f;
                if (kc + 1 > r0) s[ni][1] = -1e30f;
                if (kc     > r1) s[ni][2] = -1e30f;
                if (kc + 1 > r1) s[ni][3] = -1e30f;
                mx0 = fmaxf(mx0, fmaxf(s[ni][0], s[ni][1]));
                mx1 = fmaxf(mx1, fmaxf(s[ni][2], s[ni][3]));
            }
            mx0 = fmaxf(mx0, __shfl_xor_sync(0xffffffffu, mx0, 1));
            mx0 = fmaxf(mx0, __shfl_xor_sync(0xffffffffu, mx0, 2));
            mx1 = fmaxf(mx1, __shfl_xor_sync(0xffffffffu, mx1, 1));
            mx1 = fmaxf(mx1, __shfl_xor_sync(0xffffffffu, mx1, 2));
            float nm0 = fmaxf(m0, mx0), nm1 = fmaxf(m1, mx1);
            float c0 = __expf(m0 - nm0), c1 = __expf(m1 - nm1);
            m0 = nm0; m1 = nm1;
            float p[8][4];
            float ls0 = 0.f, ls1 = 0.f;
            #pragma unroll
            for (int ni = 0; ni < 8; ni++) {
                p[ni][0] = __expf(s[ni][0] - nm0);
                p[ni][1] = __expf(s[ni][1] - nm0);
                p[ni][2] = __expf(s[ni][2] - nm1);
                p[ni][3] = __expf(s[ni][3] - nm1);
                ls0 += p[ni][0] + p[ni][1];
                ls1 += p[ni][2] + p[ni][3];
            }
            l0 = l0 * c0 + ls0;
            l1 = l1 * c1 + ls1;
            #pragma unroll
            for (int ni = 0; ni < 8; ni++) {
                o[ni][0] *= c0; o[ni][1] *= c0; o[ni][2] *= c1; o[ni][3] *= c1;
            }
            #pragma unroll
            for (int ss = 0; ss < 4; ss++) {
                pack_hl(p[2*ss][0],   p[2*ss][1],   ph[ss][0], pl[ss][0]);
                pack_hl(p[2*ss][2],   p[2*ss][3],   ph[ss][1], pl[ss][1]);
                pack_hl(p[2*ss+1][0], p[2*ss+1][1], ph[ss][2], pl[ss][2]);
                pack_hl(p[2*ss+1][2], p[2*ss+1][3], ph[ss][3], pl[ss][3]);
            }
        }
        __syncthreads();
        {
            int kk = tid >> 2, d0 = (tid & 3) * 16;
            const float* vp = qkv + base + (size_t)(j0 + kk) * C3 + 2 * CDIM + h * HD + d0;
            #pragma unroll
            for (int i = 0; i < 4; i++) {
                float4 v = ((const float4*)vp)[i];
                int d = d0 + i * 4;
                uint16_t hh, ll;
                bsplit(v.x, hh, ll);
                sH[(d + 0) * ST + kk] = __ushort_as_bfloat16(hh);
                sL[(d + 0) * ST + kk] = __ushort_as_bfloat16(ll);
                bsplit(v.y, hh, ll);
                sH[(d + 1) * ST + kk] = __ushort_as_bfloat16(hh);
                sL[(d + 1) * ST + kk] = __ushort_as_bfloat16(ll);
                bsplit(v.z, hh, ll);
                sH[(d + 2) * ST + kk] = __ushort_as_bfloat16(hh);
                sL[(d + 2) * ST + kk] = __ushort_as_bfloat16(ll);
                bsplit(v.w, hh, ll);
                sH[(d + 3) * ST + kk] = __ushort_as_bfloat16(hh);
                sL[(d + 3) * ST + kk] = __ushort_as_bfloat16(ll);
            }
        }
        __syncthreads();
        if (act) {
            #pragma unroll
            for (int ni = 0; ni < 8; ni++)
                #pragma unroll
                for (int ss = 0; ss < 4; ss++) {
                    int ib = (8 * ni + g) * ST + 16 * ss + 2 * tg;
                    uint32_t bh[2] = { *(const uint32_t*)&sH[ib], *(const uint32_t*)&sH[ib + 8] };
                    uint32_t bl[2] = { *(const uint32_t*)&sL[ib], *(const uint32_t*)&sL[ib + 8] };
                    mma_bf16(o[ni], ph[ss], bh);
                    mma_bf16(o[ni], ph[ss], bl);
                    mma_bf16(o[ni], pl[ss], bh);
                }
        }
    }

    l0 += __shfl_xor_sync(0xffffffffu, l0, 1);
    l0 += __shfl_xor_sync(0xffffffffu, l0, 2);
    l1 += __shfl_xor_sync(0xffffffffu, l1, 1);
    l1 += __shfl_xor_sync(0xffffffffu, l1, 2);
    float i0 = 1.f / l0, i1 = 1.f / l1;
    size_t ro0 = (size_t)(b * TSEQ + qw0 + g) * CDIM + h * HD;
    size_t ro1 = ro0 + 8 * CDIM;
    #pragma unroll
    for (int ni = 0; ni < 8; ni++) {
        uint32_t hA, lA;
        pack_hl(o[ni][0] * i0, o[ni][1] * i0, hA, lA);
        *(uint32_t*)&attH[ro0 + 8 * ni + 2 * tg] = hA;
        *(uint32_t*)&attL[ro0 + 8 * ni + 2 * tg] = lA;
        pack_hl(o[ni][2] * i1, o[ni][3] * i1, hA, lA);
        *(uint32_t*)&attH[ro1 + 8 * ni + 2 * tg] = hA;
        *(uint32_t*)&attL[ro1 + 8 * ni + 2 * tg] = lA;
    }
}

// ---------------- per-row cross-entropy ----------------
__global__ __launch_bounds__(256) void loss_row_kernel(const float* __restrict__ logits,
                                                       const int* __restrict__ targets) {
    int row = blockIdx.x;
    const float* x = logits + (size_t)row * VOCAB;
    __shared__ float sh[8];
    float mx = -1e30f;
    for (int c = threadIdx.x; c < VOCAB; c += 256) mx = fmaxf(mx, x[c]);
    #pragma unroll
    for (int o = 16; o; o >>= 1) mx = fmaxf(mx, __shfl_down_sync(0xffffffffu, mx, o));
    if ((threadIdx.x & 31) == 0) sh[threadIdx.x >> 5] = mx;
    __syncthreads();
    if (threadIdx.x == 0) {
        float a = sh[0];
        #pragma unroll
        for (int i = 1; i < 8; i++) a = fmaxf(a, sh[i]);
        sh[0] = a;
    }
    __syncthreads();
    mx = sh[0];
    __syncthreads();
    float s = 0.f;
    for (int c = threadIdx.x; c < VOCAB; c += 256) s += expf(x[c] - mx);
    #pragma unroll
    for (int o = 16; o; o >>= 1) s += __shfl_down_sync(0xffffffffu, s, o);
    if ((threadIdx.x & 31) == 0) sh[threadIdx.x >> 5] = s;
    __syncthreads();
    if (threadIdx.x == 0) {
        float a = 0.f;
        #pragma unroll
        for (int i = 0; i < 8; i++) a += sh[i];
        g_rowloss[row] = (mx + logf(a)) - x[targets[row]];
    }
}

__global__ __launch_bounds__(1024) void loss_reduce_kernel(float* __restrict__ out) {
    __shared__ float sh[1024];
    int t = threadIdx.x;
    float s = 0.f;
    for (int i = t; i < NTOK; i += 1024) s += g_rowloss[i];
    sh[t] = s;
    __syncthreads();
    for (int o = 512; o; o >>= 1) {
        if (t < o) sh[t] += sh[t + o];
        __syncthreads();
    }
    if (t == 0) out[0] = sh[0] * (1.f / NTOK);
}

// ---------------- launch ----------------
extern "C" void kernel_launch(void* const* d_in, const int* in_sizes, int n_in,
                              void* d_out, int out_size) {
    const int*   x       = (const int*)  d_in[0];
    const int*   targets = (const int*)  d_in[1];
    const float* wte     = (const float*)d_in[2];
    const float* wpe     = (const float*)d_in[3];
    const float* ln1_w   = (const float*)d_in[4];
    const float* ln1_b   = (const float*)d_in[5];
    const float* attn_w  = (const float*)d_in[6];
    const float* attn_b  = (const float*)d_in[7];
    const float* proj_w  = (const float*)d_in[8];
    const float* proj_b  = (const float*)d_in[9];
    const float* ln2_w   = (const float*)d_in[10];
    const float* ln2_b   = (const float*)d_in[11];
    const float* fc_w    = (const float*)d_in[12];
    const float* fc_b    = (const float*)d_in[13];
    const float* fc2_w   = (const float*)d_in[14];
    const float* fc2_b   = (const float*)d_in[15];
    const float* lnf_w   = (const float*)d_in[16];
    const float* lnf_b   = (const float*)d_in[17];

    float* logits = (float*)d_out;
    float* lossp  = (float*)d_out + (out_size - 1);

    float *p_h, *p_qkv;
    __nv_bfloat16 *p_hnH, *p_hnL, *p_attH, *p_attL, *p_fcH, *p_fcL;
    __nv_bfloat16 *p_waH, *p_waL, *p_wpH, *p_wpL, *p_wfH, *p_wfL, *p_wf2H, *p_wf2L, *p_wteH, *p_wteL;
    cudaGetSymbolAddress((void**)&p_h,    g_h);
    cudaGetSymbolAddress((void**)&p_qkv,  g_qkv);
    cudaGetSymbolAddress((void**)&p_hnH,  g_hnH);
    cudaGetSymbolAddress((void**)&p_hnL,  g_hnL);
    cudaGetSymbolAddress((void**)&p_attH, g_attH);
    cudaGetSymbolAddress((void**)&p_attL, g_attL);
    cudaGetSymbolAddress((void**)&p_fcH,  g_fcH);
    cudaGetSymbolAddress((void**)&p_fcL,  g_fcL);
    cudaGetSymbolAddress((void**)&p_waH,  g_waH);
    cudaGetSymbolAddress((void**)&p_waL,  g_waL);
    cudaGetSymbolAddress((void**)&p_wpH,  g_wpH);
    cudaGetSymbolAddress((void**)&p_wpL,  g_wpL);
    cudaGetSymbolAddress((void**)&p_wfH,  g_wfH);
    cudaGetSymbolAddress((void**)&p_wfL,  g_wfL);
    cudaGetSymbolAddress((void**)&p_wf2H, g_wf2H);
    cudaGetSymbolAddress((void**)&p_wf2L, g_wf2L);
    cudaGetSymbolAddress((void**)&p_wteH, g_wteH);
    cudaGetSymbolAddress((void**)&p_wteL, g_wteL);

    cudaFuncSetAttribute(pgemm<0>, cudaFuncAttributeMaxDynamicSharedMemorySize, PG_SMEM);
    cudaFuncSetAttribute(pgemm<1>, cudaFuncAttributeMaxDynamicSharedMemorySize, PG_SMEM);
    cudaFuncSetAttribute(pgemm<2>, cudaFuncAttributeMaxDynamicSharedMemorySize, PG_SMEM);
    cudaFuncSetAttribute(pgemm<3>, cudaFuncAttributeMaxDynamicSharedMemorySize, PG_SMEM);

    // ---- weight pre-split (once per launch) ----
    wsplit_t<<<dim3(C3 / 32, CDIM / 32, NLAYER), 256>>>(attn_w, p_waH, p_waL, CDIM, C3);
    wsplit_t<<<dim3(CDIM / 32, CDIM / 32, NLAYER), 256>>>(proj_w, p_wpH, p_wpL, CDIM, CDIM);
    wsplit_t<<<dim3(C4 / 32, CDIM / 32, NLAYER), 256>>>(fc_w, p_wfH, p_wfL, CDIM, C4);
    wsplit_t<<<dim3(CDIM / 32, C4 / 32, NLAYER), 256>>>(fc2_w, p_wf2H, p_wf2L, C4, CDIM);
    wsplit<<<(WTEN / 2 + 255) / 256, 256>>>(wte, p_wteH, p_wteL, WTEN);

    embed_kernel<<<NTOK, 256>>>(x, wte, wpe);

    for (int l = 0; l < NLAYER; l++) {
        ln_kernel<<<NTOK, 256>>>(p_h, ln1_w + (size_t)l * CDIM, ln1_b + (size_t)l * CDIM, p_hnH, p_hnL);
        pgemm<0><<<dim3(C3 / 128, NTOK / 128), 256, PG_SMEM>>>(
            p_hnH, p_hnL, p_waH + (size_t)l * C3 * CDIM, p_waL + (size_t)l * C3 * CDIM,
            attn_b + (size_t)l * C3, nullptr, p_qkv, nullptr, nullptr, NTOK, C3, CDIM);
        attn_mma<<<dim3(TSEQ / 128, NHEAD, BATCH), 256>>>(p_qkv, p_attH, p_attL);
        pgemm<2><<<dim3(CDIM / 128, NTOK / 128), 256, PG_SMEM>>>(
            p_attH, p_attL, p_wpH + (size_t)l * CDIM * CDIM, p_wpL + (size_t)l * CDIM * CDIM,
            proj_b + (size_t)l * CDIM, p_h, p_h, nullptr, nullptr, NTOK, CDIM, CDIM);
        ln_kernel<<<NTOK, 256>>>(p_h, ln2_w + (size_t)l * CDIM, ln2_b + (size_t)l * CDIM, p_hnH, p_hnL);
        pgemm<1><<<dim3(C4 / 128, NTOK / 128), 256, PG_SMEM>>>(
            p_hnH, p_hnL, p_wfH + (size_t)l * C4 * CDIM, p_wfL + (size_t)l * C4 * CDIM,
            fc_b + (size_t)l * C4, nullptr, nullptr, p_fcH, p_fcL, NTOK, C4, CDIM);
        pgemm<2><<<dim3(CDIM / 128, NTOK / 128), 256, PG_SMEM>>>(
            p_fcH, p_fcL, p_wf2H + (size_t)l * CDIM * C4, p_wf2L + (size_t)l * CDIM * C4,
            fc2_b + (size_t)l * CDIM, p_h, p_h, nullptr, nullptr, NTOK, CDIM, C4);
    }

    ln_kernel<<<NTOK, 256>>>(p_h, lnf_w, lnf_b, p_hnH, p_hnL);
    pgemm<3><<<dim3(VOCAB / 128, NTOK / 128), 256, PG_SMEM>>>(
        p_hnH, p_hnL, p_wteH, p_wteL, nullptr, nullptr, logits, nullptr, nullptr,
        NTOK, VOCAB, CDIM);

    loss_row_kernel<<<NTOK, 256>>>(logits, targets);
    loss_reduce_kernel<<<1, 1024>>>(lossp);
}

// round 14
// speedup vs baseline: 1.3079x; 1.1501x over previous
#include <cuda_runtime.h>
#include <cuda_bf16.h>
#include <math.h>
#include <stdint.h>

// ---------------- problem constants ----------------
#define BATCH 4
#define TSEQ  1024
#define CDIM  768
#define NHEAD 12
#define HD    64
#define VOCAB 50304
#define NLAYER 12
#define NTOK  (BATCH*TSEQ)     // 4096
#define C3    (3*CDIM)         // 2304
#define C4    (4*CDIM)         // 3072

#define WATTN (NLAYER*C3*CDIM)
#define WPROJ (NLAYER*CDIM*CDIM)
#define WFC   (NLAYER*C4*CDIM)
#define WFC2  (NLAYER*CDIM*C4)
#define WTEN  (VOCAB*CDIM)

// ---------------- scratch (static device globals; no allocation allowed) ----
__device__ float g_h [NTOK * CDIM];
__device__ float g_q [NTOK * CDIM];
__device__ float g_rowloss[NTOK];
__device__ __nv_bfloat16 g_kH[NTOK * CDIM], g_kL[NTOK * CDIM];   // [b*H+h][t][d]
__device__ __nv_bfloat16 g_vH[NTOK * CDIM], g_vL[NTOK * CDIM];   // [b*H+h][d][t]
__device__ __nv_bfloat16 g_hnH[NTOK * CDIM], g_hnL[NTOK * CDIM];
__device__ __nv_bfloat16 g_attH[NTOK * CDIM], g_attL[NTOK * CDIM];
__device__ __nv_bfloat16 g_fcH[NTOK * C4],   g_fcL[NTOK * C4];
__device__ __nv_bfloat16 g_waH[WATTN],  g_waL[WATTN];
__device__ __nv_bfloat16 g_wpH[WPROJ],  g_wpL[WPROJ];
__device__ __nv_bfloat16 g_wfH[WFC],    g_wfL[WFC];
__device__ __nv_bfloat16 g_wf2H[WFC2],  g_wf2L[WFC2];
__device__ __nv_bfloat16 g_wteH[WTEN],  g_wteL[WTEN];

// ---------------- bf16 split helpers ----------------
__device__ __forceinline__ void bsplit(float x, uint16_t& h, uint16_t& l) {
    __nv_bfloat16 bh = __float2bfloat16_rn(x);
    h = __bfloat16_as_ushort(bh);
    float r = x - __bfloat162float(bh);
    l = __bfloat16_as_ushort(__float2bfloat16_rn(r));
}
__device__ __forceinline__ void pack_hl(float vx, float vy, uint32_t& h, uint32_t& l) {
    uint16_t hx, lx, hy, ly;
    bsplit(vx, hx, lx); bsplit(vy, hy, ly);
    h = (uint32_t)hx | ((uint32_t)hy << 16);
    l = (uint32_t)lx | ((uint32_t)ly << 16);
}
__device__ __forceinline__ void mma_bf16(float* c, const uint32_t* a, const uint32_t* b) {
    asm volatile(
        "mma.sync.aligned.m16n8k16.row.col.f32.bf16.bf16.f32 "
        "{%0,%1,%2,%3},{%4,%5,%6,%7},{%8,%9},{%0,%1,%2,%3};"
        : "+f"(c[0]), "+f"(c[1]), "+f"(c[2]), "+f"(c[3])
        : "r"(a[0]), "r"(a[1]), "r"(a[2]), "r"(a[3]), "r"(b[0]), "r"(b[1]));
}
__device__ __forceinline__ uint32_t smem_u32(const void* p) {
    uint32_t a;
    asm("{ .reg .u64 t; cvta.to.shared.u64 t, %1; cvt.u32.u64 %0, t; }" : "=r"(a) : "l"(p));
    return a;
}
__device__ __forceinline__ void ldsm4(uint32_t& r0, uint32_t& r1, uint32_t& r2, uint32_t& r3,
                                      uint32_t addr) {
    asm volatile("ldmatrix.sync.aligned.m8n8.x4.shared.b16 {%0,%1,%2,%3}, [%4];"
                 : "=r"(r0), "=r"(r1), "=r"(r2), "=r"(r3) : "r"(addr));
}
// swizzled offset for (logical row r, 16B chunk c4) in a 128x64B tile:
// pack 2 rows per 128B phys row; chunk(3b) ^= physrow(low 3b)
__device__ __forceinline__ uint32_t swz(uint32_t r, uint32_t c4) {
    uint32_t pr = r >> 1;
    uint32_t ch = ((r & 1) << 2) | c4;
    return (pr << 7) + (((ch ^ (pr & 7))) << 4);
}

// ---------------- weight conversion kernels (once per launch) ----------------
__global__ __launch_bounds__(256) void wsplit_t(const float* __restrict__ in,
                                                __nv_bfloat16* __restrict__ oh,
                                                __nv_bfloat16* __restrict__ ol,
                                                int K, int N) {
    __shared__ float t[32][33];
    size_t loff = (size_t)blockIdx.z * K * N;
    const float* src = in + loff;
    int nb = blockIdx.x * 32, kb = blockIdx.y * 32;
    int tx = threadIdx.x & 31, ty = threadIdx.x >> 5;
    #pragma unroll
    for (int i = 0; i < 32; i += 8)
        t[ty + i][tx] = src[(size_t)(kb + ty + i) * N + nb + tx];
    __syncthreads();
    #pragma unroll
    for (int i = 0; i < 32; i += 8) {
        float v = t[tx][ty + i];
        uint16_t h, l; bsplit(v, h, l);
        size_t o = loff + (size_t)(nb + ty + i) * K + kb + tx;
        oh[o] = __ushort_as_bfloat16(h);
        ol[o] = __ushort_as_bfloat16(l);
    }
}
__global__ __launch_bounds__(256) void wsplit(const float* __restrict__ in,
                                              __nv_bfloat16* __restrict__ oh,
                                              __nv_bfloat16* __restrict__ ol, int n) {
    int i = (blockIdx.x * 256 + threadIdx.x) * 2;
    if (i < n) {
        uint32_t h, l;
        pack_hl(in[i], in[i + 1], h, l);
        *(uint32_t*)&oh[i] = h;
        *(uint32_t*)&ol[i] = l;
    }
}

// ---------------- embedding ----------------
__global__ __launch_bounds__(256) void embed_kernel(const int* __restrict__ x,
                                                    const float* __restrict__ wte,
                                                    const float* __restrict__ wpe) {
    int m = blockIdx.x;
    int t = m % TSEQ;
    int idx = x[m];
    const float* we = wte + (size_t)idx * CDIM;
    const float* wp = wpe + (size_t)t * CDIM;
    float* o = g_h + (size_t)m * CDIM;
    for (int c = threadIdx.x; c < CDIM; c += 256)
        o[c] = we[c] + wp[c];
}

// ---------------- layernorm: fp32 in -> bf16 hi/lo pair out ----------------
__global__ __launch_bounds__(256) void ln_kernel(const float* __restrict__ in,
                                                 const float* __restrict__ w,
                                                 const float* __restrict__ bb,
                                                 __nv_bfloat16* __restrict__ oh,
                                                 __nv_bfloat16* __restrict__ ol) {
    int row = blockIdx.x;
    const float* x = in + (size_t)row * CDIM;
    float s = 0.f, s2 = 0.f;
    for (int c = threadIdx.x; c < CDIM; c += 256) {
        float v = x[c]; s += v; s2 += v * v;
    }
    __shared__ float ss[8], ss2[8];
    #pragma unroll
    for (int o = 16; o; o >>= 1) {
        s  += __shfl_down_sync(0xffffffffu, s,  o);
        s2 += __shfl_down_sync(0xffffffffu, s2, o);
    }
    if ((threadIdx.x & 31) == 0) { ss[threadIdx.x >> 5] = s; ss2[threadIdx.x >> 5] = s2; }
    __syncthreads();
    if (threadIdx.x == 0) {
        float a = 0.f, a2 = 0.f;
        #pragma unroll
        for (int i = 0; i < 8; i++) { a += ss[i]; a2 += ss2[i]; }
        ss[0] = a; ss2[0] = a2;
    }
    __syncthreads();
    float mean = ss[0] * (1.f / CDIM);
    float var  = ss2[0] * (1.f / CDIM) - mean * mean;
    float rstd = rsqrtf(var + 1e-5f);
    __nv_bfloat16* oH = oh + (size_t)row * CDIM;
    __nv_bfloat16* oL = ol + (size_t)row * CDIM;
    for (int c = threadIdx.x * 2; c < CDIM; c += 512) {
        float v0 = (x[c]     - mean) * rstd * w[c]     + bb[c];
        float v1 = (x[c + 1] - mean) * rstd * w[c + 1] + bb[c + 1];
        uint32_t hh, ll;
        pack_hl(v0, v1, hh, ll);
        *(uint32_t*)&oH[c] = hh;
        *(uint32_t*)&oL[c] = ll;
    }
}

// ---------------- pipelined 3xBF16 GEMM (swizzled smem, cp.async, ldmatrix) --
// EPI: 0 = +bias -> fp32; 1 = +bias,gelu -> bf16 pair; 2 = +bias+residual -> fp32;
//      3 = plain -> fp32; 4 = qkv split (Q fp32, K hi/lo, V transposed hi/lo)
#define PG_ARR   8192
#define PG_STG   (4 * PG_ARR)
#define PG_SMEM  (2 * PG_STG)

template<int EPI>
__global__ __launch_bounds__(256) void pgemm(const __nv_bfloat16* __restrict__ AH,
                                             const __nv_bfloat16* __restrict__ AL,
                                             const __nv_bfloat16* __restrict__ BH,
                                             const __nv_bfloat16* __restrict__ BL,
                                             const float* __restrict__ bias,
                                             const float* __restrict__ add,
                                             float* __restrict__ Cf,
                                             __nv_bfloat16* __restrict__ CH,
                                             __nv_bfloat16* __restrict__ CL,
                                             __nv_bfloat16* __restrict__ VH,
                                             __nv_bfloat16* __restrict__ VL,
                                             int M, int N, int K) {
    extern __shared__ char smem[];
    uint32_t sb = smem_u32(smem);

    int tid  = threadIdx.x;
    int wid  = tid >> 5, lane = tid & 31;
    int wr   = wid >> 2, wc = wid & 3;
    int g    = lane >> 2, tg = lane & 3;
    int row0 = blockIdx.y * 128, col0 = blockIdx.x * 128;

    const uint32_t lrow = lane & 15;
    const uint32_t lc4  = (lane >> 4);   // 0 or 1 -> +8 cols = +1 chunk

    const __nv_bfloat16* srcs[4] = { AH, AL, BH, BL };

    auto issue = [&](int k0, int s) {
        uint32_t sbase = sb + s * PG_STG;
        #pragma unroll
        for (int arr = 0; arr < 4; arr++) {
            const __nv_bfloat16* gs = srcs[arr];
            int rbase = (arr < 2) ? row0 : col0;
            #pragma unroll
            for (int i = 0; i < 2; i++) {
                int ch = tid + i * 256;
                int r = ch >> 2, cb = ch & 3;
                const char* src = (const char*)(gs + (size_t)(rbase + r) * K + k0) + cb * 16;
                uint32_t dst = sbase + arr * PG_ARR + swz(r, cb);
                asm volatile("cp.async.cg.shared.global [%0], [%1], 16;"
                             :: "r"(dst), "l"(src) : "memory");
            }
        }
        asm volatile("cp.async.commit_group;" ::: "memory");
    };

    float c[4][4][4];
    #pragma unroll
    for (int mi = 0; mi < 4; mi++)
        #pragma unroll
        for (int ni = 0; ni < 4; ni++)
            #pragma unroll
            for (int r = 0; r < 4; r++) c[mi][ni][r] = 0.f;

    int nk = K / 32;
    issue(0, 0);

    for (int ki = 0; ki < nk; ki++) {
        if (ki + 1 < nk) {
            issue((ki + 1) * 32, (ki + 1) & 1);
            asm volatile("cp.async.wait_group 1;" ::: "memory");
        } else {
            asm volatile("cp.async.wait_group 0;" ::: "memory");
        }
        __syncthreads();

        uint32_t sAh = sb + (ki & 1) * PG_STG;
        uint32_t sAl = sAh + PG_ARR;
        uint32_t sBh = sAh + 2 * PG_ARR;
        uint32_t sBl = sAh + 3 * PG_ARR;

        #pragma unroll
        for (int ks = 0; ks < 2; ks++) {
            uint32_t c4 = ks * 2 + lc4;   // 16B chunk index: (ks*16 + lc4*8)/8
            uint32_t ah[4][4], al[4][4], bh[4][2], bl[4][2];
            #pragma unroll
            for (int mi = 0; mi < 4; mi++) {
                uint32_t off = swz(wr * 64 + mi * 16 + lrow, c4);
                ldsm4(ah[mi][0], ah[mi][1], ah[mi][2], ah[mi][3], sAh + off);
                ldsm4(al[mi][0], al[mi][1], al[mi][2], al[mi][3], sAl + off);
            }
            #pragma unroll
            for (int q = 0; q < 2; q++) {
                uint32_t off = swz(wc * 32 + q * 16 + lrow, c4);
                uint32_t r0, r1, r2, r3;
                ldsm4(r0, r1, r2, r3, sBh + off);
                bh[2*q][0] = r0; bh[2*q+1][0] = r1; bh[2*q][1] = r2; bh[2*q+1][1] = r3;
                ldsm4(r0, r1, r2, r3, sBl + off);
                bl[2*q][0] = r0; bl[2*q+1][0] = r1; bl[2*q][1] = r2; bl[2*q+1][1] = r3;
            }
            #pragma unroll
            for (int mi = 0; mi < 4; mi++)
                #pragma unroll
                for (int ni = 0; ni < 4; ni++) {
                    mma_bf16(c[mi][ni], ah[mi], bh[ni]);
                    mma_bf16(c[mi][ni], ah[mi], bl[ni]);
                    mma_bf16(c[mi][ni], al[mi], bh[ni]);
                }
        }
        __syncthreads();
    }

    // ---- epilogue ----
    #pragma unroll
    for (int mi = 0; mi < 4; mi++)
        #pragma unroll
        for (int ni = 0; ni < 4; ni++) {
            int cc = col0 + wc * 32 + ni * 8 + tg * 2;
            #pragma unroll
            for (int hh = 0; hh < 2; hh++) {
                int r = row0 + wr * 64 + mi * 16 + g + hh * 8;
                float v0 = c[mi][ni][hh * 2 + 0];
                float v1 = c[mi][ni][hh * 2 + 1];
                if (EPI != 3) { v0 += bias[cc]; v1 += bias[cc + 1]; }
                if (EPI == 2) {
                    const float2 a2 = *(const float2*)(add + (size_t)r * N + cc);
                    v0 += a2.x; v1 += a2.y;
                }
                if (EPI == 1) {
                    float t0 = 0.7978845608028654f * (v0 + 0.044715f * v0 * v0 * v0);
                    v0 = 0.5f * v0 * (1.0f + tanhf(t0));
                    float t1 = 0.7978845608028654f * (v1 + 0.044715f * v1 * v1 * v1);
                    v1 = 0.5f * v1 * (1.0f + tanhf(t1));
                    uint32_t ph_, pl_;
                    pack_hl(v0, v1, ph_, pl_);
                    *(uint32_t*)&CH[(size_t)r * N + cc] = ph_;
                    *(uint32_t*)&CL[(size_t)r * N + cc] = pl_;
                } else if (EPI == 4) {
                    int b = r >> 10, t = r & 1023;
                    int sec = cc / CDIM, chn = cc % CDIM;
                    int h = chn >> 6, d = chn & 63;
                    size_t bh_ = (size_t)(b * NHEAD + h);
                    if (sec == 0) {
                        float2 o2; o2.x = v0; o2.y = v1;
                        *(float2*)(Cf + (size_t)r * CDIM + chn) = o2;
                    } else if (sec == 1) {
                        uint32_t hh_, ll_;
                        pack_hl(v0, v1, hh_, ll_);
                        size_t o = (bh_ * TSEQ + t) * HD + d;
                        *(uint32_t*)&CH[o] = hh_;
                        *(uint32_t*)&CL[o] = ll_;
                    } else {
                        uint16_t h0, l0, h1, l1;
                        bsplit(v0, h0, l0); bsplit(v1, h1, l1);
                        size_t o = (bh_ * HD + d) * TSEQ + t;
                        VH[o] = __ushort_as_bfloat16(h0);
                        VL[o] = __ushort_as_bfloat16(l0);
                        VH[o + TSEQ] = __ushort_as_bfloat16(h1);
                        VL[o + TSEQ] = __ushort_as_bfloat16(l1);
                    }
                } else {
                    float2 o2; o2.x = v0; o2.y = v1;
                    *(float2*)(Cf + (size_t)r * N + cc) = o2;
                }
            }
        }
}

// ---------------- MMA flash attention (3xBF16, causal, NO score scaling) ----
// K/V pre-split in global; staging = pure copies.
__global__ __launch_bounds__(256) void attn_mma(const float* __restrict__ Qf,
                                                const __nv_bfloat16* __restrict__ KH,
                                                const __nv_bfloat16* __restrict__ KL,
                                                const __nv_bfloat16* __restrict__ VH,
                                                const __nv_bfloat16* __restrict__ VL,
                                                __nv_bfloat16* __restrict__ attH,
                                                __nv_bfloat16* __restrict__ attL) {
    constexpr int ST = 72;
    int b = blockIdx.z, h = blockIdx.y;
    int q0 = blockIdx.x * 128;
    int tid = threadIdx.x, wid = tid >> 5, lane = tid & 31;
    int g = lane >> 2, tg = lane & 3;
    int qw0 = q0 + wid * 16;
    const size_t bh_ = (size_t)(b * NHEAD + h);

    __shared__ __nv_bfloat16 sH[64 * ST], sL[64 * ST];

    uint32_t qh[4][4], ql[4][4];
    {
        const float* q_r0 = Qf + (size_t)(b * TSEQ + qw0 + g) * CDIM + h * HD;
        const float* q_r1 = q_r0 + 8 * CDIM;
        #pragma unroll
        for (int s = 0; s < 4; s++) {
            float2 v0 = *(const float2*)(q_r0 + 16 * s + 2 * tg);
            float2 v1 = *(const float2*)(q_r1 + 16 * s + 2 * tg);
            float2 v2 = *(const float2*)(q_r0 + 16 * s + 2 * tg + 8);
            float2 v3 = *(const float2*)(q_r1 + 16 * s + 2 * tg + 8);
            pack_hl(v0.x, v0.y, qh[s][0], ql[s][0]);
            pack_hl(v1.x, v1.y, qh[s][1], ql[s][1]);
            pack_hl(v2.x, v2.y, qh[s][2], ql[s][2]);
            pack_hl(v3.x, v3.y, qh[s][3], ql[s][3]);
        }
    }

    float o[8][4];
    #pragma unroll
    for (int ni = 0; ni < 8; ni++)
        #pragma unroll
        for (int r = 0; r < 4; r++) o[ni][r] = 0.f;
    float m0 = -1e30f, m1 = -1e30f, l0 = 0.f, l1 = 0.f;

    int kend = q0 + 128;
    for (int j0 = 0; j0 < kend; j0 += 64) {
        bool act = (j0 <= qw0 + 15);
        __syncthreads();
        {   // ---- stage K [key][d] (copy) ----
            int kk = tid >> 2, d0 = (tid & 3) * 16;
            size_t ko = (bh_ * TSEQ + j0 + kk) * HD + d0;
            const uint4* kh = (const uint4*)&KH[ko];
            const uint4* kl = (const uint4*)&KL[ko];
            uint4 a0 = kh[0], a1 = kh[1];
            uint4 b0 = kl[0], b1 = kl[1];
            *(uint4*)&sH[kk * ST + d0]     = a0;
            *(uint4*)&sH[kk * ST + d0 + 8] = a1;
            *(uint4*)&sL[kk * ST + d0]     = b0;
            *(uint4*)&sL[kk * ST + d0 + 8] = b1;
        }
        __syncthreads();

        uint32_t ph[4][4], pl[4][4];
        if (act) {
            float s[8][4];
            #pragma unroll
            for (int ni = 0; ni < 8; ni++) {
                s[ni][0] = s[ni][1] = s[ni][2] = s[ni][3] = 0.f;
                #pragma unroll
                for (int ss = 0; ss < 4; ss++) {
                    int ib = (8 * ni + g) * ST + 16 * ss + 2 * tg;
                    uint32_t bh2[2] = { *(const uint32_t*)&sH[ib], *(const uint32_t*)&sH[ib + 8] };
                    uint32_t bl2[2] = { *(const uint32_t*)&sL[ib], *(const uint32_t*)&sL[ib + 8] };
                    mma_bf16(s[ni], qh[ss], bh2);
                    mma_bf16(s[ni], qh[ss], bl2);
                    mma_bf16(s[ni], ql[ss], bh2);
                }
            }
            int r0 = qw0 + g, r1 = r0 + 8;
            float mx0 = -1e30f, mx1 = -1e30f;
            #pragma unroll
            for (int ni = 0; ni < 8; ni++) {
                int kc = j0 + 8 * ni + 2 * tg;
                if (kc     > r0) s[ni][0] = -1e30f;
                if (kc + 1 > r0) s[ni][1] = -1e30f;
                if (kc     > r1) s[ni][2] = -1e30f;
                if (kc + 1 > r1) s[ni][3] = -1e30f;
                mx0 = fmaxf(mx0, fmaxf(s[ni][0], s[ni][1]));
                mx1 = fmaxf(mx1, fmaxf(s[ni][2], s[ni][3]));
            }
            mx0 = fmaxf(mx0, __shfl_xor_sync(0xffffffffu, mx0, 1));
            mx0 = fmaxf(mx0, __shfl_xor_sync(0xffffffffu, mx0, 2));
            mx1 = fmaxf(mx1, __shfl_xor_sync(0xffffffffu, mx1, 1));
            mx1 = fmaxf(mx1, __shfl_xor_sync(0xffffffffu, mx1, 2));
            float nm0 = fmaxf(m0, mx0), nm1 = fmaxf(m1, mx1);
            float c0 = __expf(m0 - nm0), c1 = __expf(m1 - nm1);
            m0 = nm0; m1 = nm1;
            float p[8][4];
            float ls0 = 0.f, ls1 = 0.f;
            #pragma unroll
            for (int ni = 0; ni < 8; ni++) {
                p[ni][0] = __expf(s[ni][0] - nm0);
                p[ni][1] = __expf(s[ni][1] - nm0);
                p[ni][2] = __expf(s[ni][2] - nm1);
                p[ni][3] = __expf(s[ni][3] - nm1);
                ls0 += p[ni][0] + p[ni][1];
                ls1 += p[ni][2] + p[ni][3];
            }
            l0 = l0 * c0 + ls0;
            l1 = l1 * c1 + ls1;
            #pragma unroll
            for (int ni = 0; ni < 8; ni++) {
                o[ni][0] *= c0; o[ni][1] *= c0; o[ni][2] *= c1; o[ni][3] *= c1;
            }
            #pragma unroll
            for (int ss = 0; ss < 4; ss++) {
                pack_hl(p[2*ss][0],   p[2*ss][1],   ph[ss][0], pl[ss][0]);
                pack_hl(p[2*ss][2],   p[2*ss][3],   ph[ss][1], pl[ss][1]);
                pack_hl(p[2*ss+1][0], p[2*ss+1][1], ph[ss][2], pl[ss][2]);
                pack_hl(p[2*ss+1][2], p[2*ss+1][3], ph[ss][3], pl[ss][3]);
            }
        }
        __syncthreads();
        {   // ---- stage V [d][key] (copy, already transposed in global) ----
            int kk = tid >> 2, d0 = (tid & 3) * 16;
            size_t vo = (bh_ * HD + kk) * TSEQ + j0 + d0;
            const uint4* vh = (const uint4*)&VH[vo];
            const uint4* vl = (const uint4*)&VL[vo];
            uint4 a0 = vh[0], a1 = vh[1];
            uint4 b0 = vl[0], b1 = vl[1];
            *(uint4*)&sH[kk * ST + d0]     = a0;
            *(uint4*)&sH[kk * ST + d0 + 8] = a1;
            *(uint4*)&sL[kk * ST + d0]     = b0;
            *(uint4*)&sL[kk * ST + d0 + 8] = b1;
        }
        __syncthreads();
        if (act) {
            #pragma unroll
            for (int ni = 0; ni < 8; ni++)
                #pragma unroll
                for (int ss = 0; ss < 4; ss++) {
                    int ib = (8 * ni + g) * ST + 16 * ss + 2 * tg;
                    uint32_t bh2[2] = { *(const uint32_t*)&sH[ib], *(const uint32_t*)&sH[ib + 8] };
                    uint32_t bl2[2] = { *(const uint32_t*)&sL[ib], *(const uint32_t*)&sL[ib + 8] };
                    mma_bf16(o[ni], ph[ss], bh2);
                    mma_bf16(o[ni], ph[ss], bl2);
                    mma_bf16(o[ni], pl[ss], bh2);
                }
        }
    }

    l0 += __shfl_xor_sync(0xffffffffu, l0, 1);
    l0 += __shfl_xor_sync(0xffffffffu, l0, 2);
    l1 += __shfl_xor_sync(0xffffffffu, l1, 1);
    l1 += __shfl_xor_sync(0xffffffffu, l1, 2);
    float i0 = 1.f / l0, i1 = 1.f / l1;
    size_t ro0 = (size_t)(b * TSEQ + qw0 + g) * CDIM + h * HD;
    size_t ro1 = ro0 + 8 * CDIM;
    #pragma unroll
    for (int ni = 0; ni < 8; ni++) {
        uint32_t hA, lA;
        pack_hl(o[ni][0] * i0, o[ni][1] * i0, hA, lA);
        *(uint32_t*)&attH[ro0 + 8 * ni + 2 * tg] = hA;
        *(uint32_t*)&attL[ro0 + 8 * ni + 2 * tg] = lA;
        pack_hl(o[ni][2] * i1, o[ni][3] * i1, hA, lA);
        *(uint32_t*)&attH[ro1 + 8 * ni + 2 * tg] = hA;
        *(uint32_t*)&attL[ro1 + 8 * ni + 2 * tg] = lA;
    }
}

// ---------------- per-row cross-entropy ----------------
__global__ __launch_bounds__(256) void loss_row_kernel(const float* __restrict__ logits,
                                                       const int* __restrict__ targets) {
    int row = blockIdx.x;
    const float* x = logits + (size_t)row * VOCAB;
    __shared__ float sh[8];
    float mx = -1e30f;
    for (int c = threadIdx.x; c < VOCAB; c += 256) mx = fmaxf(mx, x[c]);
    #pragma unroll
    for (int o = 16; o; o >>= 1) mx = fmaxf(mx, __shfl_down_sync(0xffffffffu, mx, o));
    if ((threadIdx.x & 31) == 0) sh[threadIdx.x >> 5] = mx;
    __syncthreads();
    if (threadIdx.x == 0) {
        float a = sh[0];
        #pragma unroll
        for (int i = 1; i < 8; i++) a = fmaxf(a, sh[i]);
        sh[0] = a;
    }
    __syncthreads();
    mx = sh[0];
    __syncthreads();
    float s = 0.f;
    for (int c = threadIdx.x; c < VOCAB; c += 256) s += expf(x[c] - mx);
    #pragma unroll
    for (int o = 16; o; o >>= 1) s += __shfl_down_sync(0xffffffffu, s, o);
    if ((threadIdx.x & 31) == 0) sh[threadIdx.x >> 5] = s;
    __syncthreads();
    if (threadIdx.x == 0) {
        float a = 0.f;
        #pragma unroll
        for (int i = 0; i < 8; i++) a += sh[i];
        g_rowloss[row] = (mx + logf(a)) - x[targets[row]];
    }
}

__global__ __launch_bounds__(1024) void loss_reduce_kernel(float* __restrict__ out) {
    __shared__ float sh[1024];
    int t = threadIdx.x;
    float s = 0.f;
    for (int i = t; i < NTOK; i += 1024) s += g_rowloss[i];
    sh[t] = s;
    __syncthreads();
    for (int o = 512; o; o >>= 1) {
        if (t < o) sh[t] += sh[t + o];
        __syncthreads();
    }
    if (t == 0) out[0] = sh[0] * (1.f / NTOK);
}

// ---------------- launch ----------------
extern "C" void kernel_launch(void* const* d_in, const int* in_sizes, int n_in,
                              void* d_out, int out_size) {
    const int*   x       = (const int*)  d_in[0];
    const int*   targets = (const int*)  d_in[1];
    const float* wte     = (const float*)d_in[2];
    const float* wpe     = (const float*)d_in[3];
    const float* ln1_w   = (const float*)d_in[4];
    const float* ln1_b   = (const float*)d_in[5];
    const float* attn_w  = (const float*)d_in[6];
    const float* attn_b  = (const float*)d_in[7];
    const float* proj_w  = (const float*)d_in[8];
    const float* proj_b  = (const float*)d_in[9];
    const float* ln2_w   = (const float*)d_in[10];
    const float* ln2_b   = (const float*)d_in[11];
    const float* fc_w    = (const float*)d_in[12];
    const float* fc_b    = (const float*)d_in[13];
    const float* fc2_w   = (const float*)d_in[14];
    const float* fc2_b   = (const float*)d_in[15];
    const float* lnf_w   = (const float*)d_in[16];
    const float* lnf_b   = (const float*)d_in[17];

    float* logits = (float*)d_out;
    float* lossp  = (float*)d_out + (out_size - 1);

    float *p_h, *p_q;
    __nv_bfloat16 *p_kH, *p_kL, *p_vH, *p_vL;
    __nv_bfloat16 *p_hnH, *p_hnL, *p_attH, *p_attL, *p_fcH, *p_fcL;
    __nv_bfloat16 *p_waH, *p_waL, *p_wpH, *p_wpL, *p_wfH, *p_wfL, *p_wf2H, *p_wf2L, *p_wteH, *p_wteL;
    cudaGetSymbolAddress((void**)&p_h,    g_h);
    cudaGetSymbolAddress((void**)&p_q,    g_q);
    cudaGetSymbolAddress((void**)&p_kH,   g_kH);
    cudaGetSymbolAddress((void**)&p_kL,   g_kL);
    cudaGetSymbolAddress((void**)&p_vH,   g_vH);
    cudaGetSymbolAddress((void**)&p_vL,   g_vL);
    cudaGetSymbolAddress((void**)&p_hnH,  g_hnH);
    cudaGetSymbolAddress((void**)&p_hnL,  g_hnL);
    cudaGetSymbolAddress((void**)&p_attH, g_attH);
    cudaGetSymbolAddress((void**)&p_attL, g_attL);
    cudaGetSymbolAddress((void**)&p_fcH,  g_fcH);
    cudaGetSymbolAddress((void**)&p_fcL,  g_fcL);
    cudaGetSymbolAddress((void**)&p_waH,  g_waH);
    cudaGetSymbolAddress((void**)&p_waL,  g_waL);
    cudaGetSymbolAddress((void**)&p_wpH,  g_wpH);
    cudaGetSymbolAddress((void**)&p_wpL,  g_wpL);
    cudaGetSymbolAddress((void**)&p_wfH,  g_wfH);
    cudaGetSymbolAddress((void**)&p_wfL,  g_wfL);
    cudaGetSymbolAddress((void**)&p_wf2H, g_wf2H);
    cudaGetSymbolAddress((void**)&p_wf2L, g_wf2L);
    cudaGetSymbolAddress((void**)&p_wteH, g_wteH);
    cudaGetSymbolAddress((void**)&p_wteL, g_wteL);

    cudaFuncSetAttribute(pgemm<0>, cudaFuncAttributeMaxDynamicSharedMemorySize, PG_SMEM);
    cudaFuncSetAttribute(pgemm<1>, cudaFuncAttributeMaxDynamicSharedMemorySize, PG_SMEM);
    cudaFuncSetAttribute(pgemm<2>, cudaFuncAttributeMaxDynamicSharedMemorySize, PG_SMEM);
    cudaFuncSetAttribute(pgemm<3>, cudaFuncAttributeMaxDynamicSharedMemorySize, PG_SMEM);
    cudaFuncSetAttribute(pgemm<4>, cudaFuncAttributeMaxDynamicSharedMemorySize, PG_SMEM);

    // ---- weight pre-split (once per launch) ----
    wsplit_t<<<dim3(C3 / 32, CDIM / 32, NLAYER), 256>>>(attn_w, p_waH, p_waL, CDIM, C3);
    wsplit_t<<<dim3(CDIM / 32, CDIM / 32, NLAYER), 256>>>(proj_w, p_wpH, p_wpL, CDIM, CDIM);
    wsplit_t<<<dim3(C4 / 32, CDIM / 32, NLAYER), 256>>>(fc_w, p_wfH, p_wfL, CDIM, C4);
    wsplit_t<<<dim3(CDIM / 32, C4 / 32, NLAYER), 256>>>(fc2_w, p_wf2H, p_wf2L, C4, CDIM);
    wsplit<<<(WTEN / 2 + 255) / 256, 256>>>(wte, p_wteH, p_wteL, WTEN);

    embed_kernel<<<NTOK, 256>>>(x, wte, wpe);

    for (int l = 0; l < NLAYER; l++) {
        ln_kernel<<<NTOK, 256>>>(p_h, ln1_w + (size_t)l * CDIM, ln1_b + (size_t)l * CDIM, p_hnH, p_hnL);
        pgemm<4><<<dim3(C3 / 128, NTOK / 128), 256, PG_SMEM>>>(
            p_hnH, p_hnL, p_waH + (size_t)l * C3 * CDIM, p_waL + (size_t)l * C3 * CDIM,
            attn_b + (size_t)l * C3, nullptr, p_q, p_kH, p_kL, p_vH, p_vL, NTOK, C3, CDIM);
        attn_mma<<<dim3(TSEQ / 128, NHEAD, BATCH), 256>>>(p_q, p_kH, p_kL, p_vH, p_vL, p_attH, p_attL);
        pgemm<2><<<dim3(CDIM / 128, NTOK / 128), 256, PG_SMEM>>>(
            p_attH, p_attL, p_wpH + (size_t)l * CDIM * CDIM, p_wpL + (size_t)l * CDIM * CDIM,
            proj_b + (size_t)l * CDIM, p_h, p_h, nullptr, nullptr, nullptr, nullptr, NTOK, CDIM, CDIM);
        ln_kernel<<<NTOK, 256>>>(p_h, ln2_w + (size_t)l * CDIM, ln2_b + (size_t)l * CDIM, p_hnH, p_hnL);
        pgemm<1><<<dim3(C4 / 128, NTOK / 128), 256, PG_SMEM>>>(
            p_hnH, p_hnL, p_wfH + (size_t)l * C4 * CDIM, p_wfL + (size_t)l * C4 * CDIM,
            fc_b + (size_t)l * C4, nullptr, nullptr, p_fcH, p_fcL, nullptr, nullptr, NTOK, C4, CDIM);
        pgemm<2><<<dim3(CDIM / 128, NTOK / 128), 256, PG_SMEM>>>(
            p_fcH, p_fcL, p_wf2H + (size_t)l * CDIM * C4, p_wf2L + (size_t)l * CDIM * C4,
            fc2_b + (size_t)l * CDIM, p_h, p_h, nullptr, nullptr, nullptr, nullptr, NTOK, CDIM, C4);
    }

    ln_kernel<<<NTOK, 256>>>(p_h, lnf_w, lnf_b, p_hnH, p_hnL);
    pgemm<3><<<dim3(VOCAB / 128, NTOK / 128), 256, PG_SMEM>>>(
        p_hnH, p_hnL, p_wteH, p_wteL, nullptr, nullptr, logits, nullptr, nullptr, nullptr, nullptr,
        NTOK, VOCAB, CDIM);

    loss_row_kernel<<<NTOK, 256>>>(logits, targets);
    loss_reduce_kernel<<<1, 1024>>>(lossp);
}

// round 15
// speedup vs baseline: 1.7975x; 1.3743x over previous
#include <cuda_runtime.h>
#include <cuda_bf16.h>
#include <cuda_fp16.h>
#include <math.h>
#include <stdint.h>

// ---------------- problem constants ----------------
#define BATCH 4
#define TSEQ  1024
#define CDIM  768
#define NHEAD 12
#define HD    64
#define VOCAB 50304
#define NLAYER 12
#define NTOK  (BATCH*TSEQ)     // 4096
#define C3    (3*CDIM)         // 2304
#define C4    (4*CDIM)         // 3072

#define WATTN (NLAYER*C3*CDIM)
#define WPROJ (NLAYER*CDIM*CDIM)
#define WFC   (NLAYER*C4*CDIM)
#define WFC2  (NLAYER*CDIM*C4)
#define WTEN  (VOCAB*CDIM)

// ---------------- scratch (static device globals; no allocation allowed) ----
__device__ float g_h [NTOK * CDIM];
__device__ float g_q [NTOK * CDIM];
__device__ float g_rowloss[NTOK];
__device__ __nv_bfloat16 g_kH[NTOK * CDIM], g_kL[NTOK * CDIM];   // [b*H+h][t][d]
__device__ __nv_bfloat16 g_vH[NTOK * CDIM], g_vL[NTOK * CDIM];   // [b*H+h][d][t]
__device__ __half g_hn [NTOK * CDIM];
__device__ __half g_att[NTOK * CDIM];
__device__ __half g_fc [NTOK * C4];
__device__ __half g_waH[WATTN],  g_waL[WATTN];
__device__ __half g_wpH[WPROJ],  g_wpL[WPROJ];
__device__ __half g_wfH[WFC],    g_wfL[WFC];
__device__ __half g_wf2H[WFC2],  g_wf2L[WFC2];
__device__ __half g_wteH[WTEN],  g_wteL[WTEN];

// ---------------- split helpers ----------------
__device__ __forceinline__ void bsplit(float x, uint16_t& h, uint16_t& l) {
    __nv_bfloat16 bh = __float2bfloat16_rn(x);
    h = __bfloat16_as_ushort(bh);
    float r = x - __bfloat162float(bh);
    l = __bfloat16_as_ushort(__float2bfloat16_rn(r));
}
__device__ __forceinline__ void pack_hl(float vx, float vy, uint32_t& h, uint32_t& l) {
    uint16_t hx, lx, hy, ly;
    bsplit(vx, hx, lx); bsplit(vy, hy, ly);
    h = (uint32_t)hx | ((uint32_t)hy << 16);
    l = (uint32_t)lx | ((uint32_t)ly << 16);
}
__device__ __forceinline__ void hsplit(float x, uint16_t& h, uint16_t& l) {
    __half hh = __float2half_rn(x);
    h = __half_as_ushort(hh);
    float r = x - __half2float(hh);
    l = __half_as_ushort(__float2half_rn(r));
}
__device__ __forceinline__ void pack_hl_h(float vx, float vy, uint32_t& h, uint32_t& l) {
    uint16_t hx, lx, hy, ly;
    hsplit(vx, hx, lx); hsplit(vy, hy, ly);
    h = (uint32_t)hx | ((uint32_t)hy << 16);
    l = (uint32_t)lx | ((uint32_t)ly << 16);
}
__device__ __forceinline__ uint32_t pack_h2(float x, float y) {
    __half2 t = __floats2half2_rn(x, y);
    return *(uint32_t*)&t;
}
__device__ __forceinline__ void mma_bf16(float* c, const uint32_t* a, const uint32_t* b) {
    asm volatile(
        "mma.sync.aligned.m16n8k16.row.col.f32.bf16.bf16.f32 "
        "{%0,%1,%2,%3},{%4,%5,%6,%7},{%8,%9},{%0,%1,%2,%3};"
        : "+f"(c[0]), "+f"(c[1]), "+f"(c[2]), "+f"(c[3])
        : "r"(a[0]), "r"(a[1]), "r"(a[2]), "r"(a[3]), "r"(b[0]), "r"(b[1]));
}
__device__ __forceinline__ void mma_f16(float* c, const uint32_t* a, const uint32_t* b) {
    asm volatile(
        "mma.sync.aligned.m16n8k16.row.col.f32.f16.f16.f32 "
        "{%0,%1,%2,%3},{%4,%5,%6,%7},{%8,%9},{%0,%1,%2,%3};"
        : "+f"(c[0]), "+f"(c[1]), "+f"(c[2]), "+f"(c[3])
        : "r"(a[0]), "r"(a[1]), "r"(a[2]), "r"(a[3]), "r"(b[0]), "r"(b[1]));
}
__device__ __forceinline__ uint32_t smem_u32(const void* p) {
    uint32_t a;
    asm("{ .reg .u64 t; cvta.to.shared.u64 t, %1; cvt.u32.u64 %0, t; }" : "=r"(a) : "l"(p));
    return a;
}
__device__ __forceinline__ void ldsm4(uint32_t& r0, uint32_t& r1, uint32_t& r2, uint32_t& r3,
                                      uint32_t addr) {
    asm volatile("ldmatrix.sync.aligned.m8n8.x4.shared.b16 {%0,%1,%2,%3}, [%4];"
                 : "=r"(r0), "=r"(r1), "=r"(r2), "=r"(r3) : "r"(addr));
}
// swizzled offset for (logical row r, 16B chunk c4) in a 128x64B tile
__device__ __forceinline__ uint32_t swz(uint32_t r, uint32_t c4) {
    uint32_t pr = r >> 1;
    uint32_t ch = ((r & 1) << 2) | c4;
    return (pr << 7) + (((ch ^ (pr & 7))) << 4);
}

// ---------------- weight conversion kernels (once per launch) ----------------
__global__ __launch_bounds__(256) void wsplit_t(const float* __restrict__ in,
                                                __half* __restrict__ oh,
                                                __half* __restrict__ ol,
                                                int K, int N) {
    __shared__ float t[32][33];
    size_t loff = (size_t)blockIdx.z * K * N;
    const float* src = in + loff;
    int nb = blockIdx.x * 32, kb = blockIdx.y * 32;
    int tx = threadIdx.x & 31, ty = threadIdx.x >> 5;
    #pragma unroll
    for (int i = 0; i < 32; i += 8)
        t[ty + i][tx] = src[(size_t)(kb + ty + i) * N + nb + tx];
    __syncthreads();
    #pragma unroll
    for (int i = 0; i < 32; i += 8) {
        float v = t[tx][ty + i];
        uint16_t h, l; hsplit(v, h, l);
        size_t o = loff + (size_t)(nb + ty + i) * K + kb + tx;
        oh[o] = __ushort_as_half(h);
        ol[o] = __ushort_as_half(l);
    }
}
__global__ __launch_bounds__(256) void wsplit(const float* __restrict__ in,
                                              __half* __restrict__ oh,
                                              __half* __restrict__ ol, int n) {
    int i = (blockIdx.x * 256 + threadIdx.x) * 2;
    if (i < n) {
        uint32_t h, l;
        pack_hl_h(in[i], in[i + 1], h, l);
        *(uint32_t*)&oh[i] = h;
        *(uint32_t*)&ol[i] = l;
    }
}

// ---------------- embedding ----------------
__global__ __launch_bounds__(256) void embed_kernel(const int* __restrict__ x,
                                                    const float* __restrict__ wte,
                                                    const float* __restrict__ wpe) {
    int m = blockIdx.x;
    int t = m % TSEQ;
    int idx = x[m];
    const float* we = wte + (size_t)idx * CDIM;
    const float* wp = wpe + (size_t)t * CDIM;
    float* o = g_h + (size_t)m * CDIM;
    for (int c = threadIdx.x; c < CDIM; c += 256)
        o[c] = we[c] + wp[c];
}

// ---------------- layernorm: fp32 in -> fp16 out ----------------
__global__ __launch_bounds__(256) void ln_kernel(const float* __restrict__ in,
                                                 const float* __restrict__ w,
                                                 const float* __restrict__ bb,
                                                 __half* __restrict__ oh) {
    int row = blockIdx.x;
    const float* x = in + (size_t)row * CDIM;
    float s = 0.f, s2 = 0.f;
    for (int c = threadIdx.x; c < CDIM; c += 256) {
        float v = x[c]; s += v; s2 += v * v;
    }
    __shared__ float ss[8], ss2[8];
    #pragma unroll
    for (int o = 16; o; o >>= 1) {
        s  += __shfl_down_sync(0xffffffffu, s,  o);
        s2 += __shfl_down_sync(0xffffffffu, s2, o);
    }
    if ((threadIdx.x & 31) == 0) { ss[threadIdx.x >> 5] = s; ss2[threadIdx.x >> 5] = s2; }
    __syncthreads();
    if (threadIdx.x == 0) {
        float a = 0.f, a2 = 0.f;
        #pragma unroll
        for (int i = 0; i < 8; i++) { a += ss[i]; a2 += ss2[i]; }
        ss[0] = a; ss2[0] = a2;
    }
    __syncthreads();
    float mean = ss[0] * (1.f / CDIM);
    float var  = ss2[0] * (1.f / CDIM) - mean * mean;
    float rstd = rsqrtf(var + 1e-5f);
    __half* oH = oh + (size_t)row * CDIM;
    for (int c = threadIdx.x * 2; c < CDIM; c += 512) {
        float v0 = (x[c]     - mean) * rstd * w[c]     + bb[c];
        float v1 = (x[c + 1] - mean) * rstd * w[c + 1] + bb[c + 1];
        *(uint32_t*)&oH[c] = pack_h2(v0, v1);
    }
}

// ---------------- 2xFP16 GEMM: A fp16 1-term, B fp16 hi/lo 2-term ----------
// C = epi(A @ B^T): A [M][K] fp16, B pair [N][K] fp16 (k-contiguous).
// EPI: 1 = +bias,gelu -> fp16; 2 = +bias+residual -> fp32; 3 = plain -> fp32;
//      4 = qkv split (Q fp32, K bf16 hi/lo, V transposed bf16 hi/lo)
#define PG_ARR   8192
#define PG_STG   (3 * PG_ARR)
#define PG_SMEM  (2 * PG_STG)

template<int EPI>
__global__ __launch_bounds__(256) void pgemm(const __half* __restrict__ A,
                                             const __half* __restrict__ BH,
                                             const __half* __restrict__ BL,
                                             const float* __restrict__ bias,
                                             const float* __restrict__ add,
                                             float* __restrict__ Cf,
                                             __half* __restrict__ Ch,
                                             __nv_bfloat16* __restrict__ KH,
                                             __nv_bfloat16* __restrict__ KL,
                                             __nv_bfloat16* __restrict__ VH,
                                             __nv_bfloat16* __restrict__ VL,
                                             int M, int N, int K) {
    extern __shared__ char smem[];
    uint32_t sb = smem_u32(smem);

    int tid  = threadIdx.x;
    int wid  = tid >> 5, lane = tid & 31;
    int wr   = wid >> 2, wc = wid & 3;
    int g    = lane >> 2, tg = lane & 3;
    int row0 = blockIdx.y * 128, col0 = blockIdx.x * 128;

    const uint32_t lrow = lane & 15;
    const uint32_t lc4  = (lane >> 4);

    const __half* srcs[3] = { A, BH, BL };

    auto issue = [&](int k0, int s) {
        uint32_t sbase = sb + s * PG_STG;
        #pragma unroll
        for (int arr = 0; arr < 3; arr++) {
            const __half* gs = srcs[arr];
            int rbase = (arr == 0) ? row0 : col0;
            #pragma unroll
            for (int i = 0; i < 2; i++) {
                int ch = tid + i * 256;
                int r = ch >> 2, cb = ch & 3;
                const char* src = (const char*)(gs + (size_t)(rbase + r) * K + k0) + cb * 16;
                uint32_t dst = sbase + arr * PG_ARR + swz(r, cb);
                asm volatile("cp.async.cg.shared.global [%0], [%1], 16;"
                             :: "r"(dst), "l"(src) : "memory");
            }
        }
        asm volatile("cp.async.commit_group;" ::: "memory");
    };

    float c[4][4][4];
    #pragma unroll
    for (int mi = 0; mi < 4; mi++)
        #pragma unroll
        for (int ni = 0; ni < 4; ni++)
            #pragma unroll
            for (int r = 0; r < 4; r++) c[mi][ni][r] = 0.f;

    int nk = K / 32;
    issue(0, 0);

    for (int ki = 0; ki < nk; ki++) {
        if (ki + 1 < nk) {
            issue((ki + 1) * 32, (ki + 1) & 1);
            asm volatile("cp.async.wait_group 1;" ::: "memory");
        } else {
            asm volatile("cp.async.wait_group 0;" ::: "memory");
        }
        __syncthreads();

        uint32_t sA  = sb + (ki & 1) * PG_STG;
        uint32_t sBh = sA + PG_ARR;
        uint32_t sBl = sA + 2 * PG_ARR;

        #pragma unroll
        for (int ks = 0; ks < 2; ks++) {
            uint32_t c4 = ks * 2 + lc4;
            uint32_t a[4][4], bh[4][2], bl[4][2];
            #pragma unroll
            for (int mi = 0; mi < 4; mi++) {
                uint32_t off = swz(wr * 64 + mi * 16 + lrow, c4);
                ldsm4(a[mi][0], a[mi][1], a[mi][2], a[mi][3], sA + off);
            }
            #pragma unroll
            for (int q = 0; q < 2; q++) {
                uint32_t off = swz(wc * 32 + q * 16 + lrow, c4);
                uint32_t r0, r1, r2, r3;
                ldsm4(r0, r1, r2, r3, sBh + off);
                bh[2*q][0] = r0; bh[2*q+1][0] = r1; bh[2*q][1] = r2; bh[2*q+1][1] = r3;
                ldsm4(r0, r1, r2, r3, sBl + off);
                bl[2*q][0] = r0; bl[2*q+1][0] = r1; bl[2*q][1] = r2; bl[2*q+1][1] = r3;
            }
            #pragma unroll
            for (int mi = 0; mi < 4; mi++)
                #pragma unroll
                for (int ni = 0; ni < 4; ni++) {
                    mma_f16(c[mi][ni], a[mi], bh[ni]);
                    mma_f16(c[mi][ni], a[mi], bl[ni]);
                }
        }
        __syncthreads();
    }

    // ---- epilogue ----
    #pragma unroll
    for (int mi = 0; mi < 4; mi++)
        #pragma unroll
        for (int ni = 0; ni < 4; ni++) {
            int cc = col0 + wc * 32 + ni * 8 + tg * 2;
            #pragma unroll
            for (int hh = 0; hh < 2; hh++) {
                int r = row0 + wr * 64 + mi * 16 + g + hh * 8;
                float v0 = c[mi][ni][hh * 2 + 0];
                float v1 = c[mi][ni][hh * 2 + 1];
                if (EPI != 3) { v0 += bias[cc]; v1 += bias[cc + 1]; }
                if (EPI == 2) {
                    const float2 a2 = *(const float2*)(add + (size_t)r * N + cc);
                    v0 += a2.x; v1 += a2.y;
                }
                if (EPI == 1) {
                    float t0 = 0.7978845608028654f * (v0 + 0.044715f * v0 * v0 * v0);
                    v0 = 0.5f * v0 * (1.0f + tanhf(t0));
                    float t1 = 0.7978845608028654f * (v1 + 0.044715f * v1 * v1 * v1);
                    v1 = 0.5f * v1 * (1.0f + tanhf(t1));
                    *(uint32_t*)&Ch[(size_t)r * N + cc] = pack_h2(v0, v1);
                } else if (EPI == 4) {
                    int b = r >> 10, t = r & 1023;
                    int sec = cc / CDIM, chn = cc % CDIM;
                    int h = chn >> 6, d = chn & 63;
                    size_t bh_ = (size_t)(b * NHEAD + h);
                    if (sec == 0) {
                        float2 o2; o2.x = v0; o2.y = v1;
                        *(float2*)(Cf + (size_t)r * CDIM + chn) = o2;
                    } else if (sec == 1) {
                        uint32_t hh_, ll_;
                        pack_hl(v0, v1, hh_, ll_);
                        size_t o = (bh_ * TSEQ + t) * HD + d;
                        *(uint32_t*)&KH[o] = hh_;
                        *(uint32_t*)&KL[o] = ll_;
                    } else {
                        uint16_t h0, l0, h1, l1;
                        bsplit(v0, h0, l0); bsplit(v1, h1, l1);
                        size_t o = (bh_ * HD + d) * TSEQ + t;
                        VH[o] = __ushort_as_bfloat16(h0);
                        VL[o] = __ushort_as_bfloat16(l0);
                        VH[o + TSEQ] = __ushort_as_bfloat16(h1);
                        VL[o + TSEQ] = __ushort_as_bfloat16(l1);
                    }
                } else {
                    float2 o2; o2.x = v0; o2.y = v1;
                    *(float2*)(Cf + (size_t)r * N + cc) = o2;
                }
            }
        }
}

// ---------------- MMA flash attention (3xBF16, causal, NO score scaling) ----
__global__ __launch_bounds__(256) void attn_mma(const float* __restrict__ Qf,
                                                const __nv_bfloat16* __restrict__ KH,
                                                const __nv_bfloat16* __restrict__ KL,
                                                const __nv_bfloat16* __restrict__ VH,
                                                const __nv_bfloat16* __restrict__ VL,
                                                __half* __restrict__ attF) {
    constexpr int ST = 72;
    int b = blockIdx.z, h = blockIdx.y;
    int q0 = blockIdx.x * 128;
    int tid = threadIdx.x, wid = tid >> 5, lane = tid & 31;
    int g = lane >> 2, tg = lane & 3;
    int qw0 = q0 + wid * 16;
    const size_t bh_ = (size_t)(b * NHEAD + h);

    __shared__ __nv_bfloat16 sH[64 * ST], sL[64 * ST];

    uint32_t qh[4][4], ql[4][4];
    {
        const float* q_r0 = Qf + (size_t)(b * TSEQ + qw0 + g) * CDIM + h * HD;
        const float* q_r1 = q_r0 + 8 * CDIM;
        #pragma unroll
        for (int s = 0; s < 4; s++) {
            float2 v0 = *(const float2*)(q_r0 + 16 * s + 2 * tg);
            float2 v1 = *(const float2*)(q_r1 + 16 * s + 2 * tg);
            float2 v2 = *(const float2*)(q_r0 + 16 * s + 2 * tg + 8);
            float2 v3 = *(const float2*)(q_r1 + 16 * s + 2 * tg + 8);
            pack_hl(v0.x, v0.y, qh[s][0], ql[s][0]);
            pack_hl(v1.x, v1.y, qh[s][1], ql[s][1]);
            pack_hl(v2.x, v2.y, qh[s][2], ql[s][2]);
            pack_hl(v3.x, v3.y, qh[s][3], ql[s][3]);
        }
    }

    float o[8][4];
    #pragma unroll
    for (int ni = 0; ni < 8; ni++)
        #pragma unroll
        for (int r = 0; r < 4; r++) o[ni][r] = 0.f;
    float m0 = -1e30f, m1 = -1e30f, l0 = 0.f, l1 = 0.f;

    int kend = q0 + 128;
    for (int j0 = 0; j0 < kend; j0 += 64) {
        bool act = (j0 <= qw0 + 15);
        __syncthreads();
        {
            int kk = tid >> 2, d0 = (tid & 3) * 16;
            size_t ko = (bh_ * TSEQ + j0 + kk) * HD + d0;
            const uint4* kh = (const uint4*)&KH[ko];
            const uint4* kl = (const uint4*)&KL[ko];
            uint4 a0 = kh[0], a1 = kh[1];
            uint4 b0 = kl[0], b1 = kl[1];
            *(uint4*)&sH[kk * ST + d0]     = a0;
            *(uint4*)&sH[kk * ST + d0 + 8] = a1;
            *(uint4*)&sL[kk * ST + d0]     = b0;
            *(uint4*)&sL[kk * ST + d0 + 8] = b1;
        }
        __syncthreads();

        uint32_t ph[4][4], pl[4][4];
        if (act) {
            float s[8][4];
            #pragma unroll
            for (int ni = 0; ni < 8; ni++) {
                s[ni][0] = s[ni][1] = s[ni][2] = s[ni][3] = 0.f;
                #pragma unroll
                for (int ss = 0; ss < 4; ss++) {
                    int ib = (8 * ni + g) * ST + 16 * ss + 2 * tg;
                    uint32_t bh2[2] = { *(const uint32_t*)&sH[ib], *(const uint32_t*)&sH[ib + 8] };
                    uint32_t bl2[2] = { *(const uint32_t*)&sL[ib], *(const uint32_t*)&sL[ib + 8] };
                    mma_bf16(s[ni], qh[ss], bh2);
                    mma_bf16(s[ni], qh[ss], bl2);
                    mma_bf16(s[ni], ql[ss], bh2);
                }
            }
            int r0 = qw0 + g, r1 = r0 + 8;
            float mx0 = -1e30f, mx1 = -1e30f;
            #pragma unroll
            for (int ni = 0; ni < 8; ni++) {
                int kc = j0 + 8 * ni + 2 * tg;
                if (kc     > r0) s[ni][0] = -1e30f;
                if (kc + 1 > r0) s[ni][1] = -1e30f;
                if (kc     > r1) s[ni][2] = -1e30f;
                if (kc + 1 > r1) s[ni][3] = -1e30f;
                mx0 = fmaxf(mx0, fmaxf(s[ni][0], s[ni][1]));
                mx1 = fmaxf(mx1, fmaxf(s[ni][2], s[ni][3]));
            }
            mx0 = fmaxf(mx0, __shfl_xor_sync(0xffffffffu, mx0, 1));
            mx0 = fmaxf(mx0, __shfl_xor_sync(0xffffffffu, mx0, 2));
            mx1 = fmaxf(mx1, __shfl_xor_sync(0xffffffffu, mx1, 1));
            mx1 = fmaxf(mx1, __shfl_xor_sync(0xffffffffu, mx1, 2));
            float nm0 = fmaxf(m0, mx0), nm1 = fmaxf(m1, mx1);
            float c0 = __expf(m0 - nm0), c1 = __expf(m1 - nm1);
            m0 = nm0; m1 = nm1;
            float p[8][4];
            float ls0 = 0.f, ls1 = 0.f;
            #pragma unroll
            for (int ni = 0; ni < 8; ni++) {
                p[ni][0] = __expf(s[ni][0] - nm0);
                p[ni][1] = __expf(s[ni][1] - nm0);
                p[ni][2] = __expf(s[ni][2] - nm1);
                p[ni][3] = __expf(s[ni][3] - nm1);
                ls0 += p[ni][0] + p[ni][1];
                ls1 += p[ni][2] + p[ni][3];
            }
            l0 = l0 * c0 + ls0;
            l1 = l1 * c1 + ls1;
            #pragma unroll
            for (int ni = 0; ni < 8; ni++) {
                o[ni][0] *= c0; o[ni][1] *= c0; o[ni][2] *= c1; o[ni][3] *= c1;
            }
            #pragma unroll
            for (int ss = 0; ss < 4; ss++) {
                pack_hl(p[2*ss][0],   p[2*ss][1],   ph[ss][0], pl[ss][0]);
                pack_hl(p[2*ss][2],   p[2*ss][3],   ph[ss][1], pl[ss][1]);
                pack_hl(p[2*ss+1][0], p[2*ss+1][1], ph[ss][2], pl[ss][2]);
                pack_hl(p[2*ss+1][2], p[2*ss+1][3], ph[ss][3], pl[ss][3]);
            }
        }
        __syncthreads();
        {
            int kk = tid >> 2, d0 = (tid & 3) * 16;
            size_t vo = (bh_ * HD + kk) * TSEQ + j0 + d0;
            const uint4* vh = (const uint4*)&VH[vo];
            const uint4* vl = (const uint4*)&VL[vo];
            uint4 a0 = vh[0], a1 = vh[1];
            uint4 b0 = vl[0], b1 = vl[1];
            *(uint4*)&sH[kk * ST + d0]     = a0;
            *(uint4*)&sH[kk * ST + d0 + 8] = a1;
            *(uint4*)&sL[kk * ST + d0]     = b0;
            *(uint4*)&sL[kk * ST + d0 + 8] = b1;
        }
        __syncthreads();
        if (act) {
            #pragma unroll
            for (int ni = 0; ni < 8; ni++)
                #pragma unroll
                for (int ss = 0; ss < 4; ss++) {
                    int ib = (8 * ni + g) * ST + 16 * ss + 2 * tg;
                    uint32_t bh2[2] = { *(const uint32_t*)&sH[ib], *(const uint32_t*)&sH[ib + 8] };
                    uint32_t bl2[2] = { *(const uint32_t*)&sL[ib], *(const uint32_t*)&sL[ib + 8] };
                    mma_bf16(o[ni], ph[ss], bh2);
                    mma_bf16(o[ni], ph[ss], bl2);
                    mma_bf16(o[ni], pl[ss], bh2);
                }
        }
    }

    l0 += __shfl_xor_sync(0xffffffffu, l0, 1);
    l0 += __shfl_xor_sync(0xffffffffu, l0, 2);
    l1 += __shfl_xor_sync(0xffffffffu, l1, 1);
    l1 += __shfl_xor_sync(0xffffffffu, l1, 2);
    float i0 = 1.f / l0, i1 = 1.f / l1;
    size_t ro0 = (size_t)(b * TSEQ + qw0 + g) * CDIM + h * HD;
    size_t ro1 = ro0 + 8 * CDIM;
    #pragma unroll
    for (int ni = 0; ni < 8; ni++) {
        *(uint32_t*)&attF[ro0 + 8 * ni + 2 * tg] = pack_h2(o[ni][0] * i0, o[ni][1] * i0);
        *(uint32_t*)&attF[ro1 + 8 * ni + 2 * tg] = pack_h2(o[ni][2] * i1, o[ni][3] * i1);
    }
}

// ---------------- per-row cross-entropy ----------------
__global__ __launch_bounds__(256) void loss_row_kernel(const float* __restrict__ logits,
                                                       const int* __restrict__ targets) {
    int row = blockIdx.x;
    const float* x = logits + (size_t)row * VOCAB;
    __shared__ float sh[8];
    float mx = -1e30f;
    for (int c = threadIdx.x; c < VOCAB; c += 256) mx = fmaxf(mx, x[c]);
    #pragma unroll
    for (int o = 16; o; o >>= 1) mx = fmaxf(mx, __shfl_down_sync(0xffffffffu, mx, o));
    if ((threadIdx.x & 31) == 0) sh[threadIdx.x >> 5] = mx;
    __syncthreads();
    if (threadIdx.x == 0) {
        float a = sh[0];
        #pragma unroll
        for (int i = 1; i < 8; i++) a = fmaxf(a, sh[i]);
        sh[0] = a;
    }
    __syncthreads();
    mx = sh[0];
    __syncthreads();
    float s = 0.f;
    for (int c = threadIdx.x; c < VOCAB; c += 256) s += expf(x[c] - mx);
    #pragma unroll
    for (int o = 16; o; o >>= 1) s += __shfl_down_sync(0xffffffffu, s, o);
    if ((threadIdx.x & 31) == 0) sh[threadIdx.x >> 5] = s;
    __syncthreads();
    if (threadIdx.x == 0) {
        float a = 0.f;
        #pragma unroll
        for (int i = 0; i < 8; i++) a += sh[i];
        g_rowloss[row] = (mx + logf(a)) - x[targets[row]];
    }
}

__global__ __launch_bounds__(1024) void loss_reduce_kernel(float* __restrict__ out) {
    __shared__ float sh[1024];
    int t = threadIdx.x;
    float s = 0.f;
    for (int i = t; i < NTOK; i += 1024) s += g_rowloss[i];
    sh[t] = s;
    __syncthreads();
    for (int o = 512; o; o >>= 1) {
        if (t < o) sh[t] += sh[t + o];
        __syncthreads();
    }
    if (t == 0) out[0] = sh[0] * (1.f / NTOK);
}

// ---------------- launch ----------------
extern "C" void kernel_launch(void* const* d_in, const int* in_sizes, int n_in,
                              void* d_out, int out_size) {
    const int*   x       = (const int*)  d_in[0];
    const int*   targets = (const int*)  d_in[1];
    const float* wte     = (const float*)d_in[2];
    const float* wpe     = (const float*)d_in[3];
    const float* ln1_w   = (const float*)d_in[4];
    const float* ln1_b   = (const float*)d_in[5];
    const float* attn_w  = (const float*)d_in[6];
    const float* attn_b  = (const float*)d_in[7];
    const float* proj_w  = (const float*)d_in[8];
    const float* proj_b  = (const float*)d_in[9];
    const float* ln2_w   = (const float*)d_in[10];
    const float* ln2_b   = (const float*)d_in[11];
    const float* fc_w    = (const float*)d_in[12];
    const float* fc_b    = (const float*)d_in[13];
    const float* fc2_w   = (const float*)d_in[14];
    const float* fc2_b   = (const float*)d_in[15];
    const float* lnf_w   = (const float*)d_in[16];
    const float* lnf_b   = (const float*)d_in[17];

    float* logits = (float*)d_out;
    float* lossp  = (float*)d_out + (out_size - 1);

    float *p_h, *p_q;
    __nv_bfloat16 *p_kH, *p_kL, *p_vH, *p_vL;
    __half *p_hn, *p_att, *p_fc;
    __half *p_waH, *p_waL, *p_wpH, *p_wpL, *p_wfH, *p_wfL, *p_wf2H, *p_wf2L, *p_wteH, *p_wteL;
    cudaGetSymbolAddress((void**)&p_h,    g_h);
    cudaGetSymbolAddress((void**)&p_q,    g_q);
    cudaGetSymbolAddress((void**)&p_kH,   g_kH);
    cudaGetSymbolAddress((void**)&p_kL,   g_kL);
    cudaGetSymbolAddress((void**)&p_vH,   g_vH);
    cudaGetSymbolAddress((void**)&p_vL,   g_vL);
    cudaGetSymbolAddress((void**)&p_hn,   g_hn);
    cudaGetSymbolAddress((void**)&p_att,  g_att);
    cudaGetSymbolAddress((void**)&p_fc,   g_fc);
    cudaGetSymbolAddress((void**)&p_waH,  g_waH);
    cudaGetSymbolAddress((void**)&p_waL,  g_waL);
    cudaGetSymbolAddress((void**)&p_wpH,  g_wpH);
    cudaGetSymbolAddress((void**)&p_wpL,  g_wpL);
    cudaGetSymbolAddress((void**)&p_wfH,  g_wfH);
    cudaGetSymbolAddress((void**)&p_wfL,  g_wfL);
    cudaGetSymbolAddress((void**)&p_wf2H, g_wf2H);
    cudaGetSymbolAddress((void**)&p_wf2L, g_wf2L);
    cudaGetSymbolAddress((void**)&p_wteH, g_wteH);
    cudaGetSymbolAddress((void**)&p_wteL, g_wteL);

    cudaFuncSetAttribute(pgemm<1>, cudaFuncAttributeMaxDynamicSharedMemorySize, PG_SMEM);
    cudaFuncSetAttribute(pgemm<2>, cudaFuncAttributeMaxDynamicSharedMemorySize, PG_SMEM);
    cudaFuncSetAttribute(pgemm<3>, cudaFuncAttributeMaxDynamicSharedMemorySize, PG_SMEM);
    cudaFuncSetAttribute(pgemm<4>, cudaFuncAttributeMaxDynamicSharedMemorySize, PG_SMEM);

    // ---- weight pre-split (once per launch) ----
    wsplit_t<<<dim3(C3 / 32, CDIM / 32, NLAYER), 256>>>(attn_w, p_waH, p_waL, CDIM, C3);
    wsplit_t<<<dim3(CDIM / 32, CDIM / 32, NLAYER), 256>>>(proj_w, p_wpH, p_wpL, CDIM, CDIM);
    wsplit_t<<<dim3(C4 / 32, CDIM / 32, NLAYER), 256>>>(fc_w, p_wfH, p_wfL, CDIM, C4);
    wsplit_t<<<dim3(CDIM / 32, C4 / 32, NLAYER), 256>>>(fc2_w, p_wf2H, p_wf2L, C4, CDIM);
    wsplit<<<(WTEN / 2 + 255) / 256, 256>>>(wte, p_wteH, p_wteL, WTEN);

    embed_kernel<<<NTOK, 256>>>(x, wte, wpe);

    for (int l = 0; l < NLAYER; l++) {
        ln_kernel<<<NTOK, 256>>>(p_h, ln1_w + (size_t)l * CDIM, ln1_b + (size_t)l * CDIM, p_hn);
        pgemm<4><<<dim3(C3 / 128, NTOK / 128), 256, PG_SMEM>>>(
            p_hn, p_waH + (size_t)l * C3 * CDIM, p_waL + (size_t)l * C3 * CDIM,
            attn_b + (size_t)l * C3, nullptr, p_q, nullptr, p_kH, p_kL, p_vH, p_vL, NTOK, C3, CDIM);
        attn_mma<<<dim3(TSEQ / 128, NHEAD, BATCH), 256>>>(p_q, p_kH, p_kL, p_vH, p_vL, p_att);
        pgemm<2><<<dim3(CDIM / 128, NTOK / 128), 256, PG_SMEM>>>(
            p_att, p_wpH + (size_t)l * CDIM * CDIM, p_wpL + (size_t)l * CDIM * CDIM,
            proj_b + (size_t)l * CDIM, p_h, p_h, nullptr, nullptr, nullptr, nullptr, nullptr,
            NTOK, CDIM, CDIM);
        ln_kernel<<<NTOK, 256>>>(p_h, ln2_w + (size_t)l * CDIM, ln2_b + (size_t)l * CDIM, p_hn);
        pgemm<1><<<dim3(C4 / 128, NTOK / 128), 256, PG_SMEM>>>(
            p_hn, p_wfH + (size_t)l * C4 * CDIM, p_wfL + (size_t)l * C4 * CDIM,
            fc_b + (size_t)l * C4, nullptr, nullptr, p_fc, nullptr, nullptr, nullptr, nullptr,
            NTOK, C4, CDIM);
        pgemm<2><<<dim3(CDIM / 128, NTOK / 128), 256, PG_SMEM>>>(
            p_fc, p_wf2H + (size_t)l * CDIM * C4, p_wf2L + (size_t)l * CDIM * C4,
            fc2_b + (size_t)l * CDIM, p_h, p_h, nullptr, nullptr, nullptr, nullptr, nullptr,
            NTOK, CDIM, C4);
    }

    ln_kernel<<<NTOK, 256>>>(p_h, lnf_w, lnf_b, p_hn);
    pgemm<3><<<dim3(VOCAB / 128, NTOK / 128), 256, PG_SMEM>>>(
        p_hn, p_wteH, p_wteL, nullptr, nullptr, logits, nullptr, nullptr, nullptr, nullptr, nullptr,
        NTOK, VOCAB, CDIM);

    loss_row_kernel<<<NTOK, 256>>>(logits, targets);
    loss_reduce_kernel<<<1, 1024>>>(lossp);
}

// round 16
// speedup vs baseline: 1.8186x; 1.0117x over previous
#include <cuda_runtime.h>
#include <cuda_bf16.h>
#include <cuda_fp16.h>
#include <math.h>
#include <stdint.h>

// ---------------- problem constants ----------------
#define BATCH 4
#define TSEQ  1024
#define CDIM  768
#define NHEAD 12
#define HD    64
#define VOCAB 50304
#define NLAYER 12
#define NTOK  (BATCH*TSEQ)     // 4096
#define C3    (3*CDIM)         // 2304
#define C4    (4*CDIM)         // 3072

#define WATTN (NLAYER*C3*CDIM)
#define WPROJ (NLAYER*CDIM*CDIM)
#define WFC   (NLAYER*C4*CDIM)
#define WFC2  (NLAYER*CDIM*C4)
#define WTEN  (VOCAB*CDIM)

// ---------------- scratch (static device globals; no allocation allowed) ----
__device__ float g_h [NTOK * CDIM];
__device__ float g_q [NTOK * CDIM];
__device__ float g_rowloss[NTOK];
__device__ __nv_bfloat16 g_kH[NTOK * CDIM], g_kL[NTOK * CDIM];   // [b*H+h][t][d]
__device__ __nv_bfloat16 g_vH[NTOK * CDIM], g_vL[NTOK * CDIM];   // [b*H+h][d][t]
__device__ __half g_hn [NTOK * CDIM];
__device__ __half g_att[NTOK * CDIM];
__device__ __half g_fc [NTOK * C4];
__device__ __half g_waH[WATTN],  g_waL[WATTN];
__device__ __half g_wpH[WPROJ],  g_wpL[WPROJ];
__device__ __half g_wfH[WFC],    g_wfL[WFC];
__device__ __half g_wf2H[WFC2],  g_wf2L[WFC2];
__device__ __half g_wteH[WTEN],  g_wteL[WTEN];

// ---------------- split helpers ----------------
__device__ __forceinline__ void bsplit(float x, uint16_t& h, uint16_t& l) {
    __nv_bfloat16 bh = __float2bfloat16_rn(x);
    h = __bfloat16_as_ushort(bh);
    float r = x - __bfloat162float(bh);
    l = __bfloat16_as_ushort(__float2bfloat16_rn(r));
}
__device__ __forceinline__ void pack_hl(float vx, float vy, uint32_t& h, uint32_t& l) {
    uint16_t hx, lx, hy, ly;
    bsplit(vx, hx, lx); bsplit(vy, hy, ly);
    h = (uint32_t)hx | ((uint32_t)hy << 16);
    l = (uint32_t)lx | ((uint32_t)ly << 16);
}
__device__ __forceinline__ void hsplit(float x, uint16_t& h, uint16_t& l) {
    __half hh = __float2half_rn(x);
    h = __half_as_ushort(hh);
    float r = x - __half2float(hh);
    l = __half_as_ushort(__float2half_rn(r));
}
__device__ __forceinline__ void pack_hl_h(float vx, float vy, uint32_t& h, uint32_t& l) {
    uint16_t hx, lx, hy, ly;
    hsplit(vx, hx, lx); hsplit(vy, hy, ly);
    h = (uint32_t)hx | ((uint32_t)hy << 16);
    l = (uint32_t)lx | ((uint32_t)ly << 16);
}
__device__ __forceinline__ uint32_t pack_h2(float x, float y) {
    __half2 t = __floats2half2_rn(x, y);
    return *(uint32_t*)&t;
}
__device__ __forceinline__ void mma_bf16(float* c, const uint32_t* a, const uint32_t* b) {
    asm volatile(
        "mma.sync.aligned.m16n8k16.row.col.f32.bf16.bf16.f32 "
        "{%0,%1,%2,%3},{%4,%5,%6,%7},{%8,%9},{%0,%1,%2,%3};"
        : "+f"(c[0]), "+f"(c[1]), "+f"(c[2]), "+f"(c[3])
        : "r"(a[0]), "r"(a[1]), "r"(a[2]), "r"(a[3]), "r"(b[0]), "r"(b[1]));
}
__device__ __forceinline__ void mma_f16(float* c, const uint32_t* a, const uint32_t* b) {
    asm volatile(
        "mma.sync.aligned.m16n8k16.row.col.f32.f16.f16.f32 "
        "{%0,%1,%2,%3},{%4,%5,%6,%7},{%8,%9},{%0,%1,%2,%3};"
        : "+f"(c[0]), "+f"(c[1]), "+f"(c[2]), "+f"(c[3])
        : "r"(a[0]), "r"(a[1]), "r"(a[2]), "r"(a[3]), "r"(b[0]), "r"(b[1]));
}
__device__ __forceinline__ uint32_t smem_u32(const void* p) {
    uint32_t a;
    asm("{ .reg .u64 t; cvta.to.shared.u64 t, %1; cvt.u32.u64 %0, t; }" : "=r"(a) : "l"(p));
    return a;
}
__device__ __forceinline__ void ldsm4(uint32_t& r0, uint32_t& r1, uint32_t& r2, uint32_t& r3,
                                      uint32_t addr) {
    asm volatile("ldmatrix.sync.aligned.m8n8.x4.shared.b16 {%0,%1,%2,%3}, [%4];"
                 : "=r"(r0), "=r"(r1), "=r"(r2), "=r"(r3) : "r"(addr));
}
// swizzled offset for (logical row r, 16B chunk c4) in a 128x64B tile
__device__ __forceinline__ uint32_t swz(uint32_t r, uint32_t c4) {
    uint32_t pr = r >> 1;
    uint32_t ch = ((r & 1) << 2) | c4;
    return (pr << 7) + (((ch ^ (pr & 7))) << 4);
}

// ---------------- weight conversion kernels (once per launch) ----------------
__global__ __launch_bounds__(256) void wsplit_t(const float* __restrict__ in,
                                                __half* __restrict__ oh,
                                                __half* __restrict__ ol,
                                                int K, int N) {
    __shared__ float t[32][33];
    size_t loff = (size_t)blockIdx.z * K * N;
    const float* src = in + loff;
    int nb = blockIdx.x * 32, kb = blockIdx.y * 32;
    int tx = threadIdx.x & 31, ty = threadIdx.x >> 5;
    #pragma unroll
    for (int i = 0; i < 32; i += 8)
        t[ty + i][tx] = src[(size_t)(kb + ty + i) * N + nb + tx];
    __syncthreads();
    #pragma unroll
    for (int i = 0; i < 32; i += 8) {
        float v = t[tx][ty + i];
        uint16_t h, l; hsplit(v, h, l);
        size_t o = loff + (size_t)(nb + ty + i) * K + kb + tx;
        oh[o] = __ushort_as_half(h);
        ol[o] = __ushort_as_half(l);
    }
}
__global__ __launch_bounds__(256) void wsplit(const float* __restrict__ in,
                                              __half* __restrict__ oh,
                                              __half* __restrict__ ol, int n) {
    int i = (blockIdx.x * 256 + threadIdx.x) * 2;
    if (i < n) {
        uint32_t h, l;
        pack_hl_h(in[i], in[i + 1], h, l);
        *(uint32_t*)&oh[i] = h;
        *(uint32_t*)&ol[i] = l;
    }
}

// ---------------- embedding ----------------
__global__ __launch_bounds__(256) void embed_kernel(const int* __restrict__ x,
                                                    const float* __restrict__ wte,
                                                    const float* __restrict__ wpe) {
    int m = blockIdx.x;
    int t = m % TSEQ;
    int idx = x[m];
    const float* we = wte + (size_t)idx * CDIM;
    const float* wp = wpe + (size_t)t * CDIM;
    float* o = g_h + (size_t)m * CDIM;
    for (int c = threadIdx.x; c < CDIM; c += 256)
        o[c] = we[c] + wp[c];
}

// ---------------- layernorm: fp32 in -> fp16 out ----------------
__global__ __launch_bounds__(256) void ln_kernel(const float* __restrict__ in,
                                                 const float* __restrict__ w,
                                                 const float* __restrict__ bb,
                                                 __half* __restrict__ oh) {
    int row = blockIdx.x;
    const float* x = in + (size_t)row * CDIM;
    float s = 0.f, s2 = 0.f;
    for (int c = threadIdx.x; c < CDIM; c += 256) {
        float v = x[c]; s += v; s2 += v * v;
    }
    __shared__ float ss[8], ss2[8];
    #pragma unroll
    for (int o = 16; o; o >>= 1) {
        s  += __shfl_down_sync(0xffffffffu, s,  o);
        s2 += __shfl_down_sync(0xffffffffu, s2, o);
    }
    if ((threadIdx.x & 31) == 0) { ss[threadIdx.x >> 5] = s; ss2[threadIdx.x >> 5] = s2; }
    __syncthreads();
    if (threadIdx.x == 0) {
        float a = 0.f, a2 = 0.f;
        #pragma unroll
        for (int i = 0; i < 8; i++) { a += ss[i]; a2 += ss2[i]; }
        ss[0] = a; ss2[0] = a2;
    }
    __syncthreads();
    float mean = ss[0] * (1.f / CDIM);
    float var  = ss2[0] * (1.f / CDIM) - mean * mean;
    float rstd = rsqrtf(var + 1e-5f);
    __half* oH = oh + (size_t)row * CDIM;
    for (int c = threadIdx.x * 2; c < CDIM; c += 512) {
        float v0 = (x[c]     - mean) * rstd * w[c]     + bb[c];
        float v1 = (x[c + 1] - mean) * rstd * w[c + 1] + bb[c + 1];
        *(uint32_t*)&oH[c] = pack_h2(v0, v1);
    }
}

// ---------------- 2xFP16 GEMM: A fp16 1-term, B fp16 hi/lo 2-term ----------
// EPI: 1 = +bias,gelu -> fp16; 2 = +bias+residual -> fp32; 3 = plain -> fp32;
//      4 = qkv split (Q fp32, K bf16 hi/lo, V transposed bf16 hi/lo)
#define PG_ARR   8192
#define PG_STG   (3 * PG_ARR)
#define PG_SMEM  (2 * PG_STG)

template<int EPI>
__global__ __launch_bounds__(256) void pgemm(const __half* __restrict__ A,
                                             const __half* __restrict__ BH,
                                             const __half* __restrict__ BL,
                                             const float* __restrict__ bias,
                                             const float* __restrict__ add,
                                             float* __restrict__ Cf,
                                             __half* __restrict__ Ch,
                                             __nv_bfloat16* __restrict__ KH,
                                             __nv_bfloat16* __restrict__ KL,
                                             __nv_bfloat16* __restrict__ VH,
                                             __nv_bfloat16* __restrict__ VL,
                                             int M, int N, int K) {
    extern __shared__ char smem[];
    uint32_t sb = smem_u32(smem);

    int tid  = threadIdx.x;
    int wid  = tid >> 5, lane = tid & 31;
    int wr   = wid >> 2, wc = wid & 3;
    int g    = lane >> 2, tg = lane & 3;
    int row0 = blockIdx.y * 128, col0 = blockIdx.x * 128;

    const uint32_t lrow = lane & 15;
    const uint32_t lc4  = (lane >> 4);

    const __half* srcs[3] = { A, BH, BL };

    auto issue = [&](int k0, int s) {
        uint32_t sbase = sb + s * PG_STG;
        #pragma unroll
        for (int arr = 0; arr < 3; arr++) {
            const __half* gs = srcs[arr];
            int rbase = (arr == 0) ? row0 : col0;
            #pragma unroll
            for (int i = 0; i < 2; i++) {
                int ch = tid + i * 256;
                int r = ch >> 2, cb = ch & 3;
                const char* src = (const char*)(gs + (size_t)(rbase + r) * K + k0) + cb * 16;
                uint32_t dst = sbase + arr * PG_ARR + swz(r, cb);
                asm volatile("cp.async.cg.shared.global [%0], [%1], 16;"
                             :: "r"(dst), "l"(src) : "memory");
            }
        }
        asm volatile("cp.async.commit_group;" ::: "memory");
    };

    float c[4][4][4];
    #pragma unroll
    for (int mi = 0; mi < 4; mi++)
        #pragma unroll
        for (int ni = 0; ni < 4; ni++)
            #pragma unroll
            for (int r = 0; r < 4; r++) c[mi][ni][r] = 0.f;

    int nk = K / 32;
    issue(0, 0);

    for (int ki = 0; ki < nk; ki++) {
        if (ki + 1 < nk) {
            issue((ki + 1) * 32, (ki + 1) & 1);
            asm volatile("cp.async.wait_group 1;" ::: "memory");
        } else {
            asm volatile("cp.async.wait_group 0;" ::: "memory");
        }
        __syncthreads();

        uint32_t sA  = sb + (ki & 1) * PG_STG;
        uint32_t sBh = sA + PG_ARR;
        uint32_t sBl = sA + 2 * PG_ARR;

        #pragma unroll
        for (int ks = 0; ks < 2; ks++) {
            uint32_t c4 = ks * 2 + lc4;
            uint32_t a[4][4], bh[4][2], bl[4][2];
            #pragma unroll
            for (int mi = 0; mi < 4; mi++) {
                uint32_t off = swz(wr * 64 + mi * 16 + lrow, c4);
                ldsm4(a[mi][0], a[mi][1], a[mi][2], a[mi][3], sA + off);
            }
            #pragma unroll
            for (int q = 0; q < 2; q++) {
                uint32_t off = swz(wc * 32 + q * 16 + lrow, c4);
                uint32_t r0, r1, r2, r3;
                ldsm4(r0, r1, r2, r3, sBh + off);
                bh[2*q][0] = r0; bh[2*q+1][0] = r1; bh[2*q][1] = r2; bh[2*q+1][1] = r3;
                ldsm4(r0, r1, r2, r3, sBl + off);
                bl[2*q][0] = r0; bl[2*q+1][0] = r1; bl[2*q][1] = r2; bl[2*q+1][1] = r3;
            }
            #pragma unroll
            for (int mi = 0; mi < 4; mi++)
                #pragma unroll
                for (int ni = 0; ni < 4; ni++) {
                    mma_f16(c[mi][ni], a[mi], bh[ni]);
                    mma_f16(c[mi][ni], a[mi], bl[ni]);
                }
        }
        __syncthreads();
    }

    // ---- epilogue ----
    #pragma unroll
    for (int mi = 0; mi < 4; mi++)
        #pragma unroll
        for (int ni = 0; ni < 4; ni++) {
            int cc = col0 + wc * 32 + ni * 8 + tg * 2;
            #pragma unroll
            for (int hh = 0; hh < 2; hh++) {
                int r = row0 + wr * 64 + mi * 16 + g + hh * 8;
                float v0 = c[mi][ni][hh * 2 + 0];
                float v1 = c[mi][ni][hh * 2 + 1];
                if (EPI != 3) { v0 += bias[cc]; v1 += bias[cc + 1]; }
                if (EPI == 2) {
                    const float2 a2 = *(const float2*)(add + (size_t)r * N + cc);
                    v0 += a2.x; v1 += a2.y;
                }
                if (EPI == 1) {
                    float t0 = 0.7978845608028654f * (v0 + 0.044715f * v0 * v0 * v0);
                    v0 = 0.5f * v0 * (1.0f + tanhf(t0));
                    float t1 = 0.7978845608028654f * (v1 + 0.044715f * v1 * v1 * v1);
                    v1 = 0.5f * v1 * (1.0f + tanhf(t1));
                    *(uint32_t*)&Ch[(size_t)r * N + cc] = pack_h2(v0, v1);
                } else if (EPI == 4) {
                    int b = r >> 10, t = r & 1023;
                    int sec = cc / CDIM, chn = cc % CDIM;
                    int h = chn >> 6, d = chn & 63;
                    size_t bh_ = (size_t)(b * NHEAD + h);
                    if (sec == 0) {
                        float2 o2; o2.x = v0; o2.y = v1;
                        *(float2*)(Cf + (size_t)r * CDIM + chn) = o2;
                    } else if (sec == 1) {
                        uint32_t hh_, ll_;
                        pack_hl(v0, v1, hh_, ll_);
                        size_t o = (bh_ * TSEQ + t) * HD + d;
                        *(uint32_t*)&KH[o] = hh_;
                        *(uint32_t*)&KL[o] = ll_;
                    } else {
                        uint16_t h0, l0, h1, l1;
                        bsplit(v0, h0, l0); bsplit(v1, h1, l1);
                        size_t o = (bh_ * HD + d) * TSEQ + t;
                        VH[o] = __ushort_as_bfloat16(h0);
                        VL[o] = __ushort_as_bfloat16(l0);
                        VH[o + TSEQ] = __ushort_as_bfloat16(h1);
                        VL[o + TSEQ] = __ushort_as_bfloat16(l1);
                    }
                } else {
                    float2 o2; o2.x = v0; o2.y = v1;
                    *(float2*)(Cf + (size_t)r * N + cc) = o2;
                }
            }
        }
}

// ---------------- MMA flash attention (3xBF16, causal, NO score scaling) ----
// Separate K and V smem buffers: one staging phase, 2 barriers per tile.
__global__ __launch_bounds__(256) void attn_mma(const float* __restrict__ Qf,
                                                const __nv_bfloat16* __restrict__ KH,
                                                const __nv_bfloat16* __restrict__ KL,
                                                const __nv_bfloat16* __restrict__ VH,
                                                const __nv_bfloat16* __restrict__ VL,
                                                __half* __restrict__ attF) {
    constexpr int ST = 72;
    int b = blockIdx.z, h = blockIdx.y;
    int q0 = blockIdx.x * 128;
    int tid = threadIdx.x, wid = tid >> 5, lane = tid & 31;
    int g = lane >> 2, tg = lane & 3;
    int qw0 = q0 + wid * 16;
    const size_t bh_ = (size_t)(b * NHEAD + h);

    __shared__ __nv_bfloat16 sKH[64 * ST], sKL[64 * ST];
    __shared__ __nv_bfloat16 sVH[64 * ST], sVL[64 * ST];

    uint32_t qh[4][4], ql[4][4];
    {
        const float* q_r0 = Qf + (size_t)(b * TSEQ + qw0 + g) * CDIM + h * HD;
        const float* q_r1 = q_r0 + 8 * CDIM;
        #pragma unroll
        for (int s = 0; s < 4; s++) {
            float2 v0 = *(const float2*)(q_r0 + 16 * s + 2 * tg);
            float2 v1 = *(const float2*)(q_r1 + 16 * s + 2 * tg);
            float2 v2 = *(const float2*)(q_r0 + 16 * s + 2 * tg + 8);
            float2 v3 = *(const float2*)(q_r1 + 16 * s + 2 * tg + 8);
            pack_hl(v0.x, v0.y, qh[s][0], ql[s][0]);
            pack_hl(v1.x, v1.y, qh[s][1], ql[s][1]);
            pack_hl(v2.x, v2.y, qh[s][2], ql[s][2]);
            pack_hl(v3.x, v3.y, qh[s][3], ql[s][3]);
        }
    }

    float o[8][4];
    #pragma unroll
    for (int ni = 0; ni < 8; ni++)
        #pragma unroll
        for (int r = 0; r < 4; r++) o[ni][r] = 0.f;
    float m0 = -1e30f, m1 = -1e30f, l0 = 0.f, l1 = 0.f;

    int kend = q0 + 128;
    for (int j0 = 0; j0 < kend; j0 += 64) {
        bool act = (j0 <= qw0 + 15);
        __syncthreads();   // prior tile's reads done before overwrite
        {   // ---- stage K and V (batched copies) ----
            int kk = tid >> 2, d0 = (tid & 3) * 16;
            size_t ko = (bh_ * TSEQ + j0 + kk) * HD + d0;
            size_t vo = (bh_ * HD + kk) * TSEQ + j0 + d0;
            uint4 k0_ = ((const uint4*)&KH[ko])[0];
            uint4 k1_ = ((const uint4*)&KH[ko])[1];
            uint4 k2_ = ((const uint4*)&KL[ko])[0];
            uint4 k3_ = ((const uint4*)&KL[ko])[1];
            uint4 v0_ = ((const uint4*)&VH[vo])[0];
            uint4 v1_ = ((const uint4*)&VH[vo])[1];
            uint4 v2_ = ((const uint4*)&VL[vo])[0];
            uint4 v3_ = ((const uint4*)&VL[vo])[1];
            *(uint4*)&sKH[kk * ST + d0]     = k0_;
            *(uint4*)&sKH[kk * ST + d0 + 8] = k1_;
            *(uint4*)&sKL[kk * ST + d0]     = k2_;
            *(uint4*)&sKL[kk * ST + d0 + 8] = k3_;
            *(uint4*)&sVH[kk * ST + d0]     = v0_;
            *(uint4*)&sVH[kk * ST + d0 + 8] = v1_;
            *(uint4*)&sVL[kk * ST + d0]     = v2_;
            *(uint4*)&sVL[kk * ST + d0 + 8] = v3_;
        }
        __syncthreads();

        if (act) {
            float s[8][4];
            #pragma unroll
            for (int ni = 0; ni < 8; ni++) {
                s[ni][0] = s[ni][1] = s[ni][2] = s[ni][3] = 0.f;
                #pragma unroll
                for (int ss = 0; ss < 4; ss++) {
                    int ib = (8 * ni + g) * ST + 16 * ss + 2 * tg;
                    uint32_t bh2[2] = { *(const uint32_t*)&sKH[ib], *(const uint32_t*)&sKH[ib + 8] };
                    uint32_t bl2[2] = { *(const uint32_t*)&sKL[ib], *(const uint32_t*)&sKL[ib + 8] };
                    mma_bf16(s[ni], qh[ss], bh2);
                    mma_bf16(s[ni], qh[ss], bl2);
                    mma_bf16(s[ni], ql[ss], bh2);
                }
            }
            int r0 = qw0 + g, r1 = r0 + 8;
            float mx0 = -1e30f, mx1 = -1e30f;
            #pragma unroll
            for (int ni = 0; ni < 8; ni++) {
                int kc = j0 + 8 * ni + 2 * tg;
                if (kc     > r0) s[ni][0] = -1e30f;
                if (kc + 1 > r0) s[ni][1] = -1e30f;
                if (kc     > r1) s[ni][2] = -1e30f;
                if (kc + 1 > r1) s[ni][3] = -1e30f;
                mx0 = fmaxf(mx0, fmaxf(s[ni][0], s[ni][1]));
                mx1 = fmaxf(mx1, fmaxf(s[ni][2], s[ni][3]));
            }
            mx0 = fmaxf(mx0, __shfl_xor_sync(0xffffffffu, mx0, 1));
            mx0 = fmaxf(mx0, __shfl_xor_sync(0xffffffffu, mx0, 2));
            mx1 = fmaxf(mx1, __shfl_xor_sync(0xffffffffu, mx1, 1));
            mx1 = fmaxf(mx1, __shfl_xor_sync(0xffffffffu, mx1, 2));
            float nm0 = fmaxf(m0, mx0), nm1 = fmaxf(m1, mx1);
            float c0 = __expf(m0 - nm0), c1 = __expf(m1 - nm1);
            m0 = nm0; m1 = nm1;
            float p[8][4];
            float ls0 = 0.f, ls1 = 0.f;
            #pragma unroll
            for (int ni = 0; ni < 8; ni++) {
                p[ni][0] = __expf(s[ni][0] - nm0);
                p[ni][1] = __expf(s[ni][1] - nm0);
                p[ni][2] = __expf(s[ni][2] - nm1);
                p[ni][3] = __expf(s[ni][3] - nm1);
                ls0 += p[ni][0] + p[ni][1];
                ls1 += p[ni][2] + p[ni][3];
            }
            l0 = l0 * c0 + ls0;
            l1 = l1 * c1 + ls1;
            #pragma unroll
            for (int ni = 0; ni < 8; ni++) {
                o[ni][0] *= c0; o[ni][1] *= c0; o[ni][2] *= c1; o[ni][3] *= c1;
            }
            uint32_t ph[4][4], pl[4][4];
            #pragma unroll
            for (int ss = 0; ss < 4; ss++) {
                pack_hl(p[2*ss][0],   p[2*ss][1],   ph[ss][0], pl[ss][0]);
                pack_hl(p[2*ss][2],   p[2*ss][3],   ph[ss][1], pl[ss][1]);
                pack_hl(p[2*ss+1][0], p[2*ss+1][1], ph[ss][2], pl[ss][2]);
                pack_hl(p[2*ss+1][2], p[2*ss+1][3], ph[ss][3], pl[ss][3]);
            }
            #pragma unroll
            for (int ni = 0; ni < 8; ni++)
                #pragma unroll
                for (int ss = 0; ss < 4; ss++) {
                    int ib = (8 * ni + g) * ST + 16 * ss + 2 * tg;
                    uint32_t bh2[2] = { *(const uint32_t*)&sVH[ib], *(const uint32_t*)&sVH[ib + 8] };
                    uint32_t bl2[2] = { *(const uint32_t*)&sVL[ib], *(const uint32_t*)&sVL[ib + 8] };
                    mma_bf16(o[ni], ph[ss], bh2);
                    mma_bf16(o[ni], ph[ss], bl2);
                    mma_bf16(o[ni], pl[ss], bh2);
                }
        }
    }

    l0 += __shfl_xor_sync(0xffffffffu, l0, 1);
    l0 += __shfl_xor_sync(0xffffffffu, l0, 2);
    l1 += __shfl_xor_sync(0xffffffffu, l1, 1);
    l1 += __shfl_xor_sync(0xffffffffu, l1, 2);
    float i0 = 1.f / l0, i1 = 1.f / l1;
    size_t ro0 = (size_t)(b * TSEQ + qw0 + g) * CDIM + h * HD;
    size_t ro1 = ro0 + 8 * CDIM;
    #pragma unroll
    for (int ni = 0; ni < 8; ni++) {
        *(uint32_t*)&attF[ro0 + 8 * ni + 2 * tg] = pack_h2(o[ni][0] * i0, o[ni][1] * i0);
        *(uint32_t*)&attF[ro1 + 8 * ni + 2 * tg] = pack_h2(o[ni][2] * i1, o[ni][3] * i1);
    }
}

// ---------------- per-row cross-entropy (single-pass online softmax) --------
__global__ __launch_bounds__(256) void loss_row_kernel(const float* __restrict__ logits,
                                                       const int* __restrict__ targets) {
    int row = blockIdx.x;
    const float* x = logits + (size_t)row * VOCAB;
    float mx = -1e30f, s = 0.f;
    for (int c = threadIdx.x; c < VOCAB; c += 256) {
        float v = x[c];
        if (v > mx) { s *= __expf(mx - v); mx = v; }
        s += __expf(v - mx);
    }
    #pragma unroll
    for (int o = 16; o; o >>= 1) {
        float om = __shfl_down_sync(0xffffffffu, mx, o);
        float os = __shfl_down_sync(0xffffffffu, s,  o);
        float m2 = fmaxf(mx, om);
        s = s * __expf(mx - m2) + os * __expf(om - m2);
        mx = m2;
    }
    __shared__ float sm[8], ssum[8];
    if ((threadIdx.x & 31) == 0) { sm[threadIdx.x >> 5] = mx; ssum[threadIdx.x >> 5] = s; }
    __syncthreads();
    if (threadIdx.x == 0) {
        float m2 = sm[0], s2 = ssum[0];
        #pragma unroll
        for (int i = 1; i < 8; i++) {
            float m3 = fmaxf(m2, sm[i]);
            s2 = s2 * __expf(m2 - m3) + ssum[i] * __expf(sm[i] - m3);
            m2 = m3;
        }
        g_rowloss[row] = (m2 + logf(s2)) - x[targets[row]];
    }
}

__global__ __launch_bounds__(1024) void loss_reduce_kernel(float* __restrict__ out) {
    __shared__ float sh[1024];
    int t = threadIdx.x;
    float s = 0.f;
    for (int i = t; i < NTOK; i += 1024) s += g_rowloss[i];
    sh[t] = s;
    __syncthreads();
    for (int o = 512; o; o >>= 1) {
        if (t < o) sh[t] += sh[t + o];
        __syncthreads();
    }
    if (t == 0) out[0] = sh[0] * (1.f / NTOK);
}

// ---------------- launch ----------------
extern "C" void kernel_launch(void* const* d_in, const int* in_sizes, int n_in,
                              void* d_out, int out_size) {
    const int*   x       = (const int*)  d_in[0];
    const int*   targets = (const int*)  d_in[1];
    const float* wte     = (const float*)d_in[2];
    const float* wpe     = (const float*)d_in[3];
    const float* ln1_w   = (const float*)d_in[4];
    const float* ln1_b   = (const float*)d_in[5];
    const float* attn_w  = (const float*)d_in[6];
    const float* attn_b  = (const float*)d_in[7];
    const float* proj_w  = (const float*)d_in[8];
    const float* proj_b  = (const float*)d_in[9];
    const float* ln2_w   = (const float*)d_in[10];
    const float* ln2_b   = (const float*)d_in[11];
    const float* fc_w    = (const float*)d_in[12];
    const float* fc_b    = (const float*)d_in[13];
    const float* fc2_w   = (const float*)d_in[14];
    const float* fc2_b   = (const float*)d_in[15];
    const float* lnf_w   = (const float*)d_in[16];
    const float* lnf_b   = (const float*)d_in[17];

    float* logits = (float*)d_out;
    float* lossp  = (float*)d_out + (out_size - 1);

    float *p_h, *p_q;
    __nv_bfloat16 *p_kH, *p_kL, *p_vH, *p_vL;
    __half *p_hn, *p_att, *p_fc;
    __half *p_waH, *p_waL, *p_wpH, *p_wpL, *p_wfH, *p_wfL, *p_wf2H, *p_wf2L, *p_wteH, *p_wteL;
    cudaGetSymbolAddress((void**)&p_h,    g_h);
    cudaGetSymbolAddress((void**)&p_q,    g_q);
    cudaGetSymbolAddress((void**)&p_kH,   g_kH);
    cudaGetSymbolAddress((void**)&p_kL,   g_kL);
    cudaGetSymbolAddress((void**)&p_vH,   g_vH);
    cudaGetSymbolAddress((void**)&p_vL,   g_vL);
    cudaGetSymbolAddress((void**)&p_hn,   g_hn);
    cudaGetSymbolAddress((void**)&p_att,  g_att);
    cudaGetSymbolAddress((void**)&p_fc,   g_fc);
    cudaGetSymbolAddress((void**)&p_waH,  g_waH);
    cudaGetSymbolAddress((void**)&p_waL,  g_waL);
    cudaGetSymbolAddress((void**)&p_wpH,  g_wpH);
    cudaGetSymbolAddress((void**)&p_wpL,  g_wpL);
    cudaGetSymbolAddress((void**)&p_wfH,  g_wfH);
    cudaGetSymbolAddress((void**)&p_wfL,  g_wfL);
    cudaGetSymbolAddress((void**)&p_wf2H, g_wf2H);
    cudaGetSymbolAddress((void**)&p_wf2L, g_wf2L);
    cudaGetSymbolAddress((void**)&p_wteH, g_wteH);
    cudaGetSymbolAddress((void**)&p_wteL, g_wteL);

    cudaFuncSetAttribute(pgemm<1>, cudaFuncAttributeMaxDynamicSharedMemorySize, PG_SMEM);
    cudaFuncSetAttribute(pgemm<2>, cudaFuncAttributeMaxDynamicSharedMemorySize, PG_SMEM);
    cudaFuncSetAttribute(pgemm<3>, cudaFuncAttributeMaxDynamicSharedMemorySize, PG_SMEM);
    cudaFuncSetAttribute(pgemm<4>, cudaFuncAttributeMaxDynamicSharedMemorySize, PG_SMEM);

    // ---- weight pre-split (once per launch) ----
    wsplit_t<<<dim3(C3 / 32, CDIM / 32, NLAYER), 256>>>(attn_w, p_waH, p_waL, CDIM, C3);
    wsplit_t<<<dim3(CDIM / 32, CDIM / 32, NLAYER), 256>>>(proj_w, p_wpH, p_wpL, CDIM, CDIM);
    wsplit_t<<<dim3(C4 / 32, CDIM / 32, NLAYER), 256>>>(fc_w, p_wfH, p_wfL, CDIM, C4);
    wsplit_t<<<dim3(CDIM / 32, C4 / 32, NLAYER), 256>>>(fc2_w, p_wf2H, p_wf2L, C4, CDIM);
    wsplit<<<(WTEN / 2 + 255) / 256, 256>>>(wte, p_wteH, p_wteL, WTEN);

    embed_kernel<<<NTOK, 256>>>(x, wte, wpe);

    for (int l = 0; l < NLAYER; l++) {
        ln_kernel<<<NTOK, 256>>>(p_h, ln1_w + (size_t)l * CDIM, ln1_b + (size_t)l * CDIM, p_hn);
        pgemm<4><<<dim3(C3 / 128, NTOK / 128), 256, PG_SMEM>>>(
            p_hn, p_waH + (size_t)l * C3 * CDIM, p_waL + (size_t)l * C3 * CDIM,
            attn_b + (size_t)l * C3, nullptr, p_q, nullptr, p_kH, p_kL, p_vH, p_vL, NTOK, C3, CDIM);
        attn_mma<<<dim3(TSEQ / 128, NHEAD, BATCH), 256>>>(p_q, p_kH, p_kL, p_vH, p_vL, p_att);
        pgemm<2><<<dim3(CDIM / 128, NTOK / 128), 256, PG_SMEM>>>(
            p_att, p_wpH + (size_t)l * CDIM * CDIM, p_wpL + (size_t)l * CDIM * CDIM,
            proj_b + (size_t)l * CDIM, p_h, p_h, nullptr, nullptr, nullptr, nullptr, nullptr,
            NTOK, CDIM, CDIM);
        ln_kernel<<<NTOK, 256>>>(p_h, ln2_w + (size_t)l * CDIM, ln2_b + (size_t)l * CDIM, p_hn);
        pgemm<1><<<dim3(C4 / 128, NTOK / 128), 256, PG_SMEM>>>(
            p_hn, p_wfH + (size_t)l * C4 * CDIM, p_wfL + (size_t)l * C4 * CDIM,
            fc_b + (size_t)l * C4, nullptr, nullptr, p_fc, nullptr, nullptr, nullptr, nullptr,
            NTOK, C4, CDIM);
        pgemm<2><<<dim3(CDIM / 128, NTOK / 128), 256, PG_SMEM>>>(
            p_fc, p_wf2H + (size_t)l * CDIM * C4, p_wf2L + (size_t)l * CDIM * C4,
            fc2_b + (size_t)l * CDIM, p_h, p_h, nullptr, nullptr, nullptr, nullptr, nullptr,
            NTOK, CDIM, C4);
    }

    ln_kernel<<<NTOK, 256>>>(p_h, lnf_w, lnf_b, p_hn);
    pgemm<3><<<dim3(VOCAB / 128, NTOK / 128), 256, PG_SMEM>>>(
        p_hn, p_wteH, p_wteL, nullptr, nullptr, logits, nullptr, nullptr, nullptr, nullptr, nullptr,
        NTOK, VOCAB, CDIM);

    loss_row_kernel<<<NTOK, 256>>>(logits, targets);
    loss_reduce_kernel<<<1, 1024>>>(lossp);
}

// round 17
// speedup vs baseline: 1.8796x; 1.0336x over previous
#include <cuda_runtime.h>
#include <cuda_bf16.h>
#include <cuda_fp16.h>
#include <math.h>
#include <stdint.h>

// ---------------- problem constants ----------------
#define BATCH 4
#define TSEQ  1024
#define CDIM  768
#define NHEAD 12
#define HD    64
#define VOCAB 50304
#define NLAYER 12
#define NTOK  (BATCH*TSEQ)     // 4096
#define C3    (3*CDIM)         // 2304
#define C4    (4*CDIM)         // 3072
#define NVB   (VOCAB/128)      // 393

#define WATTN (NLAYER*C3*CDIM)
#define WPROJ (NLAYER*CDIM*CDIM)
#define WFC   (NLAYER*C4*CDIM)
#define WFC2  (NLAYER*CDIM*C4)
#define WTEN  (VOCAB*CDIM)

// ---------------- scratch (static device globals; no allocation allowed) ----
__device__ float g_h [NTOK * CDIM];
__device__ float g_q [NTOK * CDIM];
__device__ float g_rowloss[NTOK];
__device__ float g_pmax[NTOK * NVB];
__device__ float g_psum[NTOK * NVB];
__device__ __nv_bfloat16 g_kH[NTOK * CDIM], g_kL[NTOK * CDIM];   // [b*H+h][t][d]
__device__ __nv_bfloat16 g_vH[NTOK * CDIM], g_vL[NTOK * CDIM];   // [b*H+h][d][t]
__device__ __half g_hn [NTOK * CDIM];
__device__ __half g_att[NTOK * CDIM];
__device__ __half g_fc [NTOK * C4];
__device__ __half g_waH[WATTN],  g_waL[WATTN];
__device__ __half g_wpH[WPROJ],  g_wpL[WPROJ];
__device__ __half g_wfH[WFC],    g_wfL[WFC];
__device__ __half g_wf2H[WFC2],  g_wf2L[WFC2];
__device__ __half g_wteH[WTEN],  g_wteL[WTEN];

// ---------------- split helpers ----------------
__device__ __forceinline__ void bsplit(float x, uint16_t& h, uint16_t& l) {
    __nv_bfloat16 bh = __float2bfloat16_rn(x);
    h = __bfloat16_as_ushort(bh);
    float r = x - __bfloat162float(bh);
    l = __bfloat16_as_ushort(__float2bfloat16_rn(r));
}
__device__ __forceinline__ void pack_hl(float vx, float vy, uint32_t& h, uint32_t& l) {
    uint16_t hx, lx, hy, ly;
    bsplit(vx, hx, lx); bsplit(vy, hy, ly);
    h = (uint32_t)hx | ((uint32_t)hy << 16);
    l = (uint32_t)lx | ((uint32_t)ly << 16);
}
__device__ __forceinline__ void hsplit(float x, uint16_t& h, uint16_t& l) {
    __half hh = __float2half_rn(x);
    h = __half_as_ushort(hh);
    float r = x - __half2float(hh);
    l = __half_as_ushort(__float2half_rn(r));
}
__device__ __forceinline__ void pack_hl_h(float vx, float vy, uint32_t& h, uint32_t& l) {
    uint16_t hx, lx, hy, ly;
    hsplit(vx, hx, lx); hsplit(vy, hy, ly);
    h = (uint32_t)hx | ((uint32_t)hy << 16);
    l = (uint32_t)lx | ((uint32_t)ly << 16);
}
__device__ __forceinline__ uint32_t pack_h2(float x, float y) {
    __half2 t = __floats2half2_rn(x, y);
    return *(uint32_t*)&t;
}
__device__ __forceinline__ void mma_bf16(float* c, const uint32_t* a, const uint32_t* b) {
    asm volatile(
        "mma.sync.aligned.m16n8k16.row.col.f32.bf16.bf16.f32 "
        "{%0,%1,%2,%3},{%4,%5,%6,%7},{%8,%9},{%0,%1,%2,%3};"
        : "+f"(c[0]), "+f"(c[1]), "+f"(c[2]), "+f"(c[3])
        : "r"(a[0]), "r"(a[1]), "r"(a[2]), "r"(a[3]), "r"(b[0]), "r"(b[1]));
}
__device__ __forceinline__ void mma_f16(float* c, const uint32_t* a, const uint32_t* b) {
    asm volatile(
        "mma.sync.aligned.m16n8k16.row.col.f32.f16.f16.f32 "
        "{%0,%1,%2,%3},{%4,%5,%6,%7},{%8,%9},{%0,%1,%2,%3};"
        : "+f"(c[0]), "+f"(c[1]), "+f"(c[2]), "+f"(c[3])
        : "r"(a[0]), "r"(a[1]), "r"(a[2]), "r"(a[3]), "r"(b[0]), "r"(b[1]));
}
__device__ __forceinline__ uint32_t smem_u32(const void* p) {
    uint32_t a;
    asm("{ .reg .u64 t; cvta.to.shared.u64 t, %1; cvt.u32.u64 %0, t; }" : "=r"(a) : "l"(p));
    return a;
}
__device__ __forceinline__ void ldsm4(uint32_t& r0, uint32_t& r1, uint32_t& r2, uint32_t& r3,
                                      uint32_t addr) {
    asm volatile("ldmatrix.sync.aligned.m8n8.x4.shared.b16 {%0,%1,%2,%3}, [%4];"
                 : "=r"(r0), "=r"(r1), "=r"(r2), "=r"(r3) : "r"(addr));
}
// swizzled offset for (logical row r, 16B chunk c4) in a 128x64B tile
__device__ __forceinline__ uint32_t swz(uint32_t r, uint32_t c4) {
    uint32_t pr = r >> 1;
    uint32_t ch = ((r & 1) << 2) | c4;
    return (pr << 7) + (((ch ^ (pr & 7))) << 4);
}

// ---------------- weight conversion kernels (once per launch) ----------------
__global__ __launch_bounds__(256) void wsplit_t(const float* __restrict__ in,
                                                __half* __restrict__ oh,
                                                __half* __restrict__ ol,
                                                int K, int N) {
    __shared__ float t[32][33];
    size_t loff = (size_t)blockIdx.z * K * N;
    const float* src = in + loff;
    int nb = blockIdx.x * 32, kb = blockIdx.y * 32;
    int tx = threadIdx.x & 31, ty = threadIdx.x >> 5;
    #pragma unroll
    for (int i = 0; i < 32; i += 8)
        t[ty + i][tx] = src[(size_t)(kb + ty + i) * N + nb + tx];
    __syncthreads();
    #pragma unroll
    for (int i = 0; i < 32; i += 8) {
        float v = t[tx][ty + i];
        uint16_t h, l; hsplit(v, h, l);
        size_t o = loff + (size_t)(nb + ty + i) * K + kb + tx;
        oh[o] = __ushort_as_half(h);
        ol[o] = __ushort_as_half(l);
    }
}
__global__ __launch_bounds__(256) void wsplit(const float* __restrict__ in,
                                              __half* __restrict__ oh,
                                              __half* __restrict__ ol, int n) {
    int i = (blockIdx.x * 256 + threadIdx.x) * 2;
    if (i < n) {
        uint32_t h, l;
        pack_hl_h(in[i], in[i + 1], h, l);
        *(uint32_t*)&oh[i] = h;
        *(uint32_t*)&ol[i] = l;
    }
}

// ---------------- embedding ----------------
__global__ __launch_bounds__(256) void embed_kernel(const int* __restrict__ x,
                                                    const float* __restrict__ wte,
                                                    const float* __restrict__ wpe) {
    int m = blockIdx.x;
    int t = m % TSEQ;
    int idx = x[m];
    const float* we = wte + (size_t)idx * CDIM;
    const float* wp = wpe + (size_t)t * CDIM;
    float* o = g_h + (size_t)m * CDIM;
    for (int c = threadIdx.x; c < CDIM; c += 256)
        o[c] = we[c] + wp[c];
}

// ---------------- layernorm: fp32 in -> fp16 out (single global read) -------
__global__ __launch_bounds__(256) void ln_kernel(const float* __restrict__ in,
                                                 const float* __restrict__ w,
                                                 const float* __restrict__ bb,
                                                 __half* __restrict__ oh) {
    int row = blockIdx.x;
    int t = threadIdx.x;
    const float* x = in + (size_t)row * CDIM;
    float4 xv = make_float4(0.f, 0.f, 0.f, 0.f);
    if (t < 192) xv = *(const float4*)(x + 4 * t);
    float s  = (xv.x + xv.y) + (xv.z + xv.w);
    float s2 = (xv.x * xv.x + xv.y * xv.y) + (xv.z * xv.z + xv.w * xv.w);
    __shared__ float ss[8], ss2[8];
    #pragma unroll
    for (int o = 16; o; o >>= 1) {
        s  += __shfl_down_sync(0xffffffffu, s,  o);
        s2 += __shfl_down_sync(0xffffffffu, s2, o);
    }
    if ((t & 31) == 0) { ss[t >> 5] = s; ss2[t >> 5] = s2; }
    __syncthreads();
    if (t == 0) {
        float a = 0.f, a2 = 0.f;
        #pragma unroll
        for (int i = 0; i < 8; i++) { a += ss[i]; a2 += ss2[i]; }
        ss[0] = a; ss2[0] = a2;
    }
    __syncthreads();
    float mean = ss[0] * (1.f / CDIM);
    float var  = ss2[0] * (1.f / CDIM) - mean * mean;
    float rstd = rsqrtf(var + 1e-5f);
    if (t < 192) {
        float4 wv = *(const float4*)(w + 4 * t);
        float4 bv = *(const float4*)(bb + 4 * t);
        float v0 = (xv.x - mean) * rstd * wv.x + bv.x;
        float v1 = (xv.y - mean) * rstd * wv.y + bv.y;
        float v2 = (xv.z - mean) * rstd * wv.z + bv.z;
        float v3 = (xv.w - mean) * rstd * wv.w + bv.w;
        uint2 o2;
        o2.x = pack_h2(v0, v1);
        o2.y = pack_h2(v2, v3);
        *(uint2*)&oh[(size_t)row * CDIM + 4 * t] = o2;
    }
}

// ---------------- 2xFP16 GEMM: A fp16 1-term, B fp16 hi/lo 2-term ----------
// EPI: 1 = +bias,gelu -> fp16; 2 = +bias+residual -> fp32;
//      3 = plain -> fp32 + fused softmax partials (head);
//      4 = qkv split (Q fp32, K bf16 hi/lo, V transposed bf16 hi/lo)
#define PG_ARR   8192
#define PG_STG   (3 * PG_ARR)
#define PG_SMEM  (2 * PG_STG)

template<int EPI>
__global__ __launch_bounds__(256) void pgemm(const __half* __restrict__ A,
                                             const __half* __restrict__ BH,
                                             const __half* __restrict__ BL,
                                             const float* __restrict__ bias,
                                             const float* __restrict__ add,
                                             float* __restrict__ Cf,
                                             __half* __restrict__ Ch,
                                             __nv_bfloat16* __restrict__ KH,
                                             __nv_bfloat16* __restrict__ KL,
                                             __nv_bfloat16* __restrict__ VH,
                                             __nv_bfloat16* __restrict__ VL,
                                             float* __restrict__ Pmax,
                                             float* __restrict__ Psum,
                                             int M, int N, int K) {
    extern __shared__ char smem[];
    uint32_t sb = smem_u32(smem);

    int tid  = threadIdx.x;
    int wid  = tid >> 5, lane = tid & 31;
    int wr   = wid >> 2, wc = wid & 3;
    int g    = lane >> 2, tg = lane & 3;
    int row0 = blockIdx.y * 128, col0 = blockIdx.x * 128;

    const uint32_t lrow = lane & 15;
    const uint32_t lc4  = (lane >> 4);

    const __half* srcs[3] = { A, BH, BL };

    auto issue = [&](int k0, int s) {
        uint32_t sbase = sb + s * PG_STG;
        #pragma unroll
        for (int arr = 0; arr < 3; arr++) {
            const __half* gs = srcs[arr];
            int rbase = (arr == 0) ? row0 : col0;
            #pragma unroll
            for (int i = 0; i < 2; i++) {
                int ch = tid + i * 256;
                int r = ch >> 2, cb = ch & 3;
                const char* src = (const char*)(gs + (size_t)(rbase + r) * K + k0) + cb * 16;
                uint32_t dst = sbase + arr * PG_ARR + swz(r, cb);
                asm volatile("cp.async.cg.shared.global [%0], [%1], 16;"
                             :: "r"(dst), "l"(src) : "memory");
            }
        }
        asm volatile("cp.async.commit_group;" ::: "memory");
    };

    float c[4][4][4];
    #pragma unroll
    for (int mi = 0; mi < 4; mi++)
        #pragma unroll
        for (int ni = 0; ni < 4; ni++)
            #pragma unroll
            for (int r = 0; r < 4; r++) c[mi][ni][r] = 0.f;

    int nk = K / 32;
    issue(0, 0);

    for (int ki = 0; ki < nk; ki++) {
        if (ki + 1 < nk) {
            issue((ki + 1) * 32, (ki + 1) & 1);
            asm volatile("cp.async.wait_group 1;" ::: "memory");
        } else {
            asm volatile("cp.async.wait_group 0;" ::: "memory");
        }
        __syncthreads();

        uint32_t sA  = sb + (ki & 1) * PG_STG;
        uint32_t sBh = sA + PG_ARR;
        uint32_t sBl = sA + 2 * PG_ARR;

        #pragma unroll
        for (int ks = 0; ks < 2; ks++) {
            uint32_t c4 = ks * 2 + lc4;
            uint32_t a[4][4], bh[4][2], bl[4][2];
            #pragma unroll
            for (int mi = 0; mi < 4; mi++) {
                uint32_t off = swz(wr * 64 + mi * 16 + lrow, c4);
                ldsm4(a[mi][0], a[mi][1], a[mi][2], a[mi][3], sA + off);
            }
            #pragma unroll
            for (int q = 0; q < 2; q++) {
                uint32_t off = swz(wc * 32 + q * 16 + lrow, c4);
                uint32_t r0, r1, r2, r3;
                ldsm4(r0, r1, r2, r3, sBh + off);
                bh[2*q][0] = r0; bh[2*q+1][0] = r1; bh[2*q][1] = r2; bh[2*q+1][1] = r3;
                ldsm4(r0, r1, r2, r3, sBl + off);
                bl[2*q][0] = r0; bl[2*q+1][0] = r1; bl[2*q][1] = r2; bl[2*q+1][1] = r3;
            }
            #pragma unroll
            for (int mi = 0; mi < 4; mi++)
                #pragma unroll
                for (int ni = 0; ni < 4; ni++) {
                    mma_f16(c[mi][ni], a[mi], bh[ni]);
                    mma_f16(c[mi][ni], a[mi], bl[ni]);
                }
        }
        __syncthreads();
    }

    // ---- epilogue ----
    if constexpr (EPI == 3) {
        __shared__ float spm[128][4], sps[128][4];
        #pragma unroll
        for (int mi = 0; mi < 4; mi++)
            #pragma unroll
            for (int hh = 0; hh < 2; hh++) {
                int rloc = wr * 64 + mi * 16 + g + hh * 8;
                int r = row0 + rloc;
                float vv[8];
                #pragma unroll
                for (int ni = 0; ni < 4; ni++) {
                    vv[2 * ni]     = c[mi][ni][hh * 2 + 0];
                    vv[2 * ni + 1] = c[mi][ni][hh * 2 + 1];
                    int cc = col0 + wc * 32 + ni * 8 + tg * 2;
                    float2 o2; o2.x = vv[2 * ni]; o2.y = vv[2 * ni + 1];
                    *(float2*)(Cf + (size_t)r * N + cc) = o2;
                }
                float mx = vv[0];
                #pragma unroll
                for (int j = 1; j < 8; j++) mx = fmaxf(mx, vv[j]);
                float sum = 0.f;
                #pragma unroll
                for (int j = 0; j < 8; j++) sum += __expf(vv[j] - mx);
                #pragma unroll
                for (int o = 1; o <= 2; o <<= 1) {
                    float om = __shfl_xor_sync(0xffffffffu, mx, o);
                    float os = __shfl_xor_sync(0xffffffffu, sum, o);
                    float m2 = fmaxf(mx, om);
                    sum = sum * __expf(mx - m2) + os * __expf(om - m2);
                    mx = m2;
                }
                if (tg == 0) { spm[rloc][wc] = mx; sps[rloc][wc] = sum; }
            }
        __syncthreads();
        if (tid < 128) {
            float mx = spm[tid][0], sum = sps[tid][0];
            #pragma unroll
            for (int i = 1; i < 4; i++) {
                float m2 = fmaxf(mx, spm[tid][i]);
                sum = sum * __expf(mx - m2) + sps[tid][i] * __expf(spm[tid][i] - m2);
                mx = m2;
            }
            int r = row0 + tid;
            Pmax[(size_t)r * NVB + blockIdx.x] = mx;
            Psum[(size_t)r * NVB + blockIdx.x] = sum;
        }
    } else {
        #pragma unroll
        for (int mi = 0; mi < 4; mi++)
            #pragma unroll
            for (int ni = 0; ni < 4; ni++) {
                int cc = col0 + wc * 32 + ni * 8 + tg * 2;
                #pragma unroll
                for (int hh = 0; hh < 2; hh++) {
                    int r = row0 + wr * 64 + mi * 16 + g + hh * 8;
                    float v0 = c[mi][ni][hh * 2 + 0];
                    float v1 = c[mi][ni][hh * 2 + 1];
                    v0 += bias[cc]; v1 += bias[cc + 1];
                    if (EPI == 2) {
                        const float2 a2 = *(const float2*)(add + (size_t)r * N + cc);
                        v0 += a2.x; v1 += a2.y;
                    }
                    if (EPI == 1) {
                        float t0 = 0.7978845608028654f * (v0 + 0.044715f * v0 * v0 * v0);
                        v0 = 0.5f * v0 * (1.0f + tanhf(t0));
                        float t1 = 0.7978845608028654f * (v1 + 0.044715f * v1 * v1 * v1);
                        v1 = 0.5f * v1 * (1.0f + tanhf(t1));
                        *(uint32_t*)&Ch[(size_t)r * N + cc] = pack_h2(v0, v1);
                    } else if (EPI == 4) {
                        int b = r >> 10, t = r & 1023;
                        int sec = cc / CDIM, chn = cc % CDIM;
                        int h = chn >> 6, d = chn & 63;
                        size_t bh_ = (size_t)(b * NHEAD + h);
                        if (sec == 0) {
                            float2 o2; o2.x = v0; o2.y = v1;
                            *(float2*)(Cf + (size_t)r * CDIM + chn) = o2;
                        } else if (sec == 1) {
                            uint32_t hh_, ll_;
                            pack_hl(v0, v1, hh_, ll_);
                            size_t o = (bh_ * TSEQ + t) * HD + d;
                            *(uint32_t*)&KH[o] = hh_;
                            *(uint32_t*)&KL[o] = ll_;
                        } else {
                            uint16_t h0, l0, h1, l1;
                            bsplit(v0, h0, l0); bsplit(v1, h1, l1);
                            size_t o = (bh_ * HD + d) * TSEQ + t;
                            VH[o] = __ushort_as_bfloat16(h0);
                            VL[o] = __ushort_as_bfloat16(l0);
                            VH[o + TSEQ] = __ushort_as_bfloat16(h1);
                            VL[o + TSEQ] = __ushort_as_bfloat16(l1);
                        }
                    } else {
                        float2 o2; o2.x = v0; o2.y = v1;
                        *(float2*)(Cf + (size_t)r * N + cc) = o2;
                    }
                }
            }
    }
}

// ---------------- MMA flash attention (3xBF16, causal, NO score scaling) ----
__global__ __launch_bounds__(256) void attn_mma(const float* __restrict__ Qf,
                                                const __nv_bfloat16* __restrict__ KH,
                                                const __nv_bfloat16* __restrict__ KL,
                                                const __nv_bfloat16* __restrict__ VH,
                                                const __nv_bfloat16* __restrict__ VL,
                                                __half* __restrict__ attF) {
    constexpr int ST = 72;
    int b = blockIdx.z, h = blockIdx.y;
    int q0 = blockIdx.x * 128;
    int tid = threadIdx.x, wid = tid >> 5, lane = tid & 31;
    int g = lane >> 2, tg = lane & 3;
    int qw0 = q0 + wid * 16;
    const size_t bh_ = (size_t)(b * NHEAD + h);

    __shared__ __nv_bfloat16 sKH[64 * ST], sKL[64 * ST];
    __shared__ __nv_bfloat16 sVH[64 * ST], sVL[64 * ST];

    uint32_t qh[4][4], ql[4][4];
    {
        const float* q_r0 = Qf + (size_t)(b * TSEQ + qw0 + g) * CDIM + h * HD;
        const float* q_r1 = q_r0 + 8 * CDIM;
        #pragma unroll
        for (int s = 0; s < 4; s++) {
            float2 v0 = *(const float2*)(q_r0 + 16 * s + 2 * tg);
            float2 v1 = *(const float2*)(q_r1 + 16 * s + 2 * tg);
            float2 v2 = *(const float2*)(q_r0 + 16 * s + 2 * tg + 8);
            float2 v3 = *(const float2*)(q_r1 + 16 * s + 2 * tg + 8);
            pack_hl(v0.x, v0.y, qh[s][0], ql[s][0]);
            pack_hl(v1.x, v1.y, qh[s][1], ql[s][1]);
            pack_hl(v2.x, v2.y, qh[s][2], ql[s][2]);
            pack_hl(v3.x, v3.y, qh[s][3], ql[s][3]);
        }
    }

    float o[8][4];
    #pragma unroll
    for (int ni = 0; ni < 8; ni++)
        #pragma unroll
        for (int r = 0; r < 4; r++) o[ni][r] = 0.f;
    float m0 = -1e30f, m1 = -1e30f, l0 = 0.f, l1 = 0.f;

    int kend = q0 + 128;
    for (int j0 = 0; j0 < kend; j0 += 64) {
        bool act = (j0 <= qw0 + 15);
        __syncthreads();
        {   // ---- stage K and V (batched copies) ----
            int kk = tid >> 2, d0 = (tid & 3) * 16;
            size_t ko = (bh_ * TSEQ + j0 + kk) * HD + d0;
            size_t vo = (bh_ * HD + kk) * TSEQ + j0 + d0;
            uint4 k0_ = ((const uint4*)&KH[ko])[0];
            uint4 k1_ = ((const uint4*)&KH[ko])[1];
            uint4 k2_ = ((const uint4*)&KL[ko])[0];
            uint4 k3_ = ((const uint4*)&KL[ko])[1];
            uint4 v0_ = ((const uint4*)&VH[vo])[0];
            uint4 v1_ = ((const uint4*)&VH[vo])[1];
            uint4 v2_ = ((const uint4*)&VL[vo])[0];
            uint4 v3_ = ((const uint4*)&VL[vo])[1];
            *(uint4*)&sKH[kk * ST + d0]     = k0_;
            *(uint4*)&sKH[kk * ST + d0 + 8] = k1_;
            *(uint4*)&sKL[kk * ST + d0]     = k2_;
            *(uint4*)&sKL[kk * ST + d0 + 8] = k3_;
            *(uint4*)&sVH[kk * ST + d0]     = v0_;
            *(uint4*)&sVH[kk * ST + d0 + 8] = v1_;
            *(uint4*)&sVL[kk * ST + d0]     = v2_;
            *(uint4*)&sVL[kk * ST + d0 + 8] = v3_;
        }
        __syncthreads();

        if (act) {
            float s[8][4];
            #pragma unroll
            for (int ni = 0; ni < 8; ni++) {
                s[ni][0] = s[ni][1] = s[ni][2] = s[ni][3] = 0.f;
                #pragma unroll
                for (int ss = 0; ss < 4; ss++) {
                    int ib = (8 * ni + g) * ST + 16 * ss + 2 * tg;
                    uint32_t bh2[2] = { *(const uint32_t*)&sKH[ib], *(const uint32_t*)&sKH[ib + 8] };
                    uint32_t bl2[2] = { *(const uint32_t*)&sKL[ib], *(const uint32_t*)&sKL[ib + 8] };
                    mma_bf16(s[ni], qh[ss], bh2);
                    mma_bf16(s[ni], qh[ss], bl2);
                    mma_bf16(s[ni], ql[ss], bh2);
                }
            }
            int r0 = qw0 + g, r1 = r0 + 8;
            float mx0 = -1e30f, mx1 = -1e30f;
            #pragma unroll
            for (int ni = 0; ni < 8; ni++) {
                int kc = j0 + 8 * ni + 2 * tg;
                if (kc     > r0) s[ni][0] = -1e30f;
                if (kc + 1 > r0) s[ni][1] = -1e30f;
                if (kc     > r1) s[ni][2] = -1e30f;
                if (kc + 1 > r1) s[ni][3] = -1e30f;
                mx0 = fmaxf(mx0, fmaxf(s[ni][0], s[ni][1]));
                mx1 = fmaxf(mx1, fmaxf(s[ni][2], s[ni][3]));
            }
            mx0 = fmaxf(mx0, __shfl_xor_sync(0xffffffffu, mx0, 1));
            mx0 = fmaxf(mx0, __shfl_xor_sync(0xffffffffu, mx0, 2));
            mx1 = fmaxf(mx1, __shfl_xor_sync(0xffffffffu, mx1, 1));
            mx1 = fmaxf(mx1, __shfl_xor_sync(0xffffffffu, mx1, 2));
            float nm0 = fmaxf(m0, mx0), nm1 = fmaxf(m1, mx1);
            float c0 = __expf(m0 - nm0), c1 = __expf(m1 - nm1);
            m0 = nm0; m1 = nm1;
            float p[8][4];
            float ls0 = 0.f, ls1 = 0.f;
            #pragma unroll
            for (int ni = 0; ni < 8; ni++) {
                p[ni][0] = __expf(s[ni][0] - nm0);
                p[ni][1] = __expf(s[ni][1] - nm0);
                p[ni][2] = __expf(s[ni][2] - nm1);
                p[ni][3] = __expf(s[ni][3] - nm1);
                ls0 += p[ni][0] + p[ni][1];
                ls1 += p[ni][2] + p[ni][3];
            }
            l0 = l0 * c0 + ls0;
            l1 = l1 * c1 + ls1;
            #pragma unroll
            for (int ni = 0; ni < 8; ni++) {
                o[ni][0] *= c0; o[ni][1] *= c0; o[ni][2] *= c1; o[ni][3] *= c1;
            }
            uint32_t ph[4][4], pl[4][4];
            #pragma unroll
            for (int ss = 0; ss < 4; ss++) {
                pack_hl(p[2*ss][0],   p[2*ss][1],   ph[ss][0], pl[ss][0]);
                pack_hl(p[2*ss][2],   p[2*ss][3],   ph[ss][1], pl[ss][1]);
                pack_hl(p[2*ss+1][0], p[2*ss+1][1], ph[ss][2], pl[ss][2]);
                pack_hl(p[2*ss+1][2], p[2*ss+1][3], ph[ss][3], pl[ss][3]);
            }
            #pragma unroll
            for (int ni = 0; ni < 8; ni++)
                #pragma unroll
                for (int ss = 0; ss < 4; ss++) {
                    int ib = (8 * ni + g) * ST + 16 * ss + 2 * tg;
                    uint32_t bh2[2] = { *(const uint32_t*)&sVH[ib], *(const uint32_t*)&sVH[ib + 8] };
                    uint32_t bl2[2] = { *(const uint32_t*)&sVL[ib], *(const uint32_t*)&sVL[ib + 8] };
                    mma_bf16(o[ni], ph[ss], bh2);
                    mma_bf16(o[ni], ph[ss], bl2);
                    mma_bf16(o[ni], pl[ss], bh2);
                }
        }
    }

    l0 += __shfl_xor_sync(0xffffffffu, l0, 1);
    l0 += __shfl_xor_sync(0xffffffffu, l0, 2);
    l1 += __shfl_xor_sync(0xffffffffu, l1, 1);
    l1 += __shfl_xor_sync(0xffffffffu, l1, 2);
    float i0 = 1.f / l0, i1 = 1.f / l1;
    size_t ro0 = (size_t)(b * TSEQ + qw0 + g) * CDIM + h * HD;
    size_t ro1 = ro0 + 8 * CDIM;
    #pragma unroll
    for (int ni = 0; ni < 8; ni++) {
        *(uint32_t*)&attF[ro0 + 8 * ni + 2 * tg] = pack_h2(o[ni][0] * i0, o[ni][1] * i0);
        *(uint32_t*)&attF[ro1 + 8 * ni + 2 * tg] = pack_h2(o[ni][2] * i1, o[ni][3] * i1);
    }
}

// ---------------- loss from fused partials (warp per row) ----------------
__global__ __launch_bounds__(256) void loss_row_kernel(const float* __restrict__ logits,
                                                       const int* __restrict__ targets) {
    int row = blockIdx.x * 8 + (threadIdx.x >> 5);
    int lane = threadIdx.x & 31;
    float mx = -1e30f, s = 0.f;
    const float* pm = g_pmax + (size_t)row * NVB;
    const float* ps = g_psum + (size_t)row * NVB;
    for (int i = lane; i < NVB; i += 32) {
        float om = pm[i], os = ps[i];
        float m2 = fmaxf(mx, om);
        s = s * __expf(mx - m2) + os * __expf(om - m2);
        mx = m2;
    }
    #pragma unroll
    for (int o = 16; o; o >>= 1) {
        float om = __shfl_down_sync(0xffffffffu, mx, o);
        float os = __shfl_down_sync(0xffffffffu, s,  o);
        float m2 = fmaxf(mx, om);
        s = s * __expf(mx - m2) + os * __expf(om - m2);
        mx = m2;
    }
    if (lane == 0)
        g_rowloss[row] = (mx + logf(s)) - logits[(size_t)row * VOCAB + targets[row]];
}

__global__ __launch_bounds__(1024) void loss_reduce_kernel(float* __restrict__ out) {
    __shared__ float sh[1024];
    int t = threadIdx.x;
    float s = 0.f;
    for (int i = t; i < NTOK; i += 1024) s += g_rowloss[i];
    sh[t] = s;
    __syncthreads();
    for (int o = 512; o; o >>= 1) {
        if (t < o) sh[t] += sh[t + o];
        __syncthreads();
    }
    if (t == 0) out[0] = sh[0] * (1.f / NTOK);
}

// ---------------- launch ----------------
extern "C" void kernel_launch(void* const* d_in, const int* in_sizes, int n_in,
                              void* d_out, int out_size) {
    const int*   x       = (const int*)  d_in[0];
    const int*   targets = (const int*)  d_in[1];
    const float* wte     = (const float*)d_in[2];
    const float* wpe     = (const float*)d_in[3];
    const float* ln1_w   = (const float*)d_in[4];
    const float* ln1_b   = (const float*)d_in[5];
    const float* attn_w  = (const float*)d_in[6];
    const float* attn_b  = (const float*)d_in[7];
    const float* proj_w  = (const float*)d_in[8];
    const float* proj_b  = (const float*)d_in[9];
    const float* ln2_w   = (const float*)d_in[10];
    const float* ln2_b   = (const float*)d_in[11];
    const float* fc_w    = (const float*)d_in[12];
    const float* fc_b    = (const float*)d_in[13];
    const float* fc2_w   = (const float*)d_in[14];
    const float* fc2_b   = (const float*)d_in[15];
    const float* lnf_w   = (const float*)d_in[16];
    const float* lnf_b   = (const float*)d_in[17];

    float* logits = (float*)d_out;
    float* lossp  = (float*)d_out + (out_size - 1);

    float *p_h, *p_q, *p_pmax, *p_psum;
    __nv_bfloat16 *p_kH, *p_kL, *p_vH, *p_vL;
    __half *p_hn, *p_att, *p_fc;
    __half *p_waH, *p_waL, *p_wpH, *p_wpL, *p_wfH, *p_wfL, *p_wf2H, *p_wf2L, *p_wteH, *p_wteL;
    cudaGetSymbolAddress((void**)&p_h,    g_h);
    cudaGetSymbolAddress((void**)&p_q,    g_q);
    cudaGetSymbolAddress((void**)&p_pmax, g_pmax);
    cudaGetSymbolAddress((void**)&p_psum, g_psum);
    cudaGetSymbolAddress((void**)&p_kH,   g_kH);
    cudaGetSymbolAddress((void**)&p_kL,   g_kL);
    cudaGetSymbolAddress((void**)&p_vH,   g_vH);
    cudaGetSymbolAddress((void**)&p_vL,   g_vL);
    cudaGetSymbolAddress((void**)&p_hn,   g_hn);
    cudaGetSymbolAddress((void**)&p_att,  g_att);
    cudaGetSymbolAddress((void**)&p_fc,   g_fc);
    cudaGetSymbolAddress((void**)&p_waH,  g_waH);
    cudaGetSymbolAddress((void**)&p_waL,  g_waL);
    cudaGetSymbolAddress((void**)&p_wpH,  g_wpH);
    cudaGetSymbolAddress((void**)&p_wpL,  g_wpL);
    cudaGetSymbolAddress((void**)&p_wfH,  g_wfH);
    cudaGetSymbolAddress((void**)&p_wfL,  g_wfL);
    cudaGetSymbolAddress((void**)&p_wf2H, g_wf2H);
    cudaGetSymbolAddress((void**)&p_wf2L, g_wf2L);
    cudaGetSymbolAddress((void**)&p_wteH, g_wteH);
    cudaGetSymbolAddress((void**)&p_wteL, g_wteL);

    cudaFuncSetAttribute(pgemm<1>, cudaFuncAttributeMaxDynamicSharedMemorySize, PG_SMEM);
    cudaFuncSetAttribute(pgemm<2>, cudaFuncAttributeMaxDynamicSharedMemorySize, PG_SMEM);
    cudaFuncSetAttribute(pgemm<3>, cudaFuncAttributeMaxDynamicSharedMemorySize, PG_SMEM);
    cudaFuncSetAttribute(pgemm<4>, cudaFuncAttributeMaxDynamicSharedMemorySize, PG_SMEM);

    // ---- weight pre-split (once per launch) ----
    wsplit_t<<<dim3(C3 / 32, CDIM / 32, NLAYER), 256>>>(attn_w, p_waH, p_waL, CDIM, C3);
    wsplit_t<<<dim3(CDIM / 32, CDIM / 32, NLAYER), 256>>>(proj_w, p_wpH, p_wpL, CDIM, CDIM);
    wsplit_t<<<dim3(C4 / 32, CDIM / 32, NLAYER), 256>>>(fc_w, p_wfH, p_wfL, CDIM, C4);
    wsplit_t<<<dim3(CDIM / 32, C4 / 32, NLAYER), 256>>>(fc2_w, p_wf2H, p_wf2L, C4, CDIM);
    wsplit<<<(WTEN / 2 + 255) / 256, 256>>>(wte, p_wteH, p_wteL, WTEN);

    embed_kernel<<<NTOK, 256>>>(x, wte, wpe);

    for (int l = 0; l < NLAYER; l++) {
        ln_kernel<<<NTOK, 256>>>(p_h, ln1_w + (size_t)l * CDIM, ln1_b + (size_t)l * CDIM, p_hn);
        pgemm<4><<<dim3(C3 / 128, NTOK / 128), 256, PG_SMEM>>>(
            p_hn, p_waH + (size_t)l * C3 * CDIM, p_waL + (size_t)l * C3 * CDIM,
            attn_b + (size_t)l * C3, nullptr, p_q, nullptr, p_kH, p_kL, p_vH, p_vL,
            nullptr, nullptr, NTOK, C3, CDIM);
        attn_mma<<<dim3(TSEQ / 128, NHEAD, BATCH), 256>>>(p_q, p_kH, p_kL, p_vH, p_vL, p_att);
        pgemm<2><<<dim3(CDIM / 128, NTOK / 128), 256, PG_SMEM>>>(
            p_att, p_wpH + (size_t)l * CDIM * CDIM, p_wpL + (size_t)l * CDIM * CDIM,
            proj_b + (size_t)l * CDIM, p_h, p_h, nullptr, nullptr, nullptr, nullptr, nullptr,
            nullptr, nullptr, NTOK, CDIM, CDIM);
        ln_kernel<<<NTOK, 256>>>(p_h, ln2_w + (size_t)l * CDIM, ln2_b + (size_t)l * CDIM, p_hn);
        pgemm<1><<<dim3(C4 / 128, NTOK / 128), 256, PG_SMEM>>>(
            p_hn, p_wfH + (size_t)l * C4 * CDIM, p_wfL + (size_t)l * C4 * CDIM,
            fc_b + (size_t)l * C4, nullptr, nullptr, p_fc, nullptr, nullptr, nullptr, nullptr,
            nullptr, nullptr, NTOK, C4, CDIM);
        pgemm<2><<<dim3(CDIM / 128, NTOK / 128), 256, PG_SMEM>>>(
            p_fc, p_wf2H + (size_t)l * CDIM * C4, p_wf2L + (size_t)l * CDIM * C4,
            fc2_b + (size_t)l * CDIM, p_h, p_h, nullptr, nullptr, nullptr, nullptr, nullptr,
            nullptr, nullptr, NTOK, CDIM, C4);
    }

    ln_kernel<<<NTOK, 256>>>(p_h, lnf_w, lnf_b, p_hn);
    pgemm<3><<<dim3(VOCAB / 128, NTOK / 128), 256, PG_SMEM>>>(
        p_hn, p_wteH, p_wteL, nullptr, nullptr, logits, nullptr, nullptr, nullptr, nullptr, nullptr,
        p_pmax, p_psum, NTOK, VOCAB, CDIM);

    loss_row_kernel<<<NTOK / 8, 256>>>(logits, targets);
    loss_reduce_kernel<<<1, 1024>>>(lossp);
}